// round 7
// baseline (speedup 1.0000x reference)
#include <cuda_runtime.h>
#include <cuda_fp16.h>
#include <cstdint>
#include <math.h>

// ---------------- problem constants ----------------
#define BATCH    2
#define SEQLEN   4096
#define NTOK     8192
#define DMODEL   1024
#define DINNER   2048
#define DSTATE   64
#define NHEADS   32
#define HDIM     64
#define CONVK    4
#define CHUNKSZ  128
#define NCHUNK   32
#define DXBC     6144
#define DPROJ    8224

// ---------------- device scratch (allocation-free) ----------------
__device__ float  g_proj[(size_t)NTOK * DPROJ];
__device__ float  g_xbc[(size_t)NTOK * DXBC];
__device__ float  g_dacum[BATCH * NHEADS * NCHUNK * CHUNKSZ];
__device__ float  g_states[(size_t)BATCH * NCHUNK * NHEADS * HDIM * DSTATE];
__device__ float  g_prev[(size_t)BATCH * NCHUNK * NHEADS * HDIM * DSTATE];
__device__ __half g_yz16[(size_t)NTOK * DINNER];
__device__ __half g_ua16[(size_t)NTOK * DMODEL];
__device__ __half g_wa16[(size_t)DPROJ * DMODEL];
__device__ __half g_wo16[(size_t)DMODEL * DINNER];

// ================= helpers =================
__device__ __forceinline__ uint32_t smem_u32(const void* p) {
    uint32_t a;
    asm("{ .reg .u64 t; cvta.to.shared.u64 t, %1; cvt.u32.u64 %0, t; }" : "=r"(a) : "l"(p));
    return a;
}
__device__ __forceinline__ void cp_async16(uint32_t s, const void* g) {
    asm volatile("cp.async.cg.shared.global [%0], [%1], 16;" :: "r"(s), "l"(g) : "memory");
}
__device__ __forceinline__ void sts_zero16(uint32_t s) {
    asm volatile("st.shared.v4.b32 [%0], {%1,%1,%1,%1};" :: "r"(s), "r"(0u) : "memory");
}
#define CP_COMMIT() asm volatile("cp.async.commit_group;" ::: "memory")
#define CP_WAIT2()  asm volatile("cp.async.wait_group 2;" ::: "memory")

__device__ __forceinline__ void ldsm_x4(uint32_t& r0, uint32_t& r1, uint32_t& r2, uint32_t& r3,
                                        uint32_t addr) {
    asm volatile("ldmatrix.sync.aligned.m8n8.x4.shared.b16 {%0,%1,%2,%3}, [%4];"
                 : "=r"(r0), "=r"(r1), "=r"(r2), "=r"(r3) : "r"(addr));
}
__device__ __forceinline__ void mma_fp16(float& d0, float& d1, float& d2, float& d3,
                                         uint32_t a0, uint32_t a1, uint32_t a2, uint32_t a3,
                                         uint32_t b0, uint32_t b1) {
    asm volatile(
        "mma.sync.aligned.m16n8k16.row.col.f32.f16.f16.f32 "
        "{%0,%1,%2,%3}, {%4,%5,%6,%7}, {%8,%9}, {%0,%1,%2,%3};"
        : "+f"(d0), "+f"(d1), "+f"(d2), "+f"(d3)
        : "r"(a0), "r"(a1), "r"(a2), "r"(a3), "r"(b0), "r"(b1));
}

// ================= f32 -> f16 conversion =================
__global__ void f2h_kernel(const float* __restrict__ in, __half* __restrict__ out, int n2) {
    int i = blockIdx.x * blockDim.x + threadIdx.x;
    if (i >= n2) return;
    float2 v = ((const float2*)in)[i];
    ((__half2*)out)[i] = __floats2half2_rn(v.x, v.y);
}

// ================= FP16 mma.sync GEMM (NT), ldmatrix operand fetch =================
// Block 128x256, 8 warps (2x4), warp tile 64x64, k-tile 32 halves, 4-stage pipeline.
#define KTILE    32
#define NSTAGE   4
#define TSTRIDE_H 40                             // halves per smem row (32 + 8 pad) = 80B
#define A_HALVES (128 * TSTRIDE_H)
#define B_HALVES (256 * TSTRIDE_H)
#define GSTAGE_HALVES (A_HALVES + B_HALVES)
#define SMEM_GEMM (NSTAGE * GSTAGE_HALVES * 2)   // 122880 bytes

__device__ __forceinline__ void load_tile_h(const __half* __restrict__ A,
                                            const __half* __restrict__ B,
                                            int K, int Nn, int bm, int bn,
                                            int ti, uint32_t sb, int tid)
{
    uint32_t st = sb + (uint32_t)(ti & (NSTAGE - 1)) * (GSTAGE_HALVES * 2);
    const __half* ag = A + (size_t)bm * K + (size_t)ti * KTILE;
#pragma unroll
    for (int i = 0; i < 2; i++) {
        int flat = tid + (i << 8);
        int r = flat >> 2, c = flat & 3;
        cp_async16(st + r * (TSTRIDE_H * 2) + c * 16, ag + (size_t)r * K + c * 8);
    }
    uint32_t stb = st + A_HALVES * 2;
    const __half* bg = B + (size_t)ti * KTILE;
#pragma unroll
    for (int i = 0; i < 4; i++) {
        int flat = tid + (i << 8);
        int r = flat >> 2, c = flat & 3;
        uint32_t so = stb + r * (TSTRIDE_H * 2) + c * 16;
        int gn = bn + r;
        if (gn < Nn) cp_async16(so, bg + (size_t)gn * K + c * 8);
        else         sts_zero16(so);
    }
}

__global__ void __launch_bounds__(256, 1)
gemm_h(const __half* __restrict__ A, const __half* __restrict__ B,
       float* __restrict__ C, int M, int Nn, int K)
{
    extern __shared__ __align__(16) __half dsmh[];
    const int tid = threadIdx.x;
    const int wid = tid >> 5;
    const int lane = tid & 31;
    const int q = lane & 3;
    const int wm = (wid & 1) * 64;
    const int wn = (wid >> 1) * 64;
    const int KT = K / KTILE;
    const int bm = blockIdx.y << 7;
    const int bn = blockIdx.x << 8;
    uint32_t sb = smem_u32(dsmh);

    // per-lane ldmatrix offset within a 16-row tile (bytes):
    // rows = lane&15, k-half select = lane>>4 (8 halves = 16 bytes)
    const uint32_t lm_off = (uint32_t)((lane & 15) * (TSTRIDE_H * 2) + (lane >> 4) * 16);

    float acc[4][8][4];
#pragma unroll
    for (int mi = 0; mi < 4; mi++)
#pragma unroll
        for (int ni = 0; ni < 8; ni++)
#pragma unroll
            for (int e = 0; e < 4; e++) acc[mi][ni][e] = 0.f;

#pragma unroll
    for (int t = 0; t < 3; t++) {
        load_tile_h(A, B, K, Nn, bm, bn, t, sb, tid);
        CP_COMMIT();
    }

    for (int kt = 0; kt < KT; kt++) {
        CP_WAIT2();
        __syncthreads();
        int ld = kt + 3;
        if (ld < KT) load_tile_h(A, B, K, Nn, bm, bn, ld, sb, tid);
        CP_COMMIT();

        uint32_t stg = sb + (uint32_t)(kt & (NSTAGE - 1)) * (GSTAGE_HALVES * 2);
        uint32_t aBase = stg + (uint32_t)wm * (TSTRIDE_H * 2) + lm_off;
        uint32_t bBase = stg + A_HALVES * 2 + (uint32_t)wn * (TSTRIDE_H * 2) + lm_off;

#pragma unroll
        for (int ks = 0; ks < 2; ks++) {          // two k=16 steps; +32B per step
            uint32_t a[4][4];
#pragma unroll
            for (int mi = 0; mi < 4; mi++)
                ldsm_x4(a[mi][0], a[mi][1], a[mi][2], a[mi][3],
                        aBase + mi * (16 * TSTRIDE_H * 2) + ks * 32);
            uint32_t b[8][2];
#pragma unroll
            for (int n2 = 0; n2 < 4; n2++)
                ldsm_x4(b[2 * n2][0], b[2 * n2 + 1][0], b[2 * n2][1], b[2 * n2 + 1][1],
                        bBase + n2 * (16 * TSTRIDE_H * 2) + ks * 32);
#pragma unroll
            for (int mi = 0; mi < 4; mi++)
#pragma unroll
                for (int ni = 0; ni < 8; ni++)
                    mma_fp16(acc[mi][ni][0], acc[mi][ni][1], acc[mi][ni][2], acc[mi][ni][3],
                             a[mi][0], a[mi][1], a[mi][2], a[mi][3],
                             b[ni][0], b[ni][1]);
        }
    }

    // epilogue
    const int g = lane >> 2;
#pragma unroll
    for (int mi = 0; mi < 4; mi++) {
#pragma unroll
        for (int ni = 0; ni < 8; ni++) {
            int col = bn + wn + ni * 8 + 2 * q;
            if (col < Nn) {
                int r0 = bm + wm + mi * 16 + g;
                *(float2*)(C + (size_t)r0 * Nn + col) =
                    make_float2(acc[mi][ni][0], acc[mi][ni][1]);
                *(float2*)(C + (size_t)(r0 + 8) * Nn + col) =
                    make_float2(acc[mi][ni][2], acc[mi][ni][3]);
            }
        }
    }
}

// ================= conv + silu (register-rolling window, 16 t/thread) =================
__global__ void __launch_bounds__(256) conv_silu_kernel(const float* __restrict__ cw,
                                                        const float* __restrict__ cb)
{
    int ch = blockIdx.x * 256 + threadIdx.x;
    int tb = blockIdx.y * 16;
    int b = tb >> 12;
    int l0 = tb & (SEQLEN - 1);
    float c0 = cw[ch * 4 + 0], c1 = cw[ch * 4 + 1], c2 = cw[ch * 4 + 2], c3 = cw[ch * 4 + 3];
    float bias = cb[ch];
    const float* base = g_proj + (size_t)(b * SEQLEN) * DPROJ + ch;
    float* outb = g_xbc + (size_t)(b * SEQLEN) * DXBC + ch;
    float w0 = (l0 >= 3) ? base[(size_t)(l0 - 3) * DPROJ] : 0.f;
    float w1 = (l0 >= 2) ? base[(size_t)(l0 - 2) * DPROJ] : 0.f;
    float w2 = (l0 >= 1) ? base[(size_t)(l0 - 1) * DPROJ] : 0.f;
#pragma unroll
    for (int tt = 0; tt < 16; tt++) {
        float xv = base[(size_t)(l0 + tt) * DPROJ];
        float a = fmaf(c3, xv, fmaf(c2, w2, fmaf(c1, w1, fmaf(c0, w0, bias))));
        outb[(size_t)(l0 + tt) * DXBC] = a / (1.f + expf(-a));
        w0 = w1; w1 = w2; w2 = xv;
    }
}

// ================= dA cumsum: one warp per (b,h,c) =================
__global__ void __launch_bounds__(256) dacum_kernel()
{
    int gw = (blockIdx.x * blockDim.x + threadIdx.x) >> 5;
    int lane = threadIdx.x & 31;
    if (gw >= BATCH * NHEADS * NCHUNK) return;
    int c = gw & 31, h = (gw >> 5) & 31, b = gw >> 10;
    int t0 = b * SEQLEN + c * CHUNKSZ + lane * 4;
    float p[4], run = 0.f;
#pragma unroll
    for (int j = 0; j < 4; j++) {
        float v = g_proj[(size_t)(t0 + j) * DPROJ + (DXBC + DINNER) + h];
        run += fmaxf(v, 0.f) + log1pf(expf(-fabsf(v)));
        p[j] = run;
    }
    float tot = run;
#pragma unroll
    for (int off = 1; off < 32; off <<= 1) {
        float nb = __shfl_up_sync(0xFFFFFFFFu, tot, off);
        if (lane >= off) tot += nb;
    }
    float excl = tot - run;
    int ob = ((b * 32 + h) * 32 + c) * CHUNKSZ + lane * 4;
#pragma unroll
    for (int j = 0; j < 4; j++) g_dacum[ob + j] = -(excl + p[j]);
}

// ================= chunk states =================
#define SMEM_STATES ((2 * 128 * 65 + 128) * 4)
__global__ void __launch_bounds__(256, 1) states_kernel()
{
    extern __shared__ float sm[];
    float* Bs = sm;
    float* xs = sm + 128 * 65;
    float* da = xs + 128 * 65;

    int bi = blockIdx.x;
    int h = bi & 31, c = (bi >> 5) & 31, b = bi >> 10;
    int tid = threadIdx.x;
    int base_t = b * SEQLEN + c * CHUNKSZ;
    int dab = ((b * 32 + h) * 32 + c) * CHUNKSZ;

    if (tid < 128) da[tid] = g_dacum[dab + tid];
    __syncthreads();
    float da_last = da[127];

#pragma unroll
    for (int i = 0; i < 32; i++) {
        int flat = tid + 256 * i;
        int s = flat >> 6, p = flat & 63;
        size_t goff = (size_t)(base_t + s) * DXBC + h * 64 + p;
        float dec = __expf(da_last - da[s]);
        xs[s * 65 + p] = g_xbc[goff] * dec;
        Bs[s * 65 + p] = g_xbc[goff + DINNER];
    }
    __syncthreads();

    int n = tid & 63, pg = tid >> 6;
    float acc[16];
#pragma unroll
    for (int i = 0; i < 16; i++) acc[i] = 0.f;
    for (int s = 0; s < CHUNKSZ; s++) {
        float bv = Bs[s * 65 + n];
#pragma unroll
        for (int i = 0; i < 16; i++)
            acc[i] = fmaf(bv, xs[s * 65 + pg + 4 * i], acc[i]);
    }
    size_t sbo = (size_t)((b * 32 + c) * 32 + h) * (HDIM * DSTATE);
#pragma unroll
    for (int i = 0; i < 16; i++)
        g_states[sbo + (pg + 4 * i) * 64 + n] = acc[i];
}

// ================= inter-chunk scan =================
__global__ void __launch_bounds__(256) scan_kernel()
{
    int bi = blockIdx.x;
    int q = bi & 15;
    int bh = bi >> 4;
    int b = bh >> 5, h = bh & 31;
    int e = q * 256 + threadIdx.x;
    float carry = 0.f;
    for (int c = 0; c < NCHUNK; c++) {
        size_t sbo = (size_t)((b * 32 + c) * 32 + h) * (HDIM * DSTATE);
        float dec = expf(g_dacum[((b * 32 + h) * 32 + c) * CHUNKSZ + 127]);
        g_prev[sbo + e] = carry;
        carry = fmaf(carry, dec, g_states[sbo + e]);
    }
}

// ================= fused Y kernel (writes fp16 yz) =================
#define SMEM_Y ((3 * 128 * 65 + 128 * 129 + 64 * 65 + 128) * 4)
__global__ void __launch_bounds__(256, 1) y_kernel(const float* __restrict__ zb,
                                                   const float* __restrict__ Dp)
{
    extern __shared__ float sm[];
    float* Cs = sm;
    float* Bs = Cs + 128 * 65;
    float* xs = Bs + 128 * 65;
    float* G  = xs + 128 * 65;
    float* pT = G + 128 * 129;
    float* da = pT + 64 * 65;

    int bi = blockIdx.x;
    int h = bi & 31, c = (bi >> 5) & 31, b = bi >> 10;
    int tid = threadIdx.x;
    int base_t = b * SEQLEN + c * CHUNKSZ;
    int dab = ((b * 32 + h) * 32 + c) * CHUNKSZ;
    size_t pb = (size_t)((b * 32 + c) * 32 + h) * (HDIM * DSTATE);

    if (tid < 128) da[tid] = g_dacum[dab + tid];
#pragma unroll
    for (int i = 0; i < 32; i++) {
        int flat = tid + 256 * i;
        int s = flat >> 6, p = flat & 63;
        size_t goff = (size_t)(base_t + s) * DXBC + h * 64 + p;
        xs[s * 65 + p] = g_xbc[goff];
        Bs[s * 65 + p] = g_xbc[goff + DINNER];
        Cs[s * 65 + p] = g_xbc[goff + 2 * DINNER];
    }
#pragma unroll
    for (int i = 0; i < 16; i++) {
        int flat = tid + 256 * i;
        int p = flat >> 6, n = flat & 63;
        pT[n * 65 + p] = g_prev[pb + flat];
    }
    __syncthreads();

    {
        int tr = tid >> 4, tc = tid & 15;
        float accg[8][8];
#pragma unroll
        for (int i = 0; i < 8; i++)
#pragma unroll
            for (int j = 0; j < 8; j++) accg[i][j] = 0.f;
        for (int n = 0; n < DSTATE; n++) {
            float a[8], bb[8];
#pragma unroll
            for (int i = 0; i < 8; i++) a[i] = Cs[(tr + 16 * i) * 65 + n];
#pragma unroll
            for (int j = 0; j < 8; j++) bb[j] = Bs[(tc + 16 * j) * 65 + n];
#pragma unroll
            for (int i = 0; i < 8; i++)
#pragma unroll
                for (int j = 0; j < 8; j++)
                    accg[i][j] = fmaf(a[i], bb[j], accg[i][j]);
        }
#pragma unroll
        for (int i = 0; i < 8; i++) {
            int l = tr + 16 * i;
            float dal = da[l];
#pragma unroll
            for (int j = 0; j < 8; j++) {
                int s = tc + 16 * j;
                G[l * 129 + s] = (s <= l) ? accg[i][j] * __expf(dal - da[s]) : 0.f;
            }
        }
    }
    __syncthreads();

    {
        int p = tid & 63;
        int tr2 = tid >> 6;
        float acc[32], acc2[32];
#pragma unroll
        for (int i = 0; i < 32; i++) { acc[i] = 0.f; acc2[i] = 0.f; }

        for (int s = 0; s < CHUNKSZ; s++) {
            float xv = xs[s * 65 + p];
#pragma unroll
            for (int i = 0; i < 32; i++)
                acc[i] = fmaf(G[(tr2 + 4 * i) * 129 + s], xv, acc[i]);
        }
        for (int n = 0; n < DSTATE; n++) {
            float pv = pT[n * 65 + p];
#pragma unroll
            for (int i = 0; i < 32; i++)
                acc2[i] = fmaf(Cs[(tr2 + 4 * i) * 65 + n], pv, acc2[i]);
        }

        float Dh = Dp[h];
        int chn = h * 64 + p;
        float zbias = zb[chn];
#pragma unroll
        for (int i = 0; i < 32; i++) {
            int l = tr2 + 4 * i;
            int t = base_t + l;
            float yv = acc[i] + __expf(da[l]) * acc2[i] + Dh * xs[l * 65 + p];
            float zv = g_proj[(size_t)t * DPROJ + DXBC + chn] + zbias;
            float sil = zv / (1.f + expf(-zv));
            g_yz16[(size_t)t * DINNER + chn] = __float2half_rn(yv * sil);
        }
    }
}

// ================= launch =================
extern "C" void kernel_launch(void* const* d_in, const int* in_sizes, int n_in,
                              void* d_out, int out_size)
{
    const float* u          = (const float*)d_in[0];
    const float* in_proj_w  = (const float*)d_in[1];
    const float* z_bias     = (const float*)d_in[2];
    const float* conv_w     = (const float*)d_in[3];
    const float* conv_b     = (const float*)d_in[4];
    const float* Dparam     = (const float*)d_in[5];
    const float* out_proj_w = (const float*)d_in[6];
    float* out = (float*)d_out;

    void *p_proj = nullptr, *p_yz = nullptr, *p_ua = nullptr, *p_wa = nullptr, *p_wo = nullptr;
    cudaGetSymbolAddress(&p_proj, g_proj);
    cudaGetSymbolAddress(&p_yz, g_yz16);
    cudaGetSymbolAddress(&p_ua, g_ua16);
    cudaGetSymbolAddress(&p_wa, g_wa16);
    cudaGetSymbolAddress(&p_wo, g_wo16);

    cudaFuncSetAttribute(gemm_h, cudaFuncAttributeMaxDynamicSharedMemorySize, SMEM_GEMM);
    cudaFuncSetAttribute(states_kernel, cudaFuncAttributeMaxDynamicSharedMemorySize, SMEM_STATES);
    cudaFuncSetAttribute(y_kernel, cudaFuncAttributeMaxDynamicSharedMemorySize, SMEM_Y);

    // 0) f32 -> f16 operand conversion
    f2h_kernel<<<(NTOK * DMODEL / 2 + 255) / 256, 256>>>(u, (__half*)p_ua, NTOK * DMODEL / 2);
    f2h_kernel<<<(DPROJ * DMODEL / 2 + 255) / 256, 256>>>(in_proj_w, (__half*)p_wa, DPROJ * DMODEL / 2);
    f2h_kernel<<<(DMODEL * DINNER / 2 + 255) / 256, 256>>>(out_proj_w, (__half*)p_wo, DMODEL * DINNER / 2);

    // 1) in_proj GEMM (fp16 mma.sync + ldmatrix): [8192,1024] x [8224,1024]^T
    {
        dim3 grid((DPROJ + 255) / 256, NTOK / 128);
        gemm_h<<<grid, 256, SMEM_GEMM>>>((const __half*)p_ua, (const __half*)p_wa,
                                         (float*)p_proj, NTOK, DPROJ, DMODEL);
    }
    // 2) conv + silu
    {
        dim3 grid(DXBC / 256, NTOK / 16);
        conv_silu_kernel<<<grid, 256>>>(conv_w, conv_b);
    }
    // 3) dA cumsum
    dacum_kernel<<<(BATCH * NHEADS * NCHUNK * 32 + 255) / 256, 256>>>();
    // 4) chunk states
    states_kernel<<<BATCH * NCHUNK * NHEADS, 256, SMEM_STATES>>>();
    // 5) inter-chunk scan
    scan_kernel<<<BATCH * NHEADS * 16, 256>>>();
    // 6) fused Y + gating (emits fp16 yz)
    y_kernel<<<BATCH * NCHUNK * NHEADS, 256, SMEM_Y>>>(z_bias, Dparam);
    // 7) out_proj GEMM (fp16 mma.sync + ldmatrix): [8192,2048] x [1024,2048]^T
    {
        dim3 grid(DMODEL / 256, NTOK / 128);
        gemm_h<<<grid, 256, SMEM_GEMM>>>((const __half*)p_yz, (const __half*)p_wo,
                                         out, NTOK, DMODEL, DINNER);
    }
}

// round 8
// speedup vs baseline: 1.1808x; 1.1808x over previous
#include <cuda_runtime.h>
#include <cuda_fp16.h>
#include <cstdint>
#include <math.h>

// ---------------- problem constants ----------------
#define BATCH    2
#define SEQLEN   4096
#define NTOK     8192
#define DMODEL   1024
#define DINNER   2048
#define DSTATE   64
#define NHEADS   32
#define HDIM     64
#define CONVK    4
#define CHUNKSZ  128
#define NCHUNK   32
#define DXBC     6144
#define DPROJ    8224

// ---------------- device scratch (allocation-free) ----------------
__device__ float  g_proj[(size_t)NTOK * DPROJ];
__device__ float  g_xbc[(size_t)NTOK * DXBC];
__device__ float  g_dacum[BATCH * NHEADS * NCHUNK * CHUNKSZ];
__device__ float  g_states[(size_t)BATCH * NCHUNK * NHEADS * HDIM * DSTATE];
__device__ float  g_prev[(size_t)BATCH * NCHUNK * NHEADS * HDIM * DSTATE];
__device__ __half g_yz16[(size_t)NTOK * DINNER];
__device__ __half g_ua16[(size_t)NTOK * DMODEL];
__device__ __half g_wa16[(size_t)DPROJ * DMODEL];
__device__ __half g_wo16[(size_t)DMODEL * DINNER];

// ================= helpers =================
__device__ __forceinline__ uint32_t smem_u32(const void* p) {
    uint32_t a;
    asm("{ .reg .u64 t; cvta.to.shared.u64 t, %1; cvt.u32.u64 %0, t; }" : "=r"(a) : "l"(p));
    return a;
}
__device__ __forceinline__ void cp_async16(uint32_t s, const void* g) {
    asm volatile("cp.async.cg.shared.global [%0], [%1], 16;" :: "r"(s), "l"(g) : "memory");
}
__device__ __forceinline__ void sts_zero16(uint32_t s) {
    asm volatile("st.shared.v4.b32 [%0], {%1,%1,%1,%1};" :: "r"(s), "r"(0u) : "memory");
}
#define CP_COMMIT() asm volatile("cp.async.commit_group;" ::: "memory")
#define CP_WAIT2()  asm volatile("cp.async.wait_group 2;" ::: "memory")

__device__ __forceinline__ void mma_fp16(float& d0, float& d1, float& d2, float& d3,
                                         uint32_t a0, uint32_t a1, uint32_t a2, uint32_t a3,
                                         uint32_t b0, uint32_t b1) {
    asm volatile(
        "mma.sync.aligned.m16n8k16.row.col.f32.f16.f16.f32 "
        "{%0,%1,%2,%3}, {%4,%5,%6,%7}, {%8,%9}, {%0,%1,%2,%3};"
        : "+f"(d0), "+f"(d1), "+f"(d2), "+f"(d3)
        : "r"(a0), "r"(a1), "r"(a2), "r"(a3), "r"(b0), "r"(b1));
}

// ================= f32 -> f16 conversion =================
__global__ void f2h_kernel(const float* __restrict__ in, __half* __restrict__ out, int n2) {
    int i = blockIdx.x * blockDim.x + threadIdx.x;
    if (i >= n2) return;
    float2 v = ((const float2*)in)[i];
    ((__half2*)out)[i] = __floats2half2_rn(v.x, v.y);
}

// ================= FP16 mma.sync GEMM (NT): C[m,n] = sum_k A[m,k]B[n,k] =================
// Block 128xBN, 8 warps (2x4), warp tile 64x(BN/4), k-tile 32 halves, 4-stage pipeline.
// Scalar LDS operand fetch (beats ldmatrix codegen here; verified R6 vs R7).
#define KTILE    32
#define NSTAGE   4
#define TSTRIDE_H 40                             // halves per smem row (32 + 8 pad) = 80B
#define A_HALVES (128 * TSTRIDE_H)
#define SMEM_GEMM_MAX (NSTAGE * (A_HALVES + 256 * TSTRIDE_H) * 2)   // 122880 (BN=256)

template<int BN>
__device__ __forceinline__ void load_tile_h(const __half* __restrict__ A,
                                            const __half* __restrict__ B,
                                            int K, int Nn, int bm, int bn,
                                            int ti, uint32_t sb, int tid)
{
    constexpr int STAGE_H = A_HALVES + BN * TSTRIDE_H;
    uint32_t st = sb + (uint32_t)(ti & (NSTAGE - 1)) * (STAGE_H * 2);
    const __half* ag = A + (size_t)bm * K + (size_t)ti * KTILE;
#pragma unroll
    for (int i = 0; i < 2; i++) {                 // A: 128 rows x 4 chunks of 16B
        int flat = tid + (i << 8);
        int r = flat >> 2, c = flat & 3;
        cp_async16(st + r * (TSTRIDE_H * 2) + c * 16, ag + (size_t)r * K + c * 8);
    }
    uint32_t stb = st + A_HALVES * 2;
    const __half* bg = B + (size_t)ti * KTILE;
#pragma unroll
    for (int i = 0; i < BN / 64; i++) {           // B: BN rows x 4 chunks of 16B
        int flat = tid + (i << 8);
        int r = flat >> 2, c = flat & 3;
        uint32_t so = stb + r * (TSTRIDE_H * 2) + c * 16;
        int gn = bn + r;
        if (gn < Nn) cp_async16(so, bg + (size_t)gn * K + c * 8);
        else         sts_zero16(so);
    }
}

template<int BN>
__global__ void __launch_bounds__(256, 1)
gemm_h(const __half* __restrict__ A, const __half* __restrict__ B,
       float* __restrict__ C, int M, int Nn, int K)
{
    constexpr int NI = BN / 32;                  // n-frags per warp (8 or 4)
    constexpr int STAGE_H = A_HALVES + BN * TSTRIDE_H;
    extern __shared__ __align__(16) uint32_t dsm32[];   // half2 view, row stride 20 u32
    const int tid = threadIdx.x;
    const int wid = tid >> 5;
    const int lane = tid & 31;
    const int g = lane >> 2;
    const int q = lane & 3;
    const int wm = (wid & 1) * 64;
    const int wn = (wid >> 1) * (BN / 4);
    const int KT = K / KTILE;
    const int bm = blockIdx.y << 7;
    const int bn = blockIdx.x * BN;
    uint32_t sb = smem_u32(dsm32);

    float acc[4][NI][4];
#pragma unroll
    for (int mi = 0; mi < 4; mi++)
#pragma unroll
        for (int ni = 0; ni < NI; ni++)
#pragma unroll
            for (int e = 0; e < 4; e++) acc[mi][ni][e] = 0.f;

#pragma unroll
    for (int t = 0; t < 3; t++) {
        load_tile_h<BN>(A, B, K, Nn, bm, bn, t, sb, tid);
        CP_COMMIT();
    }

    for (int kt = 0; kt < KT; kt++) {
        CP_WAIT2();
        __syncthreads();
        int ld = kt + 3;
        if (ld < KT) load_tile_h<BN>(A, B, K, Nn, bm, bn, ld, sb, tid);
        CP_COMMIT();

        const uint32_t* As = dsm32 + (kt & (NSTAGE - 1)) * (STAGE_H / 2);
        const uint32_t* Bs = As + A_HALVES / 2;
#pragma unroll
        for (int ks = 0; ks < 2; ks++) {          // two k=16 steps
            int kq = ks * 8 + q;                  // half2 column index
            uint32_t a[4][4];
#pragma unroll
            for (int mi = 0; mi < 4; mi++) {
                int row = wm + mi * 16;
                a[mi][0] = As[(row + g)     * 20 + kq];
                a[mi][1] = As[(row + g + 8) * 20 + kq];
                a[mi][2] = As[(row + g)     * 20 + kq + 4];
                a[mi][3] = As[(row + g + 8) * 20 + kq + 4];
            }
            uint32_t b[NI][2];
#pragma unroll
            for (int ni = 0; ni < NI; ni++) {
                int col = wn + ni * 8;
                b[ni][0] = Bs[(col + g) * 20 + kq];
                b[ni][1] = Bs[(col + g) * 20 + kq + 4];
            }
#pragma unroll
            for (int mi = 0; mi < 4; mi++)
#pragma unroll
                for (int ni = 0; ni < NI; ni++)
                    mma_fp16(acc[mi][ni][0], acc[mi][ni][1], acc[mi][ni][2], acc[mi][ni][3],
                             a[mi][0], a[mi][1], a[mi][2], a[mi][3],
                             b[ni][0], b[ni][1]);
        }
    }

    // epilogue
#pragma unroll
    for (int mi = 0; mi < 4; mi++) {
#pragma unroll
        for (int ni = 0; ni < NI; ni++) {
            int col = bn + wn + ni * 8 + 2 * q;
            if (col < Nn) {
                int r0 = bm + wm + mi * 16 + g;
                *(float2*)(C + (size_t)r0 * Nn + col) =
                    make_float2(acc[mi][ni][0], acc[mi][ni][1]);
                *(float2*)(C + (size_t)(r0 + 8) * Nn + col) =
                    make_float2(acc[mi][ni][2], acc[mi][ni][3]);
            }
        }
    }
}

// ================= conv + silu (register-rolling window, 16 t/thread) =================
__global__ void __launch_bounds__(256) conv_silu_kernel(const float* __restrict__ cw,
                                                        const float* __restrict__ cb)
{
    int ch = blockIdx.x * 256 + threadIdx.x;
    int tb = blockIdx.y * 16;
    int b = tb >> 12;
    int l0 = tb & (SEQLEN - 1);
    float c0 = cw[ch * 4 + 0], c1 = cw[ch * 4 + 1], c2 = cw[ch * 4 + 2], c3 = cw[ch * 4 + 3];
    float bias = cb[ch];
    const float* base = g_proj + (size_t)(b * SEQLEN) * DPROJ + ch;
    float* outb = g_xbc + (size_t)(b * SEQLEN) * DXBC + ch;
    float w0 = (l0 >= 3) ? base[(size_t)(l0 - 3) * DPROJ] : 0.f;
    float w1 = (l0 >= 2) ? base[(size_t)(l0 - 2) * DPROJ] : 0.f;
    float w2 = (l0 >= 1) ? base[(size_t)(l0 - 1) * DPROJ] : 0.f;
#pragma unroll
    for (int tt = 0; tt < 16; tt++) {
        float xv = base[(size_t)(l0 + tt) * DPROJ];
        float a = fmaf(c3, xv, fmaf(c2, w2, fmaf(c1, w1, fmaf(c0, w0, bias))));
        outb[(size_t)(l0 + tt) * DXBC] = a / (1.f + expf(-a));
        w0 = w1; w1 = w2; w2 = xv;
    }
}

// ================= dA cumsum: one warp per (b,h,c) =================
__global__ void __launch_bounds__(256) dacum_kernel()
{
    int gw = (blockIdx.x * blockDim.x + threadIdx.x) >> 5;
    int lane = threadIdx.x & 31;
    if (gw >= BATCH * NHEADS * NCHUNK) return;
    int c = gw & 31, h = (gw >> 5) & 31, b = gw >> 10;
    int t0 = b * SEQLEN + c * CHUNKSZ + lane * 4;
    float p[4], run = 0.f;
#pragma unroll
    for (int j = 0; j < 4; j++) {
        float v = g_proj[(size_t)(t0 + j) * DPROJ + (DXBC + DINNER) + h];
        run += fmaxf(v, 0.f) + log1pf(expf(-fabsf(v)));
        p[j] = run;
    }
    float tot = run;
#pragma unroll
    for (int off = 1; off < 32; off <<= 1) {
        float nb = __shfl_up_sync(0xFFFFFFFFu, tot, off);
        if (lane >= off) tot += nb;
    }
    float excl = tot - run;
    int ob = ((b * 32 + h) * 32 + c) * CHUNKSZ + lane * 4;
#pragma unroll
    for (int j = 0; j < 4; j++) g_dacum[ob + j] = -(excl + p[j]);
}

// ================= chunk states: 4x4 register tiling =================
// states[p,n] = sum_s B[s,n]*exp(da127-da[s])*x[s,p]
#define SMEM_STATES ((2 * 128 * 65 + 128) * 4)
__global__ void __launch_bounds__(256, 2) states_kernel()
{
    extern __shared__ float sm[];
    float* Bs = sm;                 // [128][65]
    float* xs = sm + 128 * 65;      // [128][65]
    float* da = xs + 128 * 65;      // [128]

    int bi = blockIdx.x;
    int h = bi & 31, c = (bi >> 5) & 31, b = bi >> 10;
    int tid = threadIdx.x;
    int base_t = b * SEQLEN + c * CHUNKSZ;
    int dab = ((b * 32 + h) * 32 + c) * CHUNKSZ;

    if (tid < 128) da[tid] = g_dacum[dab + tid];
    __syncthreads();
    float da_last = da[127];

#pragma unroll
    for (int i = 0; i < 32; i++) {
        int flat = tid + 256 * i;
        int s = flat >> 6, p = flat & 63;
        size_t goff = (size_t)(base_t + s) * DXBC + h * 64 + p;
        float dec = __expf(da_last - da[s]);
        xs[s * 65 + p] = g_xbc[goff] * dec;
        Bs[s * 65 + p] = g_xbc[goff + DINNER];
    }
    __syncthreads();

    // 4x4 tile: n = nt+16j, p = pt+16i
    int nt = tid & 15, pt = tid >> 4;
    float acc[4][4];
#pragma unroll
    for (int i = 0; i < 4; i++)
#pragma unroll
        for (int j = 0; j < 4; j++) acc[i][j] = 0.f;

    for (int s = 0; s < CHUNKSZ; s++) {
        float bv[4], xv[4];
#pragma unroll
        for (int j = 0; j < 4; j++) bv[j] = Bs[s * 65 + nt + 16 * j];
#pragma unroll
        for (int i = 0; i < 4; i++) xv[i] = xs[s * 65 + pt + 16 * i];
#pragma unroll
        for (int i = 0; i < 4; i++)
#pragma unroll
            for (int j = 0; j < 4; j++)
                acc[i][j] = fmaf(bv[j], xv[i], acc[i][j]);
    }
    size_t sbo = (size_t)((b * 32 + c) * 32 + h) * (HDIM * DSTATE);
#pragma unroll
    for (int i = 0; i < 4; i++)
#pragma unroll
        for (int j = 0; j < 4; j++)
            g_states[sbo + (pt + 16 * i) * 64 + nt + 16 * j] = acc[i][j];
}

// ================= inter-chunk scan =================
__global__ void __launch_bounds__(256) scan_kernel()
{
    int bi = blockIdx.x;
    int q = bi & 15;
    int bh = bi >> 4;
    int b = bh >> 5, h = bh & 31;
    int e = q * 256 + threadIdx.x;
    float carry = 0.f;
    for (int c = 0; c < NCHUNK; c++) {
        size_t sbo = (size_t)((b * 32 + c) * 32 + h) * (HDIM * DSTATE);
        float dec = expf(g_dacum[((b * 32 + h) * 32 + c) * CHUNKSZ + 127]);
        g_prev[sbo + e] = carry;
        carry = fmaf(carry, dec, g_states[sbo + e]);
    }
}

// ================= fused Y kernel (8x4 tiled phase 2, writes fp16 yz) =================
#define SMEM_Y ((3 * 128 * 65 + 128 * 129 + 64 * 65 + 128) * 4)
__global__ void __launch_bounds__(256, 1) y_kernel(const float* __restrict__ zb,
                                                   const float* __restrict__ Dp)
{
    extern __shared__ float sm[];
    float* Cs = sm;                    // [128][65]
    float* Bs = Cs + 128 * 65;         // [128][65]
    float* xs = Bs + 128 * 65;         // [128][65]
    float* G  = xs + 128 * 65;         // [128][129]
    float* pT = G + 128 * 129;         // [64][65]
    float* da = pT + 64 * 65;          // [128]

    int bi = blockIdx.x;
    int h = bi & 31, c = (bi >> 5) & 31, b = bi >> 10;
    int tid = threadIdx.x;
    int base_t = b * SEQLEN + c * CHUNKSZ;
    int dab = ((b * 32 + h) * 32 + c) * CHUNKSZ;
    size_t pb = (size_t)((b * 32 + c) * 32 + h) * (HDIM * DSTATE);

    if (tid < 128) da[tid] = g_dacum[dab + tid];
#pragma unroll
    for (int i = 0; i < 32; i++) {
        int flat = tid + 256 * i;
        int s = flat >> 6, p = flat & 63;
        size_t goff = (size_t)(base_t + s) * DXBC + h * 64 + p;
        xs[s * 65 + p] = g_xbc[goff];
        Bs[s * 65 + p] = g_xbc[goff + DINNER];
        Cs[s * 65 + p] = g_xbc[goff + 2 * DINNER];
    }
#pragma unroll
    for (int i = 0; i < 16; i++) {
        int flat = tid + 256 * i;
        int p = flat >> 6, n = flat & 63;
        pT[n * 65 + p] = g_prev[pb + flat];
    }
    __syncthreads();

    // ---- phase 1: G = (C B^T) .* L ----
    {
        int tr = tid >> 4, tc = tid & 15;
        float accg[8][8];
#pragma unroll
        for (int i = 0; i < 8; i++)
#pragma unroll
            for (int j = 0; j < 8; j++) accg[i][j] = 0.f;
        for (int n = 0; n < DSTATE; n++) {
            float a[8], bb[8];
#pragma unroll
            for (int i = 0; i < 8; i++) a[i] = Cs[(tr + 16 * i) * 65 + n];
#pragma unroll
            for (int j = 0; j < 8; j++) bb[j] = Bs[(tc + 16 * j) * 65 + n];
#pragma unroll
            for (int i = 0; i < 8; i++)
#pragma unroll
                for (int j = 0; j < 8; j++)
                    accg[i][j] = fmaf(a[i], bb[j], accg[i][j]);
        }
#pragma unroll
        for (int i = 0; i < 8; i++) {
            int l = tr + 16 * i;
            float dal = da[l];
#pragma unroll
            for (int j = 0; j < 8; j++) {
                int s = tc + 16 * j;
                G[l * 129 + s] = (s <= l) ? accg[i][j] * __expf(dal - da[s]) : 0.f;
            }
        }
    }
    __syncthreads();

    // ---- phase 2 (8l x 4p tiled): Y = G@x + exp(da)*C.prev + D*x; gate; fp16 out ----
    {
        int lt = tid >> 4;                 // 0..15 ; l = lt + 16*i (i<8)
        int pt = tid & 15;                 // 0..15 ; p = pt + 16*j (j<4)
        float acc[8][4], acc2[8][4];
#pragma unroll
        for (int i = 0; i < 8; i++)
#pragma unroll
            for (int j = 0; j < 4; j++) { acc[i][j] = 0.f; acc2[i][j] = 0.f; }

        for (int s = 0; s < CHUNKSZ; s++) {
            float gv[8], xv[4];
#pragma unroll
            for (int i = 0; i < 8; i++) gv[i] = G[(lt + 16 * i) * 129 + s];
#pragma unroll
            for (int j = 0; j < 4; j++) xv[j] = xs[s * 65 + pt + 16 * j];
#pragma unroll
            for (int i = 0; i < 8; i++)
#pragma unroll
                for (int j = 0; j < 4; j++)
                    acc[i][j] = fmaf(gv[i], xv[j], acc[i][j]);
        }
        for (int n = 0; n < DSTATE; n++) {
            float cv[8], pv[4];
#pragma unroll
            for (int i = 0; i < 8; i++) cv[i] = Cs[(lt + 16 * i) * 65 + n];
#pragma unroll
            for (int j = 0; j < 4; j++) pv[j] = pT[n * 65 + pt + 16 * j];
#pragma unroll
            for (int i = 0; i < 8; i++)
#pragma unroll
                for (int j = 0; j < 4; j++)
                    acc2[i][j] = fmaf(cv[i], pv[j], acc2[i][j]);
        }

        float Dh = Dp[h];
        float zbias[4];
#pragma unroll
        for (int j = 0; j < 4; j++) zbias[j] = zb[h * 64 + pt + 16 * j];

#pragma unroll
        for (int i = 0; i < 8; i++) {
            int l = lt + 16 * i;
            int t = base_t + l;
            float eda = __expf(da[l]);
#pragma unroll
            for (int j = 0; j < 4; j++) {
                int p = pt + 16 * j;
                int chn = h * 64 + p;
                float yv = acc[i][j] + eda * acc2[i][j] + Dh * xs[l * 65 + p];
                float zv = g_proj[(size_t)t * DPROJ + DXBC + chn] + zbias[j];
                float sil = zv / (1.f + expf(-zv));
                g_yz16[(size_t)t * DINNER + chn] = __float2half_rn(yv * sil);
            }
        }
    }
}

// ================= launch =================
extern "C" void kernel_launch(void* const* d_in, const int* in_sizes, int n_in,
                              void* d_out, int out_size)
{
    const float* u          = (const float*)d_in[0];
    const float* in_proj_w  = (const float*)d_in[1];
    const float* z_bias     = (const float*)d_in[2];
    const float* conv_w     = (const float*)d_in[3];
    const float* conv_b     = (const float*)d_in[4];
    const float* Dparam     = (const float*)d_in[5];
    const float* out_proj_w = (const float*)d_in[6];
    float* out = (float*)d_out;

    void *p_proj = nullptr, *p_yz = nullptr, *p_ua = nullptr, *p_wa = nullptr, *p_wo = nullptr;
    cudaGetSymbolAddress(&p_proj, g_proj);
    cudaGetSymbolAddress(&p_yz, g_yz16);
    cudaGetSymbolAddress(&p_ua, g_ua16);
    cudaGetSymbolAddress(&p_wa, g_wa16);
    cudaGetSymbolAddress(&p_wo, g_wo16);

    cudaFuncSetAttribute(gemm_h<256>, cudaFuncAttributeMaxDynamicSharedMemorySize, SMEM_GEMM_MAX);
    cudaFuncSetAttribute(gemm_h<128>, cudaFuncAttributeMaxDynamicSharedMemorySize,
                         NSTAGE * (A_HALVES + 128 * TSTRIDE_H) * 2);
    cudaFuncSetAttribute(states_kernel, cudaFuncAttributeMaxDynamicSharedMemorySize, SMEM_STATES);
    cudaFuncSetAttribute(y_kernel, cudaFuncAttributeMaxDynamicSharedMemorySize, SMEM_Y);

    // 0) f32 -> f16 operand conversion
    f2h_kernel<<<(NTOK * DMODEL / 2 + 255) / 256, 256>>>(u, (__half*)p_ua, NTOK * DMODEL / 2);
    f2h_kernel<<<(DPROJ * DMODEL / 2 + 255) / 256, 256>>>(in_proj_w, (__half*)p_wa, DPROJ * DMODEL / 2);
    f2h_kernel<<<(DMODEL * DINNER / 2 + 255) / 256, 256>>>(out_proj_w, (__half*)p_wo, DMODEL * DINNER / 2);

    // 1) in_proj GEMM: [8192,1024] x [8224,1024]^T, BN=256
    {
        dim3 grid((DPROJ + 255) / 256, NTOK / 128);
        gemm_h<256><<<grid, 256, SMEM_GEMM_MAX>>>((const __half*)p_ua, (const __half*)p_wa,
                                                  (float*)p_proj, NTOK, DPROJ, DMODEL);
    }
    // 2) conv + silu
    {
        dim3 grid(DXBC / 256, NTOK / 16);
        conv_silu_kernel<<<grid, 256>>>(conv_w, conv_b);
    }
    // 3) dA cumsum
    dacum_kernel<<<(BATCH * NHEADS * NCHUNK * 32 + 255) / 256, 256>>>();
    // 4) chunk states
    states_kernel<<<BATCH * NCHUNK * NHEADS, 256, SMEM_STATES>>>();
    // 5) inter-chunk scan
    scan_kernel<<<BATCH * NHEADS * 16, 256>>>();
    // 6) fused Y + gating (emits fp16 yz)
    y_kernel<<<BATCH * NCHUNK * NHEADS, 256, SMEM_Y>>>(z_bias, Dparam);
    // 7) out_proj GEMM: [8192,2048] x [1024,2048]^T, BN=128 (512 CTAs, better tail)
    {
        dim3 grid(DMODEL / 128, NTOK / 128);
        gemm_h<128><<<grid, 256, NSTAGE * (A_HALVES + 128 * TSTRIDE_H) * 2>>>(
            (const __half*)p_yz, (const __half*)p_wo, out, NTOK, DMODEL, DINNER);
    }
}

// round 9
// speedup vs baseline: 1.2482x; 1.0571x over previous
#include <cuda_runtime.h>
#include <cuda_fp16.h>
#include <cstdint>
#include <math.h>

// ---------------- problem constants ----------------
#define BATCH    2
#define SEQLEN   4096
#define NTOK     8192
#define DMODEL   1024
#define DINNER   2048
#define DSTATE   64
#define NHEADS   32
#define HDIM     64
#define CONVK    4
#define CHUNKSZ  128
#define NCHUNK   32
#define DXBC     6144
#define DPROJ    8224

// ---------------- device scratch (allocation-free) ----------------
__device__ __half g_proj16[(size_t)NTOK * DPROJ];     // fp16 in_proj output
__device__ __half g_xbc16[(size_t)NTOK * DXBC];       // fp16 post conv+silu
__device__ float  g_dacum[BATCH * NHEADS * NCHUNK * CHUNKSZ];
__device__ __half g_states16[(size_t)BATCH * NCHUNK * NHEADS * HDIM * DSTATE];
__device__ __half g_prev16[(size_t)BATCH * NCHUNK * NHEADS * HDIM * DSTATE];
__device__ __half g_yz16[(size_t)NTOK * DINNER];
__device__ __half g_ua16[(size_t)NTOK * DMODEL];
__device__ __half g_wa16[(size_t)DPROJ * DMODEL];
__device__ __half g_wo16[(size_t)DMODEL * DINNER];

// ================= helpers =================
__device__ __forceinline__ uint32_t smem_u32(const void* p) {
    uint32_t a;
    asm("{ .reg .u64 t; cvta.to.shared.u64 t, %1; cvt.u32.u64 %0, t; }" : "=r"(a) : "l"(p));
    return a;
}
__device__ __forceinline__ void cp_async16(uint32_t s, const void* g) {
    asm volatile("cp.async.cg.shared.global [%0], [%1], 16;" :: "r"(s), "l"(g) : "memory");
}
__device__ __forceinline__ void sts_zero16(uint32_t s) {
    asm volatile("st.shared.v4.b32 [%0], {%1,%1,%1,%1};" :: "r"(s), "r"(0u) : "memory");
}
#define CP_COMMIT() asm volatile("cp.async.commit_group;" ::: "memory")
#define CP_WAIT2()  asm volatile("cp.async.wait_group 2;" ::: "memory")

__device__ __forceinline__ void mma_fp16(float& d0, float& d1, float& d2, float& d3,
                                         uint32_t a0, uint32_t a1, uint32_t a2, uint32_t a3,
                                         uint32_t b0, uint32_t b1) {
    asm volatile(
        "mma.sync.aligned.m16n8k16.row.col.f32.f16.f16.f32 "
        "{%0,%1,%2,%3}, {%4,%5,%6,%7}, {%8,%9}, {%0,%1,%2,%3};"
        : "+f"(d0), "+f"(d1), "+f"(d2), "+f"(d3)
        : "r"(a0), "r"(a1), "r"(a2), "r"(a3), "r"(b0), "r"(b1));
}

// ================= f32 -> f16 conversion =================
__global__ void f2h_kernel(const float* __restrict__ in, __half* __restrict__ out, int n2) {
    int i = blockIdx.x * blockDim.x + threadIdx.x;
    if (i >= n2) return;
    float2 v = ((const float2*)in)[i];
    ((__half2*)out)[i] = __floats2half2_rn(v.x, v.y);
}

// ================= FP16 mma.sync GEMM (NT): C[m,n] = sum_k A[m,k]B[n,k] =================
// Block 128xBN, 8 warps (2x4), warp tile 64x(BN/4), k-tile 32 halves, 4-stage pipeline.
// Scalar LDS operand fetch. HALF_OUT selects fp16 vs fp32 output.
#define KTILE    32
#define NSTAGE   4
#define TSTRIDE_H 40                             // halves per smem row (32 + 8 pad) = 80B
#define A_HALVES (128 * TSTRIDE_H)
#define SMEM_GEMM_MAX (NSTAGE * (A_HALVES + 256 * TSTRIDE_H) * 2)   // 122880 (BN=256)

template<int BN>
__device__ __forceinline__ void load_tile_h(const __half* __restrict__ A,
                                            const __half* __restrict__ B,
                                            int K, int Nn, int bm, int bn,
                                            int ti, uint32_t sb, int tid)
{
    constexpr int STAGE_H = A_HALVES + BN * TSTRIDE_H;
    uint32_t st = sb + (uint32_t)(ti & (NSTAGE - 1)) * (STAGE_H * 2);
    const __half* ag = A + (size_t)bm * K + (size_t)ti * KTILE;
#pragma unroll
    for (int i = 0; i < 2; i++) {                 // A: 128 rows x 4 chunks of 16B
        int flat = tid + (i << 8);
        int r = flat >> 2, c = flat & 3;
        cp_async16(st + r * (TSTRIDE_H * 2) + c * 16, ag + (size_t)r * K + c * 8);
    }
    uint32_t stb = st + A_HALVES * 2;
    const __half* bg = B + (size_t)ti * KTILE;
#pragma unroll
    for (int i = 0; i < BN / 64; i++) {           // B: BN rows x 4 chunks of 16B
        int flat = tid + (i << 8);
        int r = flat >> 2, c = flat & 3;
        uint32_t so = stb + r * (TSTRIDE_H * 2) + c * 16;
        int gn = bn + r;
        if (gn < Nn) cp_async16(so, bg + (size_t)gn * K + c * 8);
        else         sts_zero16(so);
    }
}

template<int BN, bool HALF_OUT>
__global__ void __launch_bounds__(256, 1)
gemm_h(const __half* __restrict__ A, const __half* __restrict__ B,
       void* __restrict__ Cv, int M, int Nn, int K)
{
    constexpr int NI = BN / 32;                  // n-frags per warp
    constexpr int STAGE_H = A_HALVES + BN * TSTRIDE_H;
    extern __shared__ __align__(16) uint32_t dsm32[];   // half2 view, row stride 20 u32
    const int tid = threadIdx.x;
    const int wid = tid >> 5;
    const int lane = tid & 31;
    const int g = lane >> 2;
    const int q = lane & 3;
    const int wm = (wid & 1) * 64;
    const int wn = (wid >> 1) * (BN / 4);
    const int KT = K / KTILE;
    const int bm = blockIdx.y << 7;
    const int bn = blockIdx.x * BN;
    uint32_t sb = smem_u32(dsm32);

    float acc[4][NI][4];
#pragma unroll
    for (int mi = 0; mi < 4; mi++)
#pragma unroll
        for (int ni = 0; ni < NI; ni++)
#pragma unroll
            for (int e = 0; e < 4; e++) acc[mi][ni][e] = 0.f;

#pragma unroll
    for (int t = 0; t < 3; t++) {
        load_tile_h<BN>(A, B, K, Nn, bm, bn, t, sb, tid);
        CP_COMMIT();
    }

    for (int kt = 0; kt < KT; kt++) {
        CP_WAIT2();
        __syncthreads();
        int ld = kt + 3;
        if (ld < KT) load_tile_h<BN>(A, B, K, Nn, bm, bn, ld, sb, tid);
        CP_COMMIT();

        const uint32_t* As = dsm32 + (kt & (NSTAGE - 1)) * (STAGE_H / 2);
        const uint32_t* Bs = As + A_HALVES / 2;
#pragma unroll
        for (int ks = 0; ks < 2; ks++) {          // two k=16 steps
            int kq = ks * 8 + q;
            uint32_t a[4][4];
#pragma unroll
            for (int mi = 0; mi < 4; mi++) {
                int row = wm + mi * 16;
                a[mi][0] = As[(row + g)     * 20 + kq];
                a[mi][1] = As[(row + g + 8) * 20 + kq];
                a[mi][2] = As[(row + g)     * 20 + kq + 4];
                a[mi][3] = As[(row + g + 8) * 20 + kq + 4];
            }
            uint32_t b[NI][2];
#pragma unroll
            for (int ni = 0; ni < NI; ni++) {
                int col = wn + ni * 8;
                b[ni][0] = Bs[(col + g) * 20 + kq];
                b[ni][1] = Bs[(col + g) * 20 + kq + 4];
            }
#pragma unroll
            for (int mi = 0; mi < 4; mi++)
#pragma unroll
                for (int ni = 0; ni < NI; ni++)
                    mma_fp16(acc[mi][ni][0], acc[mi][ni][1], acc[mi][ni][2], acc[mi][ni][3],
                             a[mi][0], a[mi][1], a[mi][2], a[mi][3],
                             b[ni][0], b[ni][1]);
        }
    }

    // epilogue
#pragma unroll
    for (int mi = 0; mi < 4; mi++) {
#pragma unroll
        for (int ni = 0; ni < NI; ni++) {
            int col = bn + wn + ni * 8 + 2 * q;
            if (col < Nn) {
                int r0 = bm + wm + mi * 16 + g;
                if (HALF_OUT) {
                    __half* C = (__half*)Cv;
                    *(__half2*)(C + (size_t)r0 * Nn + col) =
                        __floats2half2_rn(acc[mi][ni][0], acc[mi][ni][1]);
                    *(__half2*)(C + (size_t)(r0 + 8) * Nn + col) =
                        __floats2half2_rn(acc[mi][ni][2], acc[mi][ni][3]);
                } else {
                    float* C = (float*)Cv;
                    *(float2*)(C + (size_t)r0 * Nn + col) =
                        make_float2(acc[mi][ni][0], acc[mi][ni][1]);
                    *(float2*)(C + (size_t)(r0 + 8) * Nn + col) =
                        make_float2(acc[mi][ni][2], acc[mi][ni][3]);
                }
            }
        }
    }
}

// ================= conv + silu (register-rolling window, 16 t/thread, fp16 io) =================
__global__ void __launch_bounds__(256) conv_silu_kernel(const float* __restrict__ cw,
                                                        const float* __restrict__ cb)
{
    int ch = blockIdx.x * 256 + threadIdx.x;
    int tb = blockIdx.y * 16;
    int b = tb >> 12;
    int l0 = tb & (SEQLEN - 1);
    float c0 = cw[ch * 4 + 0], c1 = cw[ch * 4 + 1], c2 = cw[ch * 4 + 2], c3 = cw[ch * 4 + 3];
    float bias = cb[ch];
    const __half* base = g_proj16 + (size_t)(b * SEQLEN) * DPROJ + ch;
    __half* outb = g_xbc16 + (size_t)(b * SEQLEN) * DXBC + ch;
    float w0 = (l0 >= 3) ? __half2float(base[(size_t)(l0 - 3) * DPROJ]) : 0.f;
    float w1 = (l0 >= 2) ? __half2float(base[(size_t)(l0 - 2) * DPROJ]) : 0.f;
    float w2 = (l0 >= 1) ? __half2float(base[(size_t)(l0 - 1) * DPROJ]) : 0.f;
#pragma unroll
    for (int tt = 0; tt < 16; tt++) {
        float xv = __half2float(base[(size_t)(l0 + tt) * DPROJ]);
        float a = fmaf(c3, xv, fmaf(c2, w2, fmaf(c1, w1, fmaf(c0, w0, bias))));
        outb[(size_t)(l0 + tt) * DXBC] = __float2half_rn(a / (1.f + expf(-a)));
        w0 = w1; w1 = w2; w2 = xv;
    }
}

// ================= dA cumsum: one warp per (b,h,c) =================
__global__ void __launch_bounds__(256) dacum_kernel()
{
    int gw = (blockIdx.x * blockDim.x + threadIdx.x) >> 5;
    int lane = threadIdx.x & 31;
    if (gw >= BATCH * NHEADS * NCHUNK) return;
    int c = gw & 31, h = (gw >> 5) & 31, b = gw >> 10;
    int t0 = b * SEQLEN + c * CHUNKSZ + lane * 4;
    float p[4], run = 0.f;
#pragma unroll
    for (int j = 0; j < 4; j++) {
        float v = __half2float(g_proj16[(size_t)(t0 + j) * DPROJ + (DXBC + DINNER) + h]);
        run += fmaxf(v, 0.f) + log1pf(expf(-fabsf(v)));
        p[j] = run;
    }
    float tot = run;
#pragma unroll
    for (int off = 1; off < 32; off <<= 1) {
        float nb = __shfl_up_sync(0xFFFFFFFFu, tot, off);
        if (lane >= off) tot += nb;
    }
    float excl = tot - run;
    int ob = ((b * 32 + h) * 32 + c) * CHUNKSZ + lane * 4;
#pragma unroll
    for (int j = 0; j < 4; j++) g_dacum[ob + j] = -(excl + p[j]);
}

// ================= chunk states: 4x4 register tiling, fp16 io =================
#define SMEM_STATES ((2 * 128 * 65 + 128) * 4)
__global__ void __launch_bounds__(256, 2) states_kernel()
{
    extern __shared__ float sm[];
    float* Bs = sm;                 // [128][65]
    float* xs = sm + 128 * 65;      // [128][65]
    float* da = xs + 128 * 65;      // [128]

    int bi = blockIdx.x;
    int h = bi & 31, c = (bi >> 5) & 31, b = bi >> 10;
    int tid = threadIdx.x;
    int base_t = b * SEQLEN + c * CHUNKSZ;
    int dab = ((b * 32 + h) * 32 + c) * CHUNKSZ;

    if (tid < 128) da[tid] = g_dacum[dab + tid];
    __syncthreads();
    float da_last = da[127];

#pragma unroll
    for (int i = 0; i < 32; i++) {
        int flat = tid + 256 * i;
        int s = flat >> 6, p = flat & 63;
        size_t goff = (size_t)(base_t + s) * DXBC + h * 64 + p;
        float dec = __expf(da_last - da[s]);
        xs[s * 65 + p] = __half2float(g_xbc16[goff]) * dec;
        Bs[s * 65 + p] = __half2float(g_xbc16[goff + DINNER]);
    }
    __syncthreads();

    int nt = tid & 15, pt = tid >> 4;
    float acc[4][4];
#pragma unroll
    for (int i = 0; i < 4; i++)
#pragma unroll
        for (int j = 0; j < 4; j++) acc[i][j] = 0.f;

    for (int s = 0; s < CHUNKSZ; s++) {
        float bv[4], xv[4];
#pragma unroll
        for (int j = 0; j < 4; j++) bv[j] = Bs[s * 65 + nt + 16 * j];
#pragma unroll
        for (int i = 0; i < 4; i++) xv[i] = xs[s * 65 + pt + 16 * i];
#pragma unroll
        for (int i = 0; i < 4; i++)
#pragma unroll
            for (int j = 0; j < 4; j++)
                acc[i][j] = fmaf(bv[j], xv[i], acc[i][j]);
    }
    size_t sbo = (size_t)((b * 32 + c) * 32 + h) * (HDIM * DSTATE);
#pragma unroll
    for (int i = 0; i < 4; i++)
#pragma unroll
        for (int j = 0; j < 4; j++)
            g_states16[sbo + (pt + 16 * i) * 64 + nt + 16 * j] = __float2half_rn(acc[i][j]);
}

// ================= inter-chunk scan (fp32 carry, fp16 io) =================
__global__ void __launch_bounds__(256) scan_kernel()
{
    int bi = blockIdx.x;
    int q = bi & 15;
    int bh = bi >> 4;
    int b = bh >> 5, h = bh & 31;
    int e = q * 256 + threadIdx.x;
    float carry = 0.f;
    for (int c = 0; c < NCHUNK; c++) {
        size_t sbo = (size_t)((b * 32 + c) * 32 + h) * (HDIM * DSTATE);
        float dec = expf(g_dacum[((b * 32 + h) * 32 + c) * CHUNKSZ + 127]);
        g_prev16[sbo + e] = __float2half_rn(carry);
        carry = fmaf(carry, dec, __half2float(g_states16[sbo + e]));
    }
}

// ================= fused Y kernel (8x4 tiled phase 2, fp16 io) =================
#define SMEM_Y ((3 * 128 * 65 + 128 * 129 + 64 * 65 + 128) * 4)
__global__ void __launch_bounds__(256, 1) y_kernel(const float* __restrict__ zb,
                                                   const float* __restrict__ Dp)
{
    extern __shared__ float sm[];
    float* Cs = sm;                    // [128][65]
    float* Bs = Cs + 128 * 65;         // [128][65]
    float* xs = Bs + 128 * 65;         // [128][65]
    float* G  = xs + 128 * 65;         // [128][129]
    float* pT = G + 128 * 129;         // [64][65]
    float* da = pT + 64 * 65;          // [128]

    int bi = blockIdx.x;
    int h = bi & 31, c = (bi >> 5) & 31, b = bi >> 10;
    int tid = threadIdx.x;
    int base_t = b * SEQLEN + c * CHUNKSZ;
    int dab = ((b * 32 + h) * 32 + c) * CHUNKSZ;
    size_t pb = (size_t)((b * 32 + c) * 32 + h) * (HDIM * DSTATE);

    if (tid < 128) da[tid] = g_dacum[dab + tid];
#pragma unroll
    for (int i = 0; i < 32; i++) {
        int flat = tid + 256 * i;
        int s = flat >> 6, p = flat & 63;
        size_t goff = (size_t)(base_t + s) * DXBC + h * 64 + p;
        xs[s * 65 + p] = __half2float(g_xbc16[goff]);
        Bs[s * 65 + p] = __half2float(g_xbc16[goff + DINNER]);
        Cs[s * 65 + p] = __half2float(g_xbc16[goff + 2 * DINNER]);
    }
#pragma unroll
    for (int i = 0; i < 16; i++) {
        int flat = tid + 256 * i;
        int p = flat >> 6, n = flat & 63;
        pT[n * 65 + p] = __half2float(g_prev16[pb + flat]);
    }
    __syncthreads();

    // ---- phase 1: G = (C B^T) .* L ----
    {
        int tr = tid >> 4, tc = tid & 15;
        float accg[8][8];
#pragma unroll
        for (int i = 0; i < 8; i++)
#pragma unroll
            for (int j = 0; j < 8; j++) accg[i][j] = 0.f;
        for (int n = 0; n < DSTATE; n++) {
            float a[8], bb[8];
#pragma unroll
            for (int i = 0; i < 8; i++) a[i] = Cs[(tr + 16 * i) * 65 + n];
#pragma unroll
            for (int j = 0; j < 8; j++) bb[j] = Bs[(tc + 16 * j) * 65 + n];
#pragma unroll
            for (int i = 0; i < 8; i++)
#pragma unroll
                for (int j = 0; j < 8; j++)
                    accg[i][j] = fmaf(a[i], bb[j], accg[i][j]);
        }
#pragma unroll
        for (int i = 0; i < 8; i++) {
            int l = tr + 16 * i;
            float dal = da[l];
#pragma unroll
            for (int j = 0; j < 8; j++) {
                int s = tc + 16 * j;
                G[l * 129 + s] = (s <= l) ? accg[i][j] * __expf(dal - da[s]) : 0.f;
            }
        }
    }
    __syncthreads();

    // ---- phase 2 (8l x 4p tiled): Y = G@x + exp(da)*C.prev + D*x; gate; fp16 out ----
    {
        int lt = tid >> 4;
        int pt = tid & 15;
        float acc[8][4], acc2[8][4];
#pragma unroll
        for (int i = 0; i < 8; i++)
#pragma unroll
            for (int j = 0; j < 4; j++) { acc[i][j] = 0.f; acc2[i][j] = 0.f; }

        for (int s = 0; s < CHUNKSZ; s++) {
            float gv[8], xv[4];
#pragma unroll
            for (int i = 0; i < 8; i++) gv[i] = G[(lt + 16 * i) * 129 + s];
#pragma unroll
            for (int j = 0; j < 4; j++) xv[j] = xs[s * 65 + pt + 16 * j];
#pragma unroll
            for (int i = 0; i < 8; i++)
#pragma unroll
                for (int j = 0; j < 4; j++)
                    acc[i][j] = fmaf(gv[i], xv[j], acc[i][j]);
        }
        for (int n = 0; n < DSTATE; n++) {
            float cv[8], pv[4];
#pragma unroll
            for (int i = 0; i < 8; i++) cv[i] = Cs[(lt + 16 * i) * 65 + n];
#pragma unroll
            for (int j = 0; j < 4; j++) pv[j] = pT[n * 65 + pt + 16 * j];
#pragma unroll
            for (int i = 0; i < 8; i++)
#pragma unroll
                for (int j = 0; j < 4; j++)
                    acc2[i][j] = fmaf(cv[i], pv[j], acc2[i][j]);
        }

        float Dh = Dp[h];
        float zbias[4];
#pragma unroll
        for (int j = 0; j < 4; j++) zbias[j] = zb[h * 64 + pt + 16 * j];

#pragma unroll
        for (int i = 0; i < 8; i++) {
            int l = lt + 16 * i;
            int t = base_t + l;
            float eda = __expf(da[l]);
#pragma unroll
            for (int j = 0; j < 4; j++) {
                int p = pt + 16 * j;
                int chn = h * 64 + p;
                float yv = acc[i][j] + eda * acc2[i][j] + Dh * xs[l * 65 + p];
                float zv = __half2float(g_proj16[(size_t)t * DPROJ + DXBC + chn]) + zbias[j];
                float sil = zv / (1.f + expf(-zv));
                g_yz16[(size_t)t * DINNER + chn] = __float2half_rn(yv * sil);
            }
        }
    }
}

// ================= launch =================
extern "C" void kernel_launch(void* const* d_in, const int* in_sizes, int n_in,
                              void* d_out, int out_size)
{
    const float* u          = (const float*)d_in[0];
    const float* in_proj_w  = (const float*)d_in[1];
    const float* z_bias     = (const float*)d_in[2];
    const float* conv_w     = (const float*)d_in[3];
    const float* conv_b     = (const float*)d_in[4];
    const float* Dparam     = (const float*)d_in[5];
    const float* out_proj_w = (const float*)d_in[6];
    float* out = (float*)d_out;

    void *p_proj = nullptr, *p_yz = nullptr, *p_ua = nullptr, *p_wa = nullptr, *p_wo = nullptr;
    cudaGetSymbolAddress(&p_proj, g_proj16);
    cudaGetSymbolAddress(&p_yz, g_yz16);
    cudaGetSymbolAddress(&p_ua, g_ua16);
    cudaGetSymbolAddress(&p_wa, g_wa16);
    cudaGetSymbolAddress(&p_wo, g_wo16);

    cudaFuncSetAttribute((const void*)gemm_h<256, true>,
                         cudaFuncAttributeMaxDynamicSharedMemorySize, SMEM_GEMM_MAX);
    cudaFuncSetAttribute((const void*)gemm_h<128, false>,
                         cudaFuncAttributeMaxDynamicSharedMemorySize,
                         NSTAGE * (A_HALVES + 128 * TSTRIDE_H) * 2);
    cudaFuncSetAttribute(states_kernel, cudaFuncAttributeMaxDynamicSharedMemorySize, SMEM_STATES);
    cudaFuncSetAttribute(y_kernel, cudaFuncAttributeMaxDynamicSharedMemorySize, SMEM_Y);

    // 0) f32 -> f16 operand conversion
    f2h_kernel<<<(NTOK * DMODEL / 2 + 255) / 256, 256>>>(u, (__half*)p_ua, NTOK * DMODEL / 2);
    f2h_kernel<<<(DPROJ * DMODEL / 2 + 255) / 256, 256>>>(in_proj_w, (__half*)p_wa, DPROJ * DMODEL / 2);
    f2h_kernel<<<(DMODEL * DINNER / 2 + 255) / 256, 256>>>(out_proj_w, (__half*)p_wo, DMODEL * DINNER / 2);

    // 1) in_proj GEMM: [8192,1024] x [8224,1024]^T, BN=256, fp16 out
    {
        dim3 grid((DPROJ + 255) / 256, NTOK / 128);
        gemm_h<256, true><<<grid, 256, SMEM_GEMM_MAX>>>(
            (const __half*)p_ua, (const __half*)p_wa, p_proj, NTOK, DPROJ, DMODEL);
    }
    // 2) conv + silu (fp16 io)
    {
        dim3 grid(DXBC / 256, NTOK / 16);
        conv_silu_kernel<<<grid, 256>>>(conv_w, conv_b);
    }
    // 3) dA cumsum
    dacum_kernel<<<(BATCH * NHEADS * NCHUNK * 32 + 255) / 256, 256>>>();
    // 4) chunk states
    states_kernel<<<BATCH * NCHUNK * NHEADS, 256, SMEM_STATES>>>();
    // 5) inter-chunk scan
    scan_kernel<<<BATCH * NHEADS * 16, 256>>>();
    // 6) fused Y + gating (emits fp16 yz)
    y_kernel<<<BATCH * NCHUNK * NHEADS, 256, SMEM_Y>>>(z_bias, Dparam);
    // 7) out_proj GEMM: [8192,2048] x [1024,2048]^T, BN=128, fp32 out
    {
        dim3 grid(DMODEL / 128, NTOK / 128);
        gemm_h<128, false><<<grid, 256, NSTAGE * (A_HALVES + 128 * TSTRIDE_H) * 2>>>(
            (const __half*)p_yz, (const __half*)p_wo, out, NTOK, DMODEL, DINNER);
    }
}

// round 10
// speedup vs baseline: 1.6222x; 1.2996x over previous
#include <cuda_runtime.h>
#include <cuda_fp16.h>
#include <cstdint>
#include <math.h>

// ---------------- problem constants ----------------
#define BATCH    2
#define SEQLEN   4096
#define NTOK     8192
#define DMODEL   1024
#define DINNER   2048
#define DSTATE   64
#define NHEADS   32
#define HDIM     64
#define CONVK    4
#define CHUNKSZ  128
#define NCHUNK   32
#define DXBC     6144
#define DPROJ    8224

// ---------------- device scratch (allocation-free) ----------------
__device__ __half g_proj16[(size_t)NTOK * DPROJ];
__device__ __half g_xbc16[(size_t)NTOK * DXBC];
__device__ float  g_dacum[BATCH * NHEADS * NCHUNK * CHUNKSZ];
__device__ __half g_states16[(size_t)BATCH * NCHUNK * NHEADS * HDIM * DSTATE];
__device__ __half g_prev16[(size_t)BATCH * NCHUNK * NHEADS * HDIM * DSTATE];
__device__ __half g_yz16[(size_t)NTOK * DINNER];
__device__ __half g_ua16[(size_t)NTOK * DMODEL];
__device__ __half g_wa16[(size_t)DPROJ * DMODEL];
__device__ __half g_wo16[(size_t)DMODEL * DINNER];

// ================= helpers =================
__device__ __forceinline__ uint32_t smem_u32(const void* p) {
    uint32_t a;
    asm("{ .reg .u64 t; cvta.to.shared.u64 t, %1; cvt.u32.u64 %0, t; }" : "=r"(a) : "l"(p));
    return a;
}
__device__ __forceinline__ void cp_async16(uint32_t s, const void* g) {
    asm volatile("cp.async.cg.shared.global [%0], [%1], 16;" :: "r"(s), "l"(g) : "memory");
}
__device__ __forceinline__ void sts_zero16(uint32_t s) {
    asm volatile("st.shared.v4.b32 [%0], {%1,%1,%1,%1};" :: "r"(s), "r"(0u) : "memory");
}
#define CP_COMMIT() asm volatile("cp.async.commit_group;" ::: "memory")
#define CP_WAIT2()  asm volatile("cp.async.wait_group 2;" ::: "memory")

__device__ __forceinline__ void mma_fp16(float& d0, float& d1, float& d2, float& d3,
                                         uint32_t a0, uint32_t a1, uint32_t a2, uint32_t a3,
                                         uint32_t b0, uint32_t b1) {
    asm volatile(
        "mma.sync.aligned.m16n8k16.row.col.f32.f16.f16.f32 "
        "{%0,%1,%2,%3}, {%4,%5,%6,%7}, {%8,%9}, {%0,%1,%2,%3};"
        : "+f"(d0), "+f"(d1), "+f"(d2), "+f"(d3)
        : "r"(a0), "r"(a1), "r"(a2), "r"(a3), "r"(b0), "r"(b1));
}

// ================= f32 -> f16 conversion =================
__global__ void f2h_kernel(const float* __restrict__ in, __half* __restrict__ out, int n2) {
    int i = blockIdx.x * blockDim.x + threadIdx.x;
    if (i >= n2) return;
    float2 v = ((const float2*)in)[i];
    ((__half2*)out)[i] = __floats2half2_rn(v.x, v.y);
}

// ================= FP16 mma.sync GEMM (NT): C[m,n] = sum_k A[m,k]B[n,k] =================
#define KTILE    32
#define NSTAGE   4
#define TSTRIDE_H 40
#define A_HALVES (128 * TSTRIDE_H)
#define SMEM_GEMM_MAX (NSTAGE * (A_HALVES + 256 * TSTRIDE_H) * 2)

template<int BN>
__device__ __forceinline__ void load_tile_h(const __half* __restrict__ A,
                                            const __half* __restrict__ B,
                                            int K, int Nn, int bm, int bn,
                                            int ti, uint32_t sb, int tid)
{
    constexpr int STAGE_H = A_HALVES + BN * TSTRIDE_H;
    uint32_t st = sb + (uint32_t)(ti & (NSTAGE - 1)) * (STAGE_H * 2);
    const __half* ag = A + (size_t)bm * K + (size_t)ti * KTILE;
#pragma unroll
    for (int i = 0; i < 2; i++) {
        int flat = tid + (i << 8);
        int r = flat >> 2, c = flat & 3;
        cp_async16(st + r * (TSTRIDE_H * 2) + c * 16, ag + (size_t)r * K + c * 8);
    }
    uint32_t stb = st + A_HALVES * 2;
    const __half* bg = B + (size_t)ti * KTILE;
#pragma unroll
    for (int i = 0; i < BN / 64; i++) {
        int flat = tid + (i << 8);
        int r = flat >> 2, c = flat & 3;
        uint32_t so = stb + r * (TSTRIDE_H * 2) + c * 16;
        int gn = bn + r;
        if (gn < Nn) cp_async16(so, bg + (size_t)gn * K + c * 8);
        else         sts_zero16(so);
    }
}

template<int BN, bool HALF_OUT>
__global__ void __launch_bounds__(256, 1)
gemm_h(const __half* __restrict__ A, const __half* __restrict__ B,
       void* __restrict__ Cv, int M, int Nn, int K)
{
    constexpr int NI = BN / 32;
    constexpr int STAGE_H = A_HALVES + BN * TSTRIDE_H;
    extern __shared__ __align__(16) uint32_t dsm32[];
    const int tid = threadIdx.x;
    const int wid = tid >> 5;
    const int lane = tid & 31;
    const int g = lane >> 2;
    const int q = lane & 3;
    const int wm = (wid & 1) * 64;
    const int wn = (wid >> 1) * (BN / 4);
    const int KT = K / KTILE;
    const int bm = blockIdx.y << 7;
    const int bn = blockIdx.x * BN;
    uint32_t sb = smem_u32(dsm32);

    float acc[4][NI][4];
#pragma unroll
    for (int mi = 0; mi < 4; mi++)
#pragma unroll
        for (int ni = 0; ni < NI; ni++)
#pragma unroll
            for (int e = 0; e < 4; e++) acc[mi][ni][e] = 0.f;

#pragma unroll
    for (int t = 0; t < 3; t++) {
        load_tile_h<BN>(A, B, K, Nn, bm, bn, t, sb, tid);
        CP_COMMIT();
    }

    for (int kt = 0; kt < KT; kt++) {
        CP_WAIT2();
        __syncthreads();
        int ld = kt + 3;
        if (ld < KT) load_tile_h<BN>(A, B, K, Nn, bm, bn, ld, sb, tid);
        CP_COMMIT();

        const uint32_t* As = dsm32 + (kt & (NSTAGE - 1)) * (STAGE_H / 2);
        const uint32_t* Bs = As + A_HALVES / 2;
#pragma unroll
        for (int ks = 0; ks < 2; ks++) {
            int kq = ks * 8 + q;
            uint32_t a[4][4];
#pragma unroll
            for (int mi = 0; mi < 4; mi++) {
                int row = wm + mi * 16;
                a[mi][0] = As[(row + g)     * 20 + kq];
                a[mi][1] = As[(row + g + 8) * 20 + kq];
                a[mi][2] = As[(row + g)     * 20 + kq + 4];
                a[mi][3] = As[(row + g + 8) * 20 + kq + 4];
            }
            uint32_t b[NI][2];
#pragma unroll
            for (int ni = 0; ni < NI; ni++) {
                int col = wn + ni * 8;
                b[ni][0] = Bs[(col + g) * 20 + kq];
                b[ni][1] = Bs[(col + g) * 20 + kq + 4];
            }
#pragma unroll
            for (int mi = 0; mi < 4; mi++)
#pragma unroll
                for (int ni = 0; ni < NI; ni++)
                    mma_fp16(acc[mi][ni][0], acc[mi][ni][1], acc[mi][ni][2], acc[mi][ni][3],
                             a[mi][0], a[mi][1], a[mi][2], a[mi][3],
                             b[ni][0], b[ni][1]);
        }
    }

#pragma unroll
    for (int mi = 0; mi < 4; mi++) {
#pragma unroll
        for (int ni = 0; ni < NI; ni++) {
            int col = bn + wn + ni * 8 + 2 * q;
            if (col < Nn) {
                int r0 = bm + wm + mi * 16 + g;
                if (HALF_OUT) {
                    __half* C = (__half*)Cv;
                    *(__half2*)(C + (size_t)r0 * Nn + col) =
                        __floats2half2_rn(acc[mi][ni][0], acc[mi][ni][1]);
                    *(__half2*)(C + (size_t)(r0 + 8) * Nn + col) =
                        __floats2half2_rn(acc[mi][ni][2], acc[mi][ni][3]);
                } else {
                    float* C = (float*)Cv;
                    *(float2*)(C + (size_t)r0 * Nn + col) =
                        make_float2(acc[mi][ni][0], acc[mi][ni][1]);
                    *(float2*)(C + (size_t)(r0 + 8) * Nn + col) =
                        make_float2(acc[mi][ni][2], acc[mi][ni][3]);
                }
            }
        }
    }
}

// ================= conv + silu =================
__global__ void __launch_bounds__(256) conv_silu_kernel(const float* __restrict__ cw,
                                                        const float* __restrict__ cb)
{
    int ch = blockIdx.x * 256 + threadIdx.x;
    int tb = blockIdx.y * 16;
    int b = tb >> 12;
    int l0 = tb & (SEQLEN - 1);
    float c0 = cw[ch * 4 + 0], c1 = cw[ch * 4 + 1], c2 = cw[ch * 4 + 2], c3 = cw[ch * 4 + 3];
    float bias = cb[ch];
    const __half* base = g_proj16 + (size_t)(b * SEQLEN) * DPROJ + ch;
    __half* outb = g_xbc16 + (size_t)(b * SEQLEN) * DXBC + ch;
    float w0 = (l0 >= 3) ? __half2float(base[(size_t)(l0 - 3) * DPROJ]) : 0.f;
    float w1 = (l0 >= 2) ? __half2float(base[(size_t)(l0 - 2) * DPROJ]) : 0.f;
    float w2 = (l0 >= 1) ? __half2float(base[(size_t)(l0 - 1) * DPROJ]) : 0.f;
#pragma unroll
    for (int tt = 0; tt < 16; tt++) {
        float xv = __half2float(base[(size_t)(l0 + tt) * DPROJ]);
        float a = fmaf(c3, xv, fmaf(c2, w2, fmaf(c1, w1, fmaf(c0, w0, bias))));
        outb[(size_t)(l0 + tt) * DXBC] = __float2half_rn(a / (1.f + expf(-a)));
        w0 = w1; w1 = w2; w2 = xv;
    }
}

// ================= dA cumsum =================
__global__ void __launch_bounds__(256) dacum_kernel()
{
    int gw = (blockIdx.x * blockDim.x + threadIdx.x) >> 5;
    int lane = threadIdx.x & 31;
    if (gw >= BATCH * NHEADS * NCHUNK) return;
    int c = gw & 31, h = (gw >> 5) & 31, b = gw >> 10;
    int t0 = b * SEQLEN + c * CHUNKSZ + lane * 4;
    float p[4], run = 0.f;
#pragma unroll
    for (int j = 0; j < 4; j++) {
        float v = __half2float(g_proj16[(size_t)(t0 + j) * DPROJ + (DXBC + DINNER) + h]);
        run += fmaxf(v, 0.f) + log1pf(expf(-fabsf(v)));
        p[j] = run;
    }
    float tot = run;
#pragma unroll
    for (int off = 1; off < 32; off <<= 1) {
        float nb = __shfl_up_sync(0xFFFFFFFFu, tot, off);
        if (lane >= off) tot += nb;
    }
    float excl = tot - run;
    int ob = ((b * 32 + h) * 32 + c) * CHUNKSZ + lane * 4;
#pragma unroll
    for (int j = 0; j < 4; j++) g_dacum[ob + j] = -(excl + p[j]);
}

// ================= chunk states: 4x4 register tiling, fp16 io =================
#define SMEM_STATES ((2 * 128 * 65 + 128) * 4)
__global__ void __launch_bounds__(256, 2) states_kernel()
{
    extern __shared__ float sm[];
    float* Bs = sm;
    float* xs = sm + 128 * 65;
    float* da = xs + 128 * 65;

    int bi = blockIdx.x;
    int h = bi & 31, c = (bi >> 5) & 31, b = bi >> 10;
    int tid = threadIdx.x;
    int base_t = b * SEQLEN + c * CHUNKSZ;
    int dab = ((b * 32 + h) * 32 + c) * CHUNKSZ;

    if (tid < 128) da[tid] = g_dacum[dab + tid];
    __syncthreads();
    float da_last = da[127];

#pragma unroll
    for (int i = 0; i < 32; i++) {
        int flat = tid + 256 * i;
        int s = flat >> 6, p = flat & 63;
        size_t goff = (size_t)(base_t + s) * DXBC + h * 64 + p;
        float dec = __expf(da_last - da[s]);
        xs[s * 65 + p] = __half2float(g_xbc16[goff]) * dec;
        Bs[s * 65 + p] = __half2float(g_xbc16[goff + DINNER]);
    }
    __syncthreads();

    int nt = tid & 15, pt = tid >> 4;
    float acc[4][4];
#pragma unroll
    for (int i = 0; i < 4; i++)
#pragma unroll
        for (int j = 0; j < 4; j++) acc[i][j] = 0.f;

    for (int s = 0; s < CHUNKSZ; s++) {
        float bv[4], xv[4];
#pragma unroll
        for (int j = 0; j < 4; j++) bv[j] = Bs[s * 65 + nt + 16 * j];
#pragma unroll
        for (int i = 0; i < 4; i++) xv[i] = xs[s * 65 + pt + 16 * i];
#pragma unroll
        for (int i = 0; i < 4; i++)
#pragma unroll
            for (int j = 0; j < 4; j++)
                acc[i][j] = fmaf(bv[j], xv[i], acc[i][j]);
    }
    size_t sbo = (size_t)((b * 32 + c) * 32 + h) * (HDIM * DSTATE);
#pragma unroll
    for (int i = 0; i < 4; i++)
#pragma unroll
        for (int j = 0; j < 4; j++)
            g_states16[sbo + (pt + 16 * i) * 64 + nt + 16 * j] = __float2half_rn(acc[i][j]);
}

// ================= inter-chunk scan =================
__global__ void __launch_bounds__(256) scan_kernel()
{
    int bi = blockIdx.x;
    int q = bi & 15;
    int bh = bi >> 4;
    int b = bh >> 5, h = bh & 31;
    int e = q * 256 + threadIdx.x;
    float carry = 0.f;
    for (int c = 0; c < NCHUNK; c++) {
        size_t sbo = (size_t)((b * 32 + c) * 32 + h) * (HDIM * DSTATE);
        float dec = expf(g_dacum[((b * 32 + h) * 32 + c) * CHUNKSZ + 127]);
        g_prev16[sbo + e] = __float2half_rn(carry);
        carry = fmaf(carry, dec, __half2float(g_states16[sbo + e]));
    }
}

// ================= fused Y kernel — tensor-core version =================
// smem halves layout: Cs[128][72] | Bs[128][72] | xT[64][136] | G[128][136] | pT[64][72]
// then da[128] fp32.  u32 offsets: Cs 0 / Bs 4608 / xT 9216 / G 13568 / pT 22272.
#define YH_CS 0
#define YH_BS 9216
#define YH_XT 18432
#define YH_G  27136
#define YH_PT 44544
#define YH_HALVES 49152
#define SMEM_Y (YH_HALVES * 2 + 512)

__global__ void __launch_bounds__(256, 1) y_kernel(const float* __restrict__ zb,
                                                   const float* __restrict__ Dp)
{
    extern __shared__ __align__(16) __half ysm[];
    float* da = (float*)(ysm + YH_HALVES);
    uint32_t* smu = (uint32_t*)ysm;

    int bi = blockIdx.x;
    int h = bi & 31, c = (bi >> 5) & 31, b = bi >> 10;
    int tid = threadIdx.x;
    int wid = tid >> 5, lane = tid & 31;
    int g = lane >> 2, q = lane & 3;
    int base_t = b * SEQLEN + c * CHUNKSZ;
    int dab = ((b * 32 + h) * 32 + c) * CHUNKSZ;
    size_t pb = (size_t)((b * 32 + c) * 32 + h) * (HDIM * DSTATE);

    if (tid < 128) da[tid] = g_dacum[dab + tid];
#pragma unroll
    for (int i = 0; i < 32; i++) {
        int flat = tid + 256 * i;
        int s = flat >> 6, p = flat & 63;
        size_t goff = (size_t)(base_t + s) * DXBC + h * 64 + p;
        __half xv = g_xbc16[goff];
        ysm[YH_BS + s * 72 + p] = g_xbc16[goff + DINNER];
        ysm[YH_CS + s * 72 + p] = g_xbc16[goff + 2 * DINNER];
        ysm[YH_XT + p * 136 + s] = xv;                    // x transposed [p][s]
    }
#pragma unroll
    for (int i = 0; i < 16; i++) {
        int flat = tid + 256 * i;
        int p = flat >> 6, n = flat & 63;
        ysm[YH_PT + p * 72 + n] = g_prev16[pb + flat];    // prev [p][n]
    }
    __syncthreads();

    const uint32_t* Cu = smu;               // stride 36
    const uint32_t* Bu = smu + 4608;        // stride 36
    const uint32_t* Xu = smu + 9216;        // stride 68
    const uint32_t* Gu = smu + 13568;       // stride 68
    const uint32_t* Pu = smu + 22272;       // stride 36

    // ---- phase 1: G[l,s] = (C B^T) .* mask.decay   (128x128x64 mma) ----
    {
        int l0 = (wid & 3) * 32, s0 = (wid >> 2) * 64;
        float accg[2][8][4];
#pragma unroll
        for (int mi = 0; mi < 2; mi++)
#pragma unroll
            for (int ni = 0; ni < 8; ni++)
#pragma unroll
                for (int e = 0; e < 4; e++) accg[mi][ni][e] = 0.f;

#pragma unroll
        for (int ks = 0; ks < 4; ks++) {
            int kq = ks * 8 + q;
            uint32_t a[2][4];
#pragma unroll
            for (int mi = 0; mi < 2; mi++) {
                int row = l0 + mi * 16;
                a[mi][0] = Cu[(row + g)     * 36 + kq];
                a[mi][1] = Cu[(row + g + 8) * 36 + kq];
                a[mi][2] = Cu[(row + g)     * 36 + kq + 4];
                a[mi][3] = Cu[(row + g + 8) * 36 + kq + 4];
            }
            uint32_t bf[8][2];
#pragma unroll
            for (int ni = 0; ni < 8; ni++) {
                int col = s0 + ni * 8;
                bf[ni][0] = Bu[(col + g) * 36 + kq];
                bf[ni][1] = Bu[(col + g) * 36 + kq + 4];
            }
#pragma unroll
            for (int mi = 0; mi < 2; mi++)
#pragma unroll
                for (int ni = 0; ni < 8; ni++)
                    mma_fp16(accg[mi][ni][0], accg[mi][ni][1], accg[mi][ni][2], accg[mi][ni][3],
                             a[mi][0], a[mi][1], a[mi][2], a[mi][3],
                             bf[ni][0], bf[ni][1]);
        }
        // mask + decay + store G (fp16)
#pragma unroll
        for (int mi = 0; mi < 2; mi++) {
            int lA = l0 + mi * 16 + g;
            int lB = lA + 8;
            float daA = da[lA], daB = da[lB];
#pragma unroll
            for (int ni = 0; ni < 8; ni++) {
                int s = s0 + ni * 8 + 2 * q;
                float das0 = da[s], das1 = da[s + 1];
                float gA0 = (s     <= lA) ? accg[mi][ni][0] * __expf(daA - das0) : 0.f;
                float gA1 = (s + 1 <= lA) ? accg[mi][ni][1] * __expf(daA - das1) : 0.f;
                float gB0 = (s     <= lB) ? accg[mi][ni][2] * __expf(daB - das0) : 0.f;
                float gB1 = (s + 1 <= lB) ? accg[mi][ni][3] * __expf(daB - das1) : 0.f;
                *(__half2*)(ysm + YH_G + lA * 136 + s) = __floats2half2_rn(gA0, gA1);
                *(__half2*)(ysm + YH_G + lB * 136 + s) = __floats2half2_rn(gB0, gB1);
            }
        }
    }
    __syncthreads();

    // ---- phase 2: Y = G @ x  +  exp(da)*(C @ prev^T)  + D*x; gate; fp16 out ----
    {
        int wl = (wid & 3) * 32, wp = (wid >> 2) * 32;
        float acc1[2][4][4], acc2[2][4][4];
#pragma unroll
        for (int mi = 0; mi < 2; mi++)
#pragma unroll
            for (int ni = 0; ni < 4; ni++)
#pragma unroll
                for (int e = 0; e < 4; e++) { acc1[mi][ni][e] = 0.f; acc2[mi][ni][e] = 0.f; }

        // Y1 = G(l,s) @ xT(p,s): K = 128 (8 k-steps)
#pragma unroll
        for (int ks = 0; ks < 8; ks++) {
            int kq = ks * 8 + q;
            uint32_t a[2][4];
#pragma unroll
            for (int mi = 0; mi < 2; mi++) {
                int row = wl + mi * 16;
                a[mi][0] = Gu[(row + g)     * 68 + kq];
                a[mi][1] = Gu[(row + g + 8) * 68 + kq];
                a[mi][2] = Gu[(row + g)     * 68 + kq + 4];
                a[mi][3] = Gu[(row + g + 8) * 68 + kq + 4];
            }
            uint32_t bf[4][2];
#pragma unroll
            for (int ni = 0; ni < 4; ni++) {
                int col = wp + ni * 8;
                bf[ni][0] = Xu[(col + g) * 68 + kq];
                bf[ni][1] = Xu[(col + g) * 68 + kq + 4];
            }
#pragma unroll
            for (int mi = 0; mi < 2; mi++)
#pragma unroll
                for (int ni = 0; ni < 4; ni++)
                    mma_fp16(acc1[mi][ni][0], acc1[mi][ni][1], acc1[mi][ni][2], acc1[mi][ni][3],
                             a[mi][0], a[mi][1], a[mi][2], a[mi][3],
                             bf[ni][0], bf[ni][1]);
        }
        // Y2 = C(l,n) @ prev(p,n): K = 64 (4 k-steps)
#pragma unroll
        for (int ks = 0; ks < 4; ks++) {
            int kq = ks * 8 + q;
            uint32_t a[2][4];
#pragma unroll
            for (int mi = 0; mi < 2; mi++) {
                int row = wl + mi * 16;
                a[mi][0] = Cu[(row + g)     * 36 + kq];
                a[mi][1] = Cu[(row + g + 8) * 36 + kq];
                a[mi][2] = Cu[(row + g)     * 36 + kq + 4];
                a[mi][3] = Cu[(row + g + 8) * 36 + kq + 4];
            }
            uint32_t bf[4][2];
#pragma unroll
            for (int ni = 0; ni < 4; ni++) {
                int col = wp + ni * 8;
                bf[ni][0] = Pu[(col + g) * 36 + kq];
                bf[ni][1] = Pu[(col + g) * 36 + kq + 4];
            }
#pragma unroll
            for (int mi = 0; mi < 2; mi++)
#pragma unroll
                for (int ni = 0; ni < 4; ni++)
                    mma_fp16(acc2[mi][ni][0], acc2[mi][ni][1], acc2[mi][ni][2], acc2[mi][ni][3],
                             a[mi][0], a[mi][1], a[mi][2], a[mi][3],
                             bf[ni][0], bf[ni][1]);
        }

        // epilogue: combine, gate, store
        float Dh = Dp[h];
#pragma unroll
        for (int mi = 0; mi < 2; mi++) {
            int lA = wl + mi * 16 + g;
            int lB = lA + 8;
            float edaA = __expf(da[lA]);
            float edaB = __expf(da[lB]);
            int tA = base_t + lA, tB = base_t + lB;
#pragma unroll
            for (int ni = 0; ni < 4; ni++) {
                int p = wp + ni * 8 + 2 * q;
                int chn = h * 64 + p;
                float zb0 = zb[chn], zb1 = zb[chn + 1];
                float xA0 = __half2float(ysm[YH_XT + p * 136 + lA]);
                float xA1 = __half2float(ysm[YH_XT + (p + 1) * 136 + lA]);
                float xB0 = __half2float(ysm[YH_XT + p * 136 + lB]);
                float xB1 = __half2float(ysm[YH_XT + (p + 1) * 136 + lB]);
                __half2 zA = *(const __half2*)(g_proj16 + (size_t)tA * DPROJ + DXBC + chn);
                __half2 zB = *(const __half2*)(g_proj16 + (size_t)tB * DPROJ + DXBC + chn);

                float yA0 = acc1[mi][ni][0] + edaA * acc2[mi][ni][0] + Dh * xA0;
                float yA1 = acc1[mi][ni][1] + edaA * acc2[mi][ni][1] + Dh * xA1;
                float yB0 = acc1[mi][ni][2] + edaB * acc2[mi][ni][2] + Dh * xB0;
                float yB1 = acc1[mi][ni][3] + edaB * acc2[mi][ni][3] + Dh * xB1;

                float zA0 = __half2float(zA.x) + zb0, zA1 = __half2float(zA.y) + zb1;
                float zB0 = __half2float(zB.x) + zb0, zB1 = __half2float(zB.y) + zb1;
                yA0 *= zA0 / (1.f + expf(-zA0));
                yA1 *= zA1 / (1.f + expf(-zA1));
                yB0 *= zB0 / (1.f + expf(-zB0));
                yB1 *= zB1 / (1.f + expf(-zB1));

                *(__half2*)(g_yz16 + (size_t)tA * DINNER + chn) = __floats2half2_rn(yA0, yA1);
                *(__half2*)(g_yz16 + (size_t)tB * DINNER + chn) = __floats2half2_rn(yB0, yB1);
            }
        }
    }
}

// ================= launch =================
extern "C" void kernel_launch(void* const* d_in, const int* in_sizes, int n_in,
                              void* d_out, int out_size)
{
    const float* u          = (const float*)d_in[0];
    const float* in_proj_w  = (const float*)d_in[1];
    const float* z_bias     = (const float*)d_in[2];
    const float* conv_w     = (const float*)d_in[3];
    const float* conv_b     = (const float*)d_in[4];
    const float* Dparam     = (const float*)d_in[5];
    const float* out_proj_w = (const float*)d_in[6];
    float* out = (float*)d_out;

    void *p_proj = nullptr, *p_yz = nullptr, *p_ua = nullptr, *p_wa = nullptr, *p_wo = nullptr;
    cudaGetSymbolAddress(&p_proj, g_proj16);
    cudaGetSymbolAddress(&p_yz, g_yz16);
    cudaGetSymbolAddress(&p_ua, g_ua16);
    cudaGetSymbolAddress(&p_wa, g_wa16);
    cudaGetSymbolAddress(&p_wo, g_wo16);

    cudaFuncSetAttribute((const void*)gemm_h<256, true>,
                         cudaFuncAttributeMaxDynamicSharedMemorySize, SMEM_GEMM_MAX);
    cudaFuncSetAttribute((const void*)gemm_h<128, false>,
                         cudaFuncAttributeMaxDynamicSharedMemorySize,
                         NSTAGE * (A_HALVES + 128 * TSTRIDE_H) * 2);
    cudaFuncSetAttribute(states_kernel, cudaFuncAttributeMaxDynamicSharedMemorySize, SMEM_STATES);
    cudaFuncSetAttribute(y_kernel, cudaFuncAttributeMaxDynamicSharedMemorySize, SMEM_Y);

    // 0) f32 -> f16 operand conversion
    f2h_kernel<<<(NTOK * DMODEL / 2 + 255) / 256, 256>>>(u, (__half*)p_ua, NTOK * DMODEL / 2);
    f2h_kernel<<<(DPROJ * DMODEL / 2 + 255) / 256, 256>>>(in_proj_w, (__half*)p_wa, DPROJ * DMODEL / 2);
    f2h_kernel<<<(DMODEL * DINNER / 2 + 255) / 256, 256>>>(out_proj_w, (__half*)p_wo, DMODEL * DINNER / 2);

    // 1) in_proj GEMM: BN=256, fp16 out
    {
        dim3 grid((DPROJ + 255) / 256, NTOK / 128);
        gemm_h<256, true><<<grid, 256, SMEM_GEMM_MAX>>>(
            (const __half*)p_ua, (const __half*)p_wa, p_proj, NTOK, DPROJ, DMODEL);
    }
    // 2) conv + silu
    {
        dim3 grid(DXBC / 256, NTOK / 16);
        conv_silu_kernel<<<grid, 256>>>(conv_w, conv_b);
    }
    // 3) dA cumsum
    dacum_kernel<<<(BATCH * NHEADS * NCHUNK * 32 + 255) / 256, 256>>>();
    // 4) chunk states
    states_kernel<<<BATCH * NCHUNK * NHEADS, 256, SMEM_STATES>>>();
    // 5) inter-chunk scan
    scan_kernel<<<BATCH * NHEADS * 16, 256>>>();
    // 6) fused Y + gating (tensor-core)
    y_kernel<<<BATCH * NCHUNK * NHEADS, 256, SMEM_Y>>>(z_bias, Dparam);
    // 7) out_proj GEMM: BN=128, fp32 out
    {
        dim3 grid(DMODEL / 128, NTOK / 128);
        gemm_h<128, false><<<grid, 256, NSTAGE * (A_HALVES + 128 * TSTRIDE_H) * 2>>>(
            (const __half*)p_yz, (const __half*)p_wo, out, NTOK, DMODEL, DINNER);
    }
}

// round 11
// speedup vs baseline: 1.7134x; 1.0562x over previous
#include <cuda_runtime.h>
#include <cuda_fp16.h>
#include <cstdint>
#include <math.h>

// ---------------- problem constants ----------------
#define BATCH    2
#define SEQLEN   4096
#define NTOK     8192
#define DMODEL   1024
#define DINNER   2048
#define DSTATE   64
#define NHEADS   32
#define HDIM     64
#define CONVK    4
#define CHUNKSZ  128
#define NCHUNK   32
#define DXBC     6144
#define DPROJ    8224

// ---------------- device scratch (allocation-free) ----------------
__device__ __half g_proj16[(size_t)NTOK * DPROJ];
__device__ __half g_xbc16[(size_t)NTOK * DXBC];
__device__ float  g_dacum[BATCH * NHEADS * NCHUNK * CHUNKSZ];
__device__ __half g_states16[(size_t)BATCH * NCHUNK * NHEADS * HDIM * DSTATE];
__device__ __half g_prev16[(size_t)BATCH * NCHUNK * NHEADS * HDIM * DSTATE];
__device__ __half g_yz16[(size_t)NTOK * DINNER];
__device__ __half g_ua16[(size_t)NTOK * DMODEL];
__device__ __half g_wa16[(size_t)DPROJ * DMODEL];
__device__ __half g_wo16[(size_t)DMODEL * DINNER];

// ================= helpers =================
__device__ __forceinline__ uint32_t smem_u32(const void* p) {
    uint32_t a;
    asm("{ .reg .u64 t; cvta.to.shared.u64 t, %1; cvt.u32.u64 %0, t; }" : "=r"(a) : "l"(p));
    return a;
}
__device__ __forceinline__ void cp_async16(uint32_t s, const void* g) {
    asm volatile("cp.async.cg.shared.global [%0], [%1], 16;" :: "r"(s), "l"(g) : "memory");
}
__device__ __forceinline__ void sts_zero16(uint32_t s) {
    asm volatile("st.shared.v4.b32 [%0], {%1,%1,%1,%1};" :: "r"(s), "r"(0u) : "memory");
}
#define CP_COMMIT() asm volatile("cp.async.commit_group;" ::: "memory")
#define CP_WAIT2()  asm volatile("cp.async.wait_group 2;" ::: "memory")

__device__ __forceinline__ void mma_fp16(float& d0, float& d1, float& d2, float& d3,
                                         uint32_t a0, uint32_t a1, uint32_t a2, uint32_t a3,
                                         uint32_t b0, uint32_t b1) {
    asm volatile(
        "mma.sync.aligned.m16n8k16.row.col.f32.f16.f16.f32 "
        "{%0,%1,%2,%3}, {%4,%5,%6,%7}, {%8,%9}, {%0,%1,%2,%3};"
        : "+f"(d0), "+f"(d1), "+f"(d2), "+f"(d3)
        : "r"(a0), "r"(a1), "r"(a2), "r"(a3), "r"(b0), "r"(b1));
}

// ================= f32 -> f16 conversion =================
__global__ void f2h_kernel(const float* __restrict__ in, __half* __restrict__ out, int n2) {
    int i = blockIdx.x * blockDim.x + threadIdx.x;
    if (i >= n2) return;
    float2 v = ((const float2*)in)[i];
    ((__half2*)out)[i] = __floats2half2_rn(v.x, v.y);
}

// ================= FP16 mma.sync GEMM (NT): C[m,n] = sum_k A[m,k]B[n,k] =================
// Block 128x128, 8 warps (2x4), warp tile 64x32, k-tile 32 halves, 4-stage pipeline.
// 64 acc regs/thread -> <=128 regs -> 2 CTAs/SM (16 warps: hides LDS latency + barrier).
#define KTILE    32
#define NSTAGE   4
#define TSTRIDE_H 40                             // halves per smem row (32 + 8 pad) = 80B
#define A_HALVES (128 * TSTRIDE_H)               // 5120
#define B_HALVES (128 * TSTRIDE_H)               // 5120
#define STAGE_H  (A_HALVES + B_HALVES)           // 10240
#define SMEM_GEMM (NSTAGE * STAGE_H * 2)         // 81920 bytes -> 2 CTAs/SM

__device__ __forceinline__ void load_tile_h(const __half* __restrict__ A,
                                            const __half* __restrict__ B,
                                            int K, int Nn, int bm, int bn,
                                            int ti, uint32_t sb, int tid)
{
    uint32_t st = sb + (uint32_t)(ti & (NSTAGE - 1)) * (STAGE_H * 2);
    const __half* ag = A + (size_t)bm * K + (size_t)ti * KTILE;
#pragma unroll
    for (int i = 0; i < 2; i++) {                 // A: 128 rows x 4 chunks of 16B
        int flat = tid + (i << 8);
        int r = flat >> 2, c = flat & 3;
        cp_async16(st + r * (TSTRIDE_H * 2) + c * 16, ag + (size_t)r * K + c * 8);
    }
    uint32_t stb = st + A_HALVES * 2;
    const __half* bg = B + (size_t)ti * KTILE;
#pragma unroll
    for (int i = 0; i < 2; i++) {                 // B: 128 rows x 4 chunks of 16B
        int flat = tid + (i << 8);
        int r = flat >> 2, c = flat & 3;
        uint32_t so = stb + r * (TSTRIDE_H * 2) + c * 16;
        int gn = bn + r;
        if (gn < Nn) cp_async16(so, bg + (size_t)gn * K + c * 8);
        else         sts_zero16(so);
    }
}

template<bool HALF_OUT>
__global__ void __launch_bounds__(256, 2)
gemm_h(const __half* __restrict__ A, const __half* __restrict__ B,
       void* __restrict__ Cv, int M, int Nn, int K)
{
    extern __shared__ __align__(16) uint32_t dsm32[];   // half2 view, row stride 20 u32
    const int tid = threadIdx.x;
    const int wid = tid >> 5;
    const int lane = tid & 31;
    const int g = lane >> 2;
    const int q = lane & 3;
    const int wm = (wid & 1) * 64;
    const int wn = (wid >> 1) * 32;
    const int KT = K / KTILE;
    const int bm = blockIdx.y << 7;
    const int bn = blockIdx.x << 7;
    uint32_t sb = smem_u32(dsm32);

    float acc[4][4][4];
#pragma unroll
    for (int mi = 0; mi < 4; mi++)
#pragma unroll
        for (int ni = 0; ni < 4; ni++)
#pragma unroll
            for (int e = 0; e < 4; e++) acc[mi][ni][e] = 0.f;

#pragma unroll
    for (int t = 0; t < 3; t++) {
        load_tile_h(A, B, K, Nn, bm, bn, t, sb, tid);
        CP_COMMIT();
    }

    for (int kt = 0; kt < KT; kt++) {
        CP_WAIT2();
        __syncthreads();
        int ld = kt + 3;
        if (ld < KT) load_tile_h(A, B, K, Nn, bm, bn, ld, sb, tid);
        CP_COMMIT();

        const uint32_t* As = dsm32 + (kt & (NSTAGE - 1)) * (STAGE_H / 2);
        const uint32_t* Bs = As + A_HALVES / 2;
#pragma unroll
        for (int ks = 0; ks < 2; ks++) {
            int kq = ks * 8 + q;
            uint32_t a[4][4];
#pragma unroll
            for (int mi = 0; mi < 4; mi++) {
                int row = wm + mi * 16;
                a[mi][0] = As[(row + g)     * 20 + kq];
                a[mi][1] = As[(row + g + 8) * 20 + kq];
                a[mi][2] = As[(row + g)     * 20 + kq + 4];
                a[mi][3] = As[(row + g + 8) * 20 + kq + 4];
            }
            uint32_t b[4][2];
#pragma unroll
            for (int ni = 0; ni < 4; ni++) {
                int col = wn + ni * 8;
                b[ni][0] = Bs[(col + g) * 20 + kq];
                b[ni][1] = Bs[(col + g) * 20 + kq + 4];
            }
#pragma unroll
            for (int mi = 0; mi < 4; mi++)
#pragma unroll
                for (int ni = 0; ni < 4; ni++)
                    mma_fp16(acc[mi][ni][0], acc[mi][ni][1], acc[mi][ni][2], acc[mi][ni][3],
                             a[mi][0], a[mi][1], a[mi][2], a[mi][3],
                             b[ni][0], b[ni][1]);
        }
    }

#pragma unroll
    for (int mi = 0; mi < 4; mi++) {
#pragma unroll
        for (int ni = 0; ni < 4; ni++) {
            int col = bn + wn + ni * 8 + 2 * q;
            if (col < Nn) {
                int r0 = bm + wm + mi * 16 + g;
                if (HALF_OUT) {
                    __half* C = (__half*)Cv;
                    *(__half2*)(C + (size_t)r0 * Nn + col) =
                        __floats2half2_rn(acc[mi][ni][0], acc[mi][ni][1]);
                    *(__half2*)(C + (size_t)(r0 + 8) * Nn + col) =
                        __floats2half2_rn(acc[mi][ni][2], acc[mi][ni][3]);
                } else {
                    float* C = (float*)Cv;
                    *(float2*)(C + (size_t)r0 * Nn + col) =
                        make_float2(acc[mi][ni][0], acc[mi][ni][1]);
                    *(float2*)(C + (size_t)(r0 + 8) * Nn + col) =
                        make_float2(acc[mi][ni][2], acc[mi][ni][3]);
                }
            }
        }
    }
}

// ================= conv + silu =================
__global__ void __launch_bounds__(256) conv_silu_kernel(const float* __restrict__ cw,
                                                        const float* __restrict__ cb)
{
    int ch = blockIdx.x * 256 + threadIdx.x;
    int tb = blockIdx.y * 16;
    int b = tb >> 12;
    int l0 = tb & (SEQLEN - 1);
    float c0 = cw[ch * 4 + 0], c1 = cw[ch * 4 + 1], c2 = cw[ch * 4 + 2], c3 = cw[ch * 4 + 3];
    float bias = cb[ch];
    const __half* base = g_proj16 + (size_t)(b * SEQLEN) * DPROJ + ch;
    __half* outb = g_xbc16 + (size_t)(b * SEQLEN) * DXBC + ch;
    float w0 = (l0 >= 3) ? __half2float(base[(size_t)(l0 - 3) * DPROJ]) : 0.f;
    float w1 = (l0 >= 2) ? __half2float(base[(size_t)(l0 - 2) * DPROJ]) : 0.f;
    float w2 = (l0 >= 1) ? __half2float(base[(size_t)(l0 - 1) * DPROJ]) : 0.f;
#pragma unroll
    for (int tt = 0; tt < 16; tt++) {
        float xv = __half2float(base[(size_t)(l0 + tt) * DPROJ]);
        float a = fmaf(c3, xv, fmaf(c2, w2, fmaf(c1, w1, fmaf(c0, w0, bias))));
        outb[(size_t)(l0 + tt) * DXBC] = __float2half_rn(a / (1.f + expf(-a)));
        w0 = w1; w1 = w2; w2 = xv;
    }
}

// ================= dA cumsum =================
__global__ void __launch_bounds__(256) dacum_kernel()
{
    int gw = (blockIdx.x * blockDim.x + threadIdx.x) >> 5;
    int lane = threadIdx.x & 31;
    if (gw >= BATCH * NHEADS * NCHUNK) return;
    int c = gw & 31, h = (gw >> 5) & 31, b = gw >> 10;
    int t0 = b * SEQLEN + c * CHUNKSZ + lane * 4;
    float p[4], run = 0.f;
#pragma unroll
    for (int j = 0; j < 4; j++) {
        float v = __half2float(g_proj16[(size_t)(t0 + j) * DPROJ + (DXBC + DINNER) + h]);
        run += fmaxf(v, 0.f) + log1pf(expf(-fabsf(v)));
        p[j] = run;
    }
    float tot = run;
#pragma unroll
    for (int off = 1; off < 32; off <<= 1) {
        float nb = __shfl_up_sync(0xFFFFFFFFu, tot, off);
        if (lane >= off) tot += nb;
    }
    float excl = tot - run;
    int ob = ((b * 32 + h) * 32 + c) * CHUNKSZ + lane * 4;
#pragma unroll
    for (int j = 0; j < 4; j++) g_dacum[ob + j] = -(excl + p[j]);
}

// ================= chunk states: 4x4 register tiling, fp16 io =================
#define SMEM_STATES ((2 * 128 * 65 + 128) * 4)
__global__ void __launch_bounds__(256, 2) states_kernel()
{
    extern __shared__ float sm[];
    float* Bs = sm;
    float* xs = sm + 128 * 65;
    float* da = xs + 128 * 65;

    int bi = blockIdx.x;
    int h = bi & 31, c = (bi >> 5) & 31, b = bi >> 10;
    int tid = threadIdx.x;
    int base_t = b * SEQLEN + c * CHUNKSZ;
    int dab = ((b * 32 + h) * 32 + c) * CHUNKSZ;

    if (tid < 128) da[tid] = g_dacum[dab + tid];
    __syncthreads();
    float da_last = da[127];

#pragma unroll
    for (int i = 0; i < 32; i++) {
        int flat = tid + 256 * i;
        int s = flat >> 6, p = flat & 63;
        size_t goff = (size_t)(base_t + s) * DXBC + h * 64 + p;
        float dec = __expf(da_last - da[s]);
        xs[s * 65 + p] = __half2float(g_xbc16[goff]) * dec;
        Bs[s * 65 + p] = __half2float(g_xbc16[goff + DINNER]);
    }
    __syncthreads();

    int nt = tid & 15, pt = tid >> 4;
    float acc[4][4];
#pragma unroll
    for (int i = 0; i < 4; i++)
#pragma unroll
        for (int j = 0; j < 4; j++) acc[i][j] = 0.f;

    for (int s = 0; s < CHUNKSZ; s++) {
        float bv[4], xv[4];
#pragma unroll
        for (int j = 0; j < 4; j++) bv[j] = Bs[s * 65 + nt + 16 * j];
#pragma unroll
        for (int i = 0; i < 4; i++) xv[i] = xs[s * 65 + pt + 16 * i];
#pragma unroll
        for (int i = 0; i < 4; i++)
#pragma unroll
            for (int j = 0; j < 4; j++)
                acc[i][j] = fmaf(bv[j], xv[i], acc[i][j]);
    }
    size_t sbo = (size_t)((b * 32 + c) * 32 + h) * (HDIM * DSTATE);
#pragma unroll
    for (int i = 0; i < 4; i++)
#pragma unroll
        for (int j = 0; j < 4; j++)
            g_states16[sbo + (pt + 16 * i) * 64 + nt + 16 * j] = __float2half_rn(acc[i][j]);
}

// ================= inter-chunk scan =================
__global__ void __launch_bounds__(256) scan_kernel()
{
    int bi = blockIdx.x;
    int q = bi & 15;
    int bh = bi >> 4;
    int b = bh >> 5, h = bh & 31;
    int e = q * 256 + threadIdx.x;
    float carry = 0.f;
    for (int c = 0; c < NCHUNK; c++) {
        size_t sbo = (size_t)((b * 32 + c) * 32 + h) * (HDIM * DSTATE);
        float dec = expf(g_dacum[((b * 32 + h) * 32 + c) * CHUNKSZ + 127]);
        g_prev16[sbo + e] = __float2half_rn(carry);
        carry = fmaf(carry, dec, __half2float(g_states16[sbo + e]));
    }
}

// ================= fused Y kernel — tensor-core version =================
#define YH_CS 0
#define YH_BS 9216
#define YH_XT 18432
#define YH_G  27136
#define YH_PT 44544
#define YH_HALVES 49152
#define SMEM_Y (YH_HALVES * 2 + 512)

__global__ void __launch_bounds__(256, 1) y_kernel(const float* __restrict__ zb,
                                                   const float* __restrict__ Dp)
{
    extern __shared__ __align__(16) __half ysm[];
    float* da = (float*)(ysm + YH_HALVES);
    uint32_t* smu = (uint32_t*)ysm;

    int bi = blockIdx.x;
    int h = bi & 31, c = (bi >> 5) & 31, b = bi >> 10;
    int tid = threadIdx.x;
    int wid = tid >> 5, lane = tid & 31;
    int g = lane >> 2, q = lane & 3;
    int base_t = b * SEQLEN + c * CHUNKSZ;
    int dab = ((b * 32 + h) * 32 + c) * CHUNKSZ;
    size_t pb = (size_t)((b * 32 + c) * 32 + h) * (HDIM * DSTATE);

    if (tid < 128) da[tid] = g_dacum[dab + tid];
#pragma unroll
    for (int i = 0; i < 32; i++) {
        int flat = tid + 256 * i;
        int s = flat >> 6, p = flat & 63;
        size_t goff = (size_t)(base_t + s) * DXBC + h * 64 + p;
        __half xv = g_xbc16[goff];
        ysm[YH_BS + s * 72 + p] = g_xbc16[goff + DINNER];
        ysm[YH_CS + s * 72 + p] = g_xbc16[goff + 2 * DINNER];
        ysm[YH_XT + p * 136 + s] = xv;
    }
#pragma unroll
    for (int i = 0; i < 16; i++) {
        int flat = tid + 256 * i;
        int p = flat >> 6, n = flat & 63;
        ysm[YH_PT + p * 72 + n] = g_prev16[pb + flat];
    }
    __syncthreads();

    const uint32_t* Cu = smu;
    const uint32_t* Bu = smu + 4608;
    const uint32_t* Xu = smu + 9216;
    const uint32_t* Gu = smu + 13568;
    const uint32_t* Pu = smu + 22272;

    // ---- phase 1: G = (C B^T) .* mask.decay ----
    {
        int l0 = (wid & 3) * 32, s0 = (wid >> 2) * 64;
        float accg[2][8][4];
#pragma unroll
        for (int mi = 0; mi < 2; mi++)
#pragma unroll
            for (int ni = 0; ni < 8; ni++)
#pragma unroll
                for (int e = 0; e < 4; e++) accg[mi][ni][e] = 0.f;

#pragma unroll
        for (int ks = 0; ks < 4; ks++) {
            int kq = ks * 8 + q;
            uint32_t a[2][4];
#pragma unroll
            for (int mi = 0; mi < 2; mi++) {
                int row = l0 + mi * 16;
                a[mi][0] = Cu[(row + g)     * 36 + kq];
                a[mi][1] = Cu[(row + g + 8) * 36 + kq];
                a[mi][2] = Cu[(row + g)     * 36 + kq + 4];
                a[mi][3] = Cu[(row + g + 8) * 36 + kq + 4];
            }
            uint32_t bf[8][2];
#pragma unroll
            for (int ni = 0; ni < 8; ni++) {
                int col = s0 + ni * 8;
                bf[ni][0] = Bu[(col + g) * 36 + kq];
                bf[ni][1] = Bu[(col + g) * 36 + kq + 4];
            }
#pragma unroll
            for (int mi = 0; mi < 2; mi++)
#pragma unroll
                for (int ni = 0; ni < 8; ni++)
                    mma_fp16(accg[mi][ni][0], accg[mi][ni][1], accg[mi][ni][2], accg[mi][ni][3],
                             a[mi][0], a[mi][1], a[mi][2], a[mi][3],
                             bf[ni][0], bf[ni][1]);
        }
#pragma unroll
        for (int mi = 0; mi < 2; mi++) {
            int lA = l0 + mi * 16 + g;
            int lB = lA + 8;
            float daA = da[lA], daB = da[lB];
#pragma unroll
            for (int ni = 0; ni < 8; ni++) {
                int s = s0 + ni * 8 + 2 * q;
                float das0 = da[s], das1 = da[s + 1];
                float gA0 = (s     <= lA) ? accg[mi][ni][0] * __expf(daA - das0) : 0.f;
                float gA1 = (s + 1 <= lA) ? accg[mi][ni][1] * __expf(daA - das1) : 0.f;
                float gB0 = (s     <= lB) ? accg[mi][ni][2] * __expf(daB - das0) : 0.f;
                float gB1 = (s + 1 <= lB) ? accg[mi][ni][3] * __expf(daB - das1) : 0.f;
                *(__half2*)(ysm + YH_G + lA * 136 + s) = __floats2half2_rn(gA0, gA1);
                *(__half2*)(ysm + YH_G + lB * 136 + s) = __floats2half2_rn(gB0, gB1);
            }
        }
    }
    __syncthreads();

    // ---- phase 2: Y = G @ x + exp(da)*(C @ prev^T) + D*x; gate; fp16 out ----
    {
        int wl = (wid & 3) * 32, wp = (wid >> 2) * 32;
        float acc1[2][4][4], acc2[2][4][4];
#pragma unroll
        for (int mi = 0; mi < 2; mi++)
#pragma unroll
            for (int ni = 0; ni < 4; ni++)
#pragma unroll
                for (int e = 0; e < 4; e++) { acc1[mi][ni][e] = 0.f; acc2[mi][ni][e] = 0.f; }

#pragma unroll
        for (int ks = 0; ks < 8; ks++) {
            int kq = ks * 8 + q;
            uint32_t a[2][4];
#pragma unroll
            for (int mi = 0; mi < 2; mi++) {
                int row = wl + mi * 16;
                a[mi][0] = Gu[(row + g)     * 68 + kq];
                a[mi][1] = Gu[(row + g + 8) * 68 + kq];
                a[mi][2] = Gu[(row + g)     * 68 + kq + 4];
                a[mi][3] = Gu[(row + g + 8) * 68 + kq + 4];
            }
            uint32_t bf[4][2];
#pragma unroll
            for (int ni = 0; ni < 4; ni++) {
                int col = wp + ni * 8;
                bf[ni][0] = Xu[(col + g) * 68 + kq];
                bf[ni][1] = Xu[(col + g) * 68 + kq + 4];
            }
#pragma unroll
            for (int mi = 0; mi < 2; mi++)
#pragma unroll
                for (int ni = 0; ni < 4; ni++)
                    mma_fp16(acc1[mi][ni][0], acc1[mi][ni][1], acc1[mi][ni][2], acc1[mi][ni][3],
                             a[mi][0], a[mi][1], a[mi][2], a[mi][3],
                             bf[ni][0], bf[ni][1]);
        }
#pragma unroll
        for (int ks = 0; ks < 4; ks++) {
            int kq = ks * 8 + q;
            uint32_t a[2][4];
#pragma unroll
            for (int mi = 0; mi < 2; mi++) {
                int row = wl + mi * 16;
                a[mi][0] = Cu[(row + g)     * 36 + kq];
                a[mi][1] = Cu[(row + g + 8) * 36 + kq];
                a[mi][2] = Cu[(row + g)     * 36 + kq + 4];
                a[mi][3] = Cu[(row + g + 8) * 36 + kq + 4];
            }
            uint32_t bf[4][2];
#pragma unroll
            for (int ni = 0; ni < 4; ni++) {
                int col = wp + ni * 8;
                bf[ni][0] = Pu[(col + g) * 36 + kq];
                bf[ni][1] = Pu[(col + g) * 36 + kq + 4];
            }
#pragma unroll
            for (int mi = 0; mi < 2; mi++)
#pragma unroll
                for (int ni = 0; ni < 4; ni++)
                    mma_fp16(acc2[mi][ni][0], acc2[mi][ni][1], acc2[mi][ni][2], acc2[mi][ni][3],
                             a[mi][0], a[mi][1], a[mi][2], a[mi][3],
                             bf[ni][0], bf[ni][1]);
        }

        float Dh = Dp[h];
#pragma unroll
        for (int mi = 0; mi < 2; mi++) {
            int lA = wl + mi * 16 + g;
            int lB = lA + 8;
            float edaA = __expf(da[lA]);
            float edaB = __expf(da[lB]);
            int tA = base_t + lA, tB = base_t + lB;
#pragma unroll
            for (int ni = 0; ni < 4; ni++) {
                int p = wp + ni * 8 + 2 * q;
                int chn = h * 64 + p;
                float zb0 = zb[chn], zb1 = zb[chn + 1];
                float xA0 = __half2float(ysm[YH_XT + p * 136 + lA]);
                float xA1 = __half2float(ysm[YH_XT + (p + 1) * 136 + lA]);
                float xB0 = __half2float(ysm[YH_XT + p * 136 + lB]);
                float xB1 = __half2float(ysm[YH_XT + (p + 1) * 136 + lB]);
                __half2 zA = *(const __half2*)(g_proj16 + (size_t)tA * DPROJ + DXBC + chn);
                __half2 zB = *(const __half2*)(g_proj16 + (size_t)tB * DPROJ + DXBC + chn);

                float yA0 = acc1[mi][ni][0] + edaA * acc2[mi][ni][0] + Dh * xA0;
                float yA1 = acc1[mi][ni][1] + edaA * acc2[mi][ni][1] + Dh * xA1;
                float yB0 = acc1[mi][ni][2] + edaB * acc2[mi][ni][2] + Dh * xB0;
                float yB1 = acc1[mi][ni][3] + edaB * acc2[mi][ni][3] + Dh * xB1;

                float zA0 = __half2float(zA.x) + zb0, zA1 = __half2float(zA.y) + zb1;
                float zB0 = __half2float(zB.x) + zb0, zB1 = __half2float(zB.y) + zb1;
                yA0 *= zA0 / (1.f + expf(-zA0));
                yA1 *= zA1 / (1.f + expf(-zA1));
                yB0 *= zB0 / (1.f + expf(-zB0));
                yB1 *= zB1 / (1.f + expf(-zB1));

                *(__half2*)(g_yz16 + (size_t)tA * DINNER + chn) = __floats2half2_rn(yA0, yA1);
                *(__half2*)(g_yz16 + (size_t)tB * DINNER + chn) = __floats2half2_rn(yB0, yB1);
            }
        }
    }
}

// ================= launch =================
extern "C" void kernel_launch(void* const* d_in, const int* in_sizes, int n_in,
                              void* d_out, int out_size)
{
    const float* u          = (const float*)d_in[0];
    const float* in_proj_w  = (const float*)d_in[1];
    const float* z_bias     = (const float*)d_in[2];
    const float* conv_w     = (const float*)d_in[3];
    const float* conv_b     = (const float*)d_in[4];
    const float* Dparam     = (const float*)d_in[5];
    const float* out_proj_w = (const float*)d_in[6];
    float* out = (float*)d_out;

    void *p_proj = nullptr, *p_yz = nullptr, *p_ua = nullptr, *p_wa = nullptr, *p_wo = nullptr;
    cudaGetSymbolAddress(&p_proj, g_proj16);
    cudaGetSymbolAddress(&p_yz, g_yz16);
    cudaGetSymbolAddress(&p_ua, g_ua16);
    cudaGetSymbolAddress(&p_wa, g_wa16);
    cudaGetSymbolAddress(&p_wo, g_wo16);

    cudaFuncSetAttribute((const void*)gemm_h<true>,
                         cudaFuncAttributeMaxDynamicSharedMemorySize, SMEM_GEMM);
    cudaFuncSetAttribute((const void*)gemm_h<false>,
                         cudaFuncAttributeMaxDynamicSharedMemorySize, SMEM_GEMM);
    cudaFuncSetAttribute(states_kernel, cudaFuncAttributeMaxDynamicSharedMemorySize, SMEM_STATES);
    cudaFuncSetAttribute(y_kernel, cudaFuncAttributeMaxDynamicSharedMemorySize, SMEM_Y);

    // 0) f32 -> f16 operand conversion
    f2h_kernel<<<(NTOK * DMODEL / 2 + 255) / 256, 256>>>(u, (__half*)p_ua, NTOK * DMODEL / 2);
    f2h_kernel<<<(DPROJ * DMODEL / 2 + 255) / 256, 256>>>(in_proj_w, (__half*)p_wa, DPROJ * DMODEL / 2);
    f2h_kernel<<<(DMODEL * DINNER / 2 + 255) / 256, 256>>>(out_proj_w, (__half*)p_wo, DMODEL * DINNER / 2);

    // 1) in_proj GEMM: 128x128 tile, 2 CTAs/SM, fp16 out
    {
        dim3 grid((DPROJ + 127) / 128, NTOK / 128);
        gemm_h<true><<<grid, 256, SMEM_GEMM>>>(
            (const __half*)p_ua, (const __half*)p_wa, p_proj, NTOK, DPROJ, DMODEL);
    }
    // 2) conv + silu
    {
        dim3 grid(DXBC / 256, NTOK / 16);
        conv_silu_kernel<<<grid, 256>>>(conv_w, conv_b);
    }
    // 3) dA cumsum
    dacum_kernel<<<(BATCH * NHEADS * NCHUNK * 32 + 255) / 256, 256>>>();
    // 4) chunk states
    states_kernel<<<BATCH * NCHUNK * NHEADS, 256, SMEM_STATES>>>();
    // 5) inter-chunk scan
    scan_kernel<<<BATCH * NHEADS * 16, 256>>>();
    // 6) fused Y + gating (tensor-core)
    y_kernel<<<BATCH * NCHUNK * NHEADS, 256, SMEM_Y>>>(z_bias, Dparam);
    // 7) out_proj GEMM: 128x128 tile, 2 CTAs/SM, fp32 out
    {
        dim3 grid(DMODEL / 128, NTOK / 128);
        gemm_h<false><<<grid, 256, SMEM_GEMM>>>(
            (const __half*)p_yz, (const __half*)p_wo, out, NTOK, DMODEL, DINNER);
    }
}

// round 12
// speedup vs baseline: 1.8202x; 1.0623x over previous
#include <cuda_runtime.h>
#include <cuda_fp16.h>
#include <cstdint>
#include <math.h>

// ---------------- problem constants ----------------
#define BATCH    2
#define SEQLEN   4096
#define NTOK     8192
#define DMODEL   1024
#define DINNER   2048
#define DSTATE   64
#define NHEADS   32
#define HDIM     64
#define CONVK    4
#define CHUNKSZ  128
#define NCHUNK   32
#define DXBC     6144
#define DPROJ    8224

// ---------------- device scratch (allocation-free) ----------------
__device__ __half g_proj16[(size_t)NTOK * DPROJ];
__device__ __half g_xbc16[(size_t)NTOK * DXBC];
__device__ float  g_dacum[BATCH * NHEADS * NCHUNK * CHUNKSZ];
__device__ __half g_states16[(size_t)BATCH * NCHUNK * NHEADS * HDIM * DSTATE];
__device__ __half g_prev16[(size_t)BATCH * NCHUNK * NHEADS * HDIM * DSTATE];
__device__ __half g_yz16[(size_t)NTOK * DINNER];
__device__ __half g_ua16[(size_t)NTOK * DMODEL];
__device__ __half g_wa16[(size_t)DPROJ * DMODEL];
__device__ __half g_wo16[(size_t)DMODEL * DINNER];

// ================= helpers =================
__device__ __forceinline__ uint32_t smem_u32(const void* p) {
    uint32_t a;
    asm("{ .reg .u64 t; cvta.to.shared.u64 t, %1; cvt.u32.u64 %0, t; }" : "=r"(a) : "l"(p));
    return a;
}
__device__ __forceinline__ void cp_async16(uint32_t s, const void* g) {
    asm volatile("cp.async.cg.shared.global [%0], [%1], 16;" :: "r"(s), "l"(g) : "memory");
}
__device__ __forceinline__ void sts_zero16(uint32_t s) {
    asm volatile("st.shared.v4.b32 [%0], {%1,%1,%1,%1};" :: "r"(s), "r"(0u) : "memory");
}
#define CP_COMMIT() asm volatile("cp.async.commit_group;" ::: "memory")
#define CP_WAIT2()  asm volatile("cp.async.wait_group 2;" ::: "memory")

__device__ __forceinline__ void mma_fp16(float& d0, float& d1, float& d2, float& d3,
                                         uint32_t a0, uint32_t a1, uint32_t a2, uint32_t a3,
                                         uint32_t b0, uint32_t b1) {
    asm volatile(
        "mma.sync.aligned.m16n8k16.row.col.f32.f16.f16.f32 "
        "{%0,%1,%2,%3}, {%4,%5,%6,%7}, {%8,%9}, {%0,%1,%2,%3};"
        : "+f"(d0), "+f"(d1), "+f"(d2), "+f"(d3)
        : "r"(a0), "r"(a1), "r"(a2), "r"(a3), "r"(b0), "r"(b1));
}

// ================= f32 -> f16 conversion =================
__global__ void f2h_kernel(const float* __restrict__ in, __half* __restrict__ out, int n2) {
    int i = blockIdx.x * blockDim.x + threadIdx.x;
    if (i >= n2) return;
    float2 v = ((const float2*)in)[i];
    ((__half2*)out)[i] = __floats2half2_rn(v.x, v.y);
}

// ================= FP16 mma.sync GEMM (NT): C[m,n] = sum_k A[m,k]B[n,k] =================
// Block 128x128, 8 warps (2x4), warp tile 64x32, k-tile 32 halves, 4-stage pipeline.
// 2 CTAs/SM (validated R11).
#define KTILE    32
#define NSTAGE   4
#define TSTRIDE_H 40
#define A_HALVES (128 * TSTRIDE_H)
#define B_HALVES (128 * TSTRIDE_H)
#define STAGE_H  (A_HALVES + B_HALVES)
#define SMEM_GEMM (NSTAGE * STAGE_H * 2)         // 81920 bytes

__device__ __forceinline__ void load_tile_h(const __half* __restrict__ A,
                                            const __half* __restrict__ B,
                                            int K, int Nn, int bm, int bn,
                                            int ti, uint32_t sb, int tid)
{
    uint32_t st = sb + (uint32_t)(ti & (NSTAGE - 1)) * (STAGE_H * 2);
    const __half* ag = A + (size_t)bm * K + (size_t)ti * KTILE;
#pragma unroll
    for (int i = 0; i < 2; i++) {
        int flat = tid + (i << 8);
        int r = flat >> 2, c = flat & 3;
        cp_async16(st + r * (TSTRIDE_H * 2) + c * 16, ag + (size_t)r * K + c * 8);
    }
    uint32_t stb = st + A_HALVES * 2;
    const __half* bg = B + (size_t)ti * KTILE;
#pragma unroll
    for (int i = 0; i < 2; i++) {
        int flat = tid + (i << 8);
        int r = flat >> 2, c = flat & 3;
        uint32_t so = stb + r * (TSTRIDE_H * 2) + c * 16;
        int gn = bn + r;
        if (gn < Nn) cp_async16(so, bg + (size_t)gn * K + c * 8);
        else         sts_zero16(so);
    }
}

template<bool HALF_OUT>
__global__ void __launch_bounds__(256, 2)
gemm_h(const __half* __restrict__ A, const __half* __restrict__ B,
       void* __restrict__ Cv, int M, int Nn, int K)
{
    extern __shared__ __align__(16) uint32_t dsm32[];
    const int tid = threadIdx.x;
    const int wid = tid >> 5;
    const int lane = tid & 31;
    const int g = lane >> 2;
    const int q = lane & 3;
    const int wm = (wid & 1) * 64;
    const int wn = (wid >> 1) * 32;
    const int KT = K / KTILE;
    const int bm = blockIdx.y << 7;
    const int bn = blockIdx.x << 7;
    uint32_t sb = smem_u32(dsm32);

    float acc[4][4][4];
#pragma unroll
    for (int mi = 0; mi < 4; mi++)
#pragma unroll
        for (int ni = 0; ni < 4; ni++)
#pragma unroll
            for (int e = 0; e < 4; e++) acc[mi][ni][e] = 0.f;

#pragma unroll
    for (int t = 0; t < 3; t++) {
        load_tile_h(A, B, K, Nn, bm, bn, t, sb, tid);
        CP_COMMIT();
    }

    for (int kt = 0; kt < KT; kt++) {
        CP_WAIT2();
        __syncthreads();
        int ld = kt + 3;
        if (ld < KT) load_tile_h(A, B, K, Nn, bm, bn, ld, sb, tid);
        CP_COMMIT();

        const uint32_t* As = dsm32 + (kt & (NSTAGE - 1)) * (STAGE_H / 2);
        const uint32_t* Bs = As + A_HALVES / 2;
#pragma unroll
        for (int ks = 0; ks < 2; ks++) {
            int kq = ks * 8 + q;
            uint32_t a[4][4];
#pragma unroll
            for (int mi = 0; mi < 4; mi++) {
                int row = wm + mi * 16;
                a[mi][0] = As[(row + g)     * 20 + kq];
                a[mi][1] = As[(row + g + 8) * 20 + kq];
                a[mi][2] = As[(row + g)     * 20 + kq + 4];
                a[mi][3] = As[(row + g + 8) * 20 + kq + 4];
            }
            uint32_t b[4][2];
#pragma unroll
            for (int ni = 0; ni < 4; ni++) {
                int col = wn + ni * 8;
                b[ni][0] = Bs[(col + g) * 20 + kq];
                b[ni][1] = Bs[(col + g) * 20 + kq + 4];
            }
#pragma unroll
            for (int mi = 0; mi < 4; mi++)
#pragma unroll
                for (int ni = 0; ni < 4; ni++)
                    mma_fp16(acc[mi][ni][0], acc[mi][ni][1], acc[mi][ni][2], acc[mi][ni][3],
                             a[mi][0], a[mi][1], a[mi][2], a[mi][3],
                             b[ni][0], b[ni][1]);
        }
    }

#pragma unroll
    for (int mi = 0; mi < 4; mi++) {
#pragma unroll
        for (int ni = 0; ni < 4; ni++) {
            int col = bn + wn + ni * 8 + 2 * q;
            if (col < Nn) {
                int r0 = bm + wm + mi * 16 + g;
                if (HALF_OUT) {
                    __half* C = (__half*)Cv;
                    *(__half2*)(C + (size_t)r0 * Nn + col) =
                        __floats2half2_rn(acc[mi][ni][0], acc[mi][ni][1]);
                    *(__half2*)(C + (size_t)(r0 + 8) * Nn + col) =
                        __floats2half2_rn(acc[mi][ni][2], acc[mi][ni][3]);
                } else {
                    float* C = (float*)Cv;
                    *(float2*)(C + (size_t)r0 * Nn + col) =
                        make_float2(acc[mi][ni][0], acc[mi][ni][1]);
                    *(float2*)(C + (size_t)(r0 + 8) * Nn + col) =
                        make_float2(acc[mi][ni][2], acc[mi][ni][3]);
                }
            }
        }
    }
}

// ================= conv + silu (half2-vectorized: 2 channels/thread) =================
__global__ void __launch_bounds__(256) conv_silu_kernel(const float* __restrict__ cw,
                                                        const float* __restrict__ cb)
{
    int ch = (blockIdx.x * 256 + threadIdx.x) * 2;   // even channel index
    int tb = blockIdx.y * 16;
    int b = tb >> 12;
    int l0 = tb & (SEQLEN - 1);
    // per-channel taps (2 channels)
    float c00 = cw[ch * 4 + 0], c01 = cw[ch * 4 + 1], c02 = cw[ch * 4 + 2], c03 = cw[ch * 4 + 3];
    float c10 = cw[ch * 4 + 4], c11 = cw[ch * 4 + 5], c12 = cw[ch * 4 + 6], c13 = cw[ch * 4 + 7];
    float b0 = cb[ch], b1 = cb[ch + 1];
    const __half2* base = (const __half2*)(g_proj16 + (size_t)(b * SEQLEN) * DPROJ + ch);
    __half2* outb = (__half2*)(g_xbc16 + (size_t)(b * SEQLEN) * DXBC + ch);
    const int strideIn = DPROJ / 2;   // half2 stride per row
    const int strideOut = DXBC / 2;

    float2 w0 = make_float2(0.f, 0.f), w1 = w0, w2 = w0;
    if (l0 >= 3) w0 = __half22float2(base[(size_t)(l0 - 3) * strideIn]);
    if (l0 >= 2) w1 = __half22float2(base[(size_t)(l0 - 2) * strideIn]);
    if (l0 >= 1) w2 = __half22float2(base[(size_t)(l0 - 1) * strideIn]);
#pragma unroll
    for (int tt = 0; tt < 16; tt++) {
        float2 xv = __half22float2(base[(size_t)(l0 + tt) * strideIn]);
        float a0 = fmaf(c03, xv.x, fmaf(c02, w2.x, fmaf(c01, w1.x, fmaf(c00, w0.x, b0))));
        float a1 = fmaf(c13, xv.y, fmaf(c12, w2.y, fmaf(c11, w1.y, fmaf(c10, w0.y, b1))));
        float s0 = a0 / (1.f + expf(-a0));
        float s1 = a1 / (1.f + expf(-a1));
        outb[(size_t)(l0 + tt) * strideOut] = __floats2half2_rn(s0, s1);
        w0 = w1; w1 = w2; w2 = xv;
    }
}

// ================= dA cumsum =================
__global__ void __launch_bounds__(256) dacum_kernel()
{
    int gw = (blockIdx.x * blockDim.x + threadIdx.x) >> 5;
    int lane = threadIdx.x & 31;
    if (gw >= BATCH * NHEADS * NCHUNK) return;
    int c = gw & 31, h = (gw >> 5) & 31, b = gw >> 10;
    int t0 = b * SEQLEN + c * CHUNKSZ + lane * 4;
    float p[4], run = 0.f;
#pragma unroll
    for (int j = 0; j < 4; j++) {
        float v = __half2float(g_proj16[(size_t)(t0 + j) * DPROJ + (DXBC + DINNER) + h]);
        run += fmaxf(v, 0.f) + log1pf(expf(-fabsf(v)));
        p[j] = run;
    }
    float tot = run;
#pragma unroll
    for (int off = 1; off < 32; off <<= 1) {
        float nb = __shfl_up_sync(0xFFFFFFFFu, tot, off);
        if (lane >= off) tot += nb;
    }
    float excl = tot - run;
    int ob = ((b * 32 + h) * 32 + c) * CHUNKSZ + lane * 4;
#pragma unroll
    for (int j = 0; j < 4; j++) g_dacum[ob + j] = -(excl + p[j]);
}

// ================= chunk states: 4x4 register tiling, fp16 io =================
#define SMEM_STATES ((2 * 128 * 65 + 128) * 4)
__global__ void __launch_bounds__(256, 2) states_kernel()
{
    extern __shared__ float sm[];
    float* Bs = sm;
    float* xs = sm + 128 * 65;
    float* da = xs + 128 * 65;

    int bi = blockIdx.x;
    int h = bi & 31, c = (bi >> 5) & 31, b = bi >> 10;
    int tid = threadIdx.x;
    int base_t = b * SEQLEN + c * CHUNKSZ;
    int dab = ((b * 32 + h) * 32 + c) * CHUNKSZ;

    if (tid < 128) da[tid] = g_dacum[dab + tid];
    __syncthreads();
    float da_last = da[127];

#pragma unroll
    for (int i = 0; i < 32; i++) {
        int flat = tid + 256 * i;
        int s = flat >> 6, p = flat & 63;
        size_t goff = (size_t)(base_t + s) * DXBC + h * 64 + p;
        float dec = __expf(da_last - da[s]);
        xs[s * 65 + p] = __half2float(g_xbc16[goff]) * dec;
        Bs[s * 65 + p] = __half2float(g_xbc16[goff + DINNER]);
    }
    __syncthreads();

    int nt = tid & 15, pt = tid >> 4;
    float acc[4][4];
#pragma unroll
    for (int i = 0; i < 4; i++)
#pragma unroll
        for (int j = 0; j < 4; j++) acc[i][j] = 0.f;

    for (int s = 0; s < CHUNKSZ; s++) {
        float bv[4], xv[4];
#pragma unroll
        for (int j = 0; j < 4; j++) bv[j] = Bs[s * 65 + nt + 16 * j];
#pragma unroll
        for (int i = 0; i < 4; i++) xv[i] = xs[s * 65 + pt + 16 * i];
#pragma unroll
        for (int i = 0; i < 4; i++)
#pragma unroll
            for (int j = 0; j < 4; j++)
                acc[i][j] = fmaf(bv[j], xv[i], acc[i][j]);
    }
    size_t sbo = (size_t)((b * 32 + c) * 32 + h) * (HDIM * DSTATE);
#pragma unroll
    for (int i = 0; i < 4; i++)
#pragma unroll
        for (int j = 0; j < 4; j++)
            g_states16[sbo + (pt + 16 * i) * 64 + nt + 16 * j] = __float2half_rn(acc[i][j]);
}

// ================= inter-chunk scan =================
__global__ void __launch_bounds__(256) scan_kernel()
{
    int bi = blockIdx.x;
    int q = bi & 15;
    int bh = bi >> 4;
    int b = bh >> 5, h = bh & 31;
    int e = q * 256 + threadIdx.x;
    float carry = 0.f;
    for (int c = 0; c < NCHUNK; c++) {
        size_t sbo = (size_t)((b * 32 + c) * 32 + h) * (HDIM * DSTATE);
        float dec = expf(g_dacum[((b * 32 + h) * 32 + c) * CHUNKSZ + 127]);
        g_prev16[sbo + e] = __float2half_rn(carry);
        carry = fmaf(carry, dec, __half2float(g_states16[sbo + e]));
    }
}

// ================= fused Y kernel — tensor-core, 2 CTAs/SM =================
#define YH_CS 0
#define YH_BS 9216
#define YH_XT 18432
#define YH_G  27136
#define YH_PT 44544
#define YH_HALVES 49152
#define SMEM_Y (YH_HALVES * 2 + 512)

__global__ void __launch_bounds__(256, 2) y_kernel(const float* __restrict__ zb,
                                                   const float* __restrict__ Dp)
{
    extern __shared__ __align__(16) __half ysm[];
    float* da = (float*)(ysm + YH_HALVES);
    uint32_t* smu = (uint32_t*)ysm;

    int bi = blockIdx.x;
    int h = bi & 31, c = (bi >> 5) & 31, b = bi >> 10;
    int tid = threadIdx.x;
    int wid = tid >> 5, lane = tid & 31;
    int g = lane >> 2, q = lane & 3;
    int base_t = b * SEQLEN + c * CHUNKSZ;
    int dab = ((b * 32 + h) * 32 + c) * CHUNKSZ;
    size_t pb = (size_t)((b * 32 + c) * 32 + h) * (HDIM * DSTATE);

    if (tid < 128) da[tid] = g_dacum[dab + tid];
#pragma unroll
    for (int i = 0; i < 32; i++) {
        int flat = tid + 256 * i;
        int s = flat >> 6, p = flat & 63;
        size_t goff = (size_t)(base_t + s) * DXBC + h * 64 + p;
        __half xv = g_xbc16[goff];
        ysm[YH_BS + s * 72 + p] = g_xbc16[goff + DINNER];
        ysm[YH_CS + s * 72 + p] = g_xbc16[goff + 2 * DINNER];
        ysm[YH_XT + p * 136 + s] = xv;
    }
#pragma unroll
    for (int i = 0; i < 16; i++) {
        int flat = tid + 256 * i;
        int p = flat >> 6, n = flat & 63;
        ysm[YH_PT + p * 72 + n] = g_prev16[pb + flat];
    }
    __syncthreads();

    const uint32_t* Cu = smu;
    const uint32_t* Bu = smu + 4608;
    const uint32_t* Xu = smu + 9216;
    const uint32_t* Gu = smu + 13568;
    const uint32_t* Pu = smu + 22272;

    // ---- phase 1: G = (C B^T) .* mask.decay ----
    {
        int l0 = (wid & 3) * 32, s0 = (wid >> 2) * 64;
        float accg[2][8][4];
#pragma unroll
        for (int mi = 0; mi < 2; mi++)
#pragma unroll
            for (int ni = 0; ni < 8; ni++)
#pragma unroll
                for (int e = 0; e < 4; e++) accg[mi][ni][e] = 0.f;

#pragma unroll
        for (int ks = 0; ks < 4; ks++) {
            int kq = ks * 8 + q;
            uint32_t a[2][4];
#pragma unroll
            for (int mi = 0; mi < 2; mi++) {
                int row = l0 + mi * 16;
                a[mi][0] = Cu[(row + g)     * 36 + kq];
                a[mi][1] = Cu[(row + g + 8) * 36 + kq];
                a[mi][2] = Cu[(row + g)     * 36 + kq + 4];
                a[mi][3] = Cu[(row + g + 8) * 36 + kq + 4];
            }
            uint32_t bf[8][2];
#pragma unroll
            for (int ni = 0; ni < 8; ni++) {
                int col = s0 + ni * 8;
                bf[ni][0] = Bu[(col + g) * 36 + kq];
                bf[ni][1] = Bu[(col + g) * 36 + kq + 4];
            }
#pragma unroll
            for (int mi = 0; mi < 2; mi++)
#pragma unroll
                for (int ni = 0; ni < 8; ni++)
                    mma_fp16(accg[mi][ni][0], accg[mi][ni][1], accg[mi][ni][2], accg[mi][ni][3],
                             a[mi][0], a[mi][1], a[mi][2], a[mi][3],
                             bf[ni][0], bf[ni][1]);
        }
#pragma unroll
        for (int mi = 0; mi < 2; mi++) {
            int lA = l0 + mi * 16 + g;
            int lB = lA + 8;
            float daA = da[lA], daB = da[lB];
#pragma unroll
            for (int ni = 0; ni < 8; ni++) {
                int s = s0 + ni * 8 + 2 * q;
                float das0 = da[s], das1 = da[s + 1];
                float gA0 = (s     <= lA) ? accg[mi][ni][0] * __expf(daA - das0) : 0.f;
                float gA1 = (s + 1 <= lA) ? accg[mi][ni][1] * __expf(daA - das1) : 0.f;
                float gB0 = (s     <= lB) ? accg[mi][ni][2] * __expf(daB - das0) : 0.f;
                float gB1 = (s + 1 <= lB) ? accg[mi][ni][3] * __expf(daB - das1) : 0.f;
                *(__half2*)(ysm + YH_G + lA * 136 + s) = __floats2half2_rn(gA0, gA1);
                *(__half2*)(ysm + YH_G + lB * 136 + s) = __floats2half2_rn(gB0, gB1);
            }
        }
    }
    __syncthreads();

    // ---- phase 2: Y = G @ x + exp(da)*(C @ prev^T) + D*x; gate; fp16 out ----
    {
        int wl = (wid & 3) * 32, wp = (wid >> 2) * 32;
        float acc1[2][4][4], acc2[2][4][4];
#pragma unroll
        for (int mi = 0; mi < 2; mi++)
#pragma unroll
            for (int ni = 0; ni < 4; ni++)
#pragma unroll
                for (int e = 0; e < 4; e++) { acc1[mi][ni][e] = 0.f; acc2[mi][ni][e] = 0.f; }

#pragma unroll
        for (int ks = 0; ks < 8; ks++) {
            int kq = ks * 8 + q;
            uint32_t a[2][4];
#pragma unroll
            for (int mi = 0; mi < 2; mi++) {
                int row = wl + mi * 16;
                a[mi][0] = Gu[(row + g)     * 68 + kq];
                a[mi][1] = Gu[(row + g + 8) * 68 + kq];
                a[mi][2] = Gu[(row + g)     * 68 + kq + 4];
                a[mi][3] = Gu[(row + g + 8) * 68 + kq + 4];
            }
            uint32_t bf[4][2];
#pragma unroll
            for (int ni = 0; ni < 4; ni++) {
                int col = wp + ni * 8;
                bf[ni][0] = Xu[(col + g) * 68 + kq];
                bf[ni][1] = Xu[(col + g) * 68 + kq + 4];
            }
#pragma unroll
            for (int mi = 0; mi < 2; mi++)
#pragma unroll
                for (int ni = 0; ni < 4; ni++)
                    mma_fp16(acc1[mi][ni][0], acc1[mi][ni][1], acc1[mi][ni][2], acc1[mi][ni][3],
                             a[mi][0], a[mi][1], a[mi][2], a[mi][3],
                             bf[ni][0], bf[ni][1]);
        }
#pragma unroll
        for (int ks = 0; ks < 4; ks++) {
            int kq = ks * 8 + q;
            uint32_t a[2][4];
#pragma unroll
            for (int mi = 0; mi < 2; mi++) {
                int row = wl + mi * 16;
                a[mi][0] = Cu[(row + g)     * 36 + kq];
                a[mi][1] = Cu[(row + g + 8) * 36 + kq];
                a[mi][2] = Cu[(row + g)     * 36 + kq + 4];
                a[mi][3] = Cu[(row + g + 8) * 36 + kq + 4];
            }
            uint32_t bf[4][2];
#pragma unroll
            for (int ni = 0; ni < 4; ni++) {
                int col = wp + ni * 8;
                bf[ni][0] = Pu[(col + g) * 36 + kq];
                bf[ni][1] = Pu[(col + g) * 36 + kq + 4];
            }
#pragma unroll
            for (int mi = 0; mi < 2; mi++)
#pragma unroll
                for (int ni = 0; ni < 4; ni++)
                    mma_fp16(acc2[mi][ni][0], acc2[mi][ni][1], acc2[mi][ni][2], acc2[mi][ni][3],
                             a[mi][0], a[mi][1], a[mi][2], a[mi][3],
                             bf[ni][0], bf[ni][1]);
        }

        float Dh = Dp[h];
#pragma unroll
        for (int mi = 0; mi < 2; mi++) {
            int lA = wl + mi * 16 + g;
            int lB = lA + 8;
            float edaA = __expf(da[lA]);
            float edaB = __expf(da[lB]);
            int tA = base_t + lA, tB = base_t + lB;
#pragma unroll
            for (int ni = 0; ni < 4; ni++) {
                int p = wp + ni * 8 + 2 * q;
                int chn = h * 64 + p;
                float zb0 = zb[chn], zb1 = zb[chn + 1];
                float xA0 = __half2float(ysm[YH_XT + p * 136 + lA]);
                float xA1 = __half2float(ysm[YH_XT + (p + 1) * 136 + lA]);
                float xB0 = __half2float(ysm[YH_XT + p * 136 + lB]);
                float xB1 = __half2float(ysm[YH_XT + (p + 1) * 136 + lB]);
                __half2 zA = *(const __half2*)(g_proj16 + (size_t)tA * DPROJ + DXBC + chn);
                __half2 zB = *(const __half2*)(g_proj16 + (size_t)tB * DPROJ + DXBC + chn);

                float yA0 = acc1[mi][ni][0] + edaA * acc2[mi][ni][0] + Dh * xA0;
                float yA1 = acc1[mi][ni][1] + edaA * acc2[mi][ni][1] + Dh * xA1;
                float yB0 = acc1[mi][ni][2] + edaB * acc2[mi][ni][2] + Dh * xB0;
                float yB1 = acc1[mi][ni][3] + edaB * acc2[mi][ni][3] + Dh * xB1;

                float zA0 = __half2float(zA.x) + zb0, zA1 = __half2float(zA.y) + zb1;
                float zB0 = __half2float(zB.x) + zb0, zB1 = __half2float(zB.y) + zb1;
                yA0 *= zA0 / (1.f + expf(-zA0));
                yA1 *= zA1 / (1.f + expf(-zA1));
                yB0 *= zB0 / (1.f + expf(-zB0));
                yB1 *= zB1 / (1.f + expf(-zB1));

                *(__half2*)(g_yz16 + (size_t)tA * DINNER + chn) = __floats2half2_rn(yA0, yA1);
                *(__half2*)(g_yz16 + (size_t)tB * DINNER + chn) = __floats2half2_rn(yB0, yB1);
            }
        }
    }
}

// ================= launch =================
extern "C" void kernel_launch(void* const* d_in, const int* in_sizes, int n_in,
                              void* d_out, int out_size)
{
    const float* u          = (const float*)d_in[0];
    const float* in_proj_w  = (const float*)d_in[1];
    const float* z_bias     = (const float*)d_in[2];
    const float* conv_w     = (const float*)d_in[3];
    const float* conv_b     = (const float*)d_in[4];
    const float* Dparam     = (const float*)d_in[5];
    const float* out_proj_w = (const float*)d_in[6];
    float* out = (float*)d_out;

    void *p_proj = nullptr, *p_yz = nullptr, *p_ua = nullptr, *p_wa = nullptr, *p_wo = nullptr;
    cudaGetSymbolAddress(&p_proj, g_proj16);
    cudaGetSymbolAddress(&p_yz, g_yz16);
    cudaGetSymbolAddress(&p_ua, g_ua16);
    cudaGetSymbolAddress(&p_wa, g_wa16);
    cudaGetSymbolAddress(&p_wo, g_wo16);

    cudaFuncSetAttribute((const void*)gemm_h<true>,
                         cudaFuncAttributeMaxDynamicSharedMemorySize, SMEM_GEMM);
    cudaFuncSetAttribute((const void*)gemm_h<false>,
                         cudaFuncAttributeMaxDynamicSharedMemorySize, SMEM_GEMM);
    cudaFuncSetAttribute(states_kernel, cudaFuncAttributeMaxDynamicSharedMemorySize, SMEM_STATES);
    cudaFuncSetAttribute(y_kernel, cudaFuncAttributeMaxDynamicSharedMemorySize, SMEM_Y);

    // 0) f32 -> f16 operand conversion
    f2h_kernel<<<(NTOK * DMODEL / 2 + 255) / 256, 256>>>(u, (__half*)p_ua, NTOK * DMODEL / 2);
    f2h_kernel<<<(DPROJ * DMODEL / 2 + 255) / 256, 256>>>(in_proj_w, (__half*)p_wa, DPROJ * DMODEL / 2);
    f2h_kernel<<<(DMODEL * DINNER / 2 + 255) / 256, 256>>>(out_proj_w, (__half*)p_wo, DMODEL * DINNER / 2);

    // 1) in_proj GEMM: 128x128 tile, 2 CTAs/SM, fp16 out
    {
        dim3 grid((DPROJ + 127) / 128, NTOK / 128);
        gemm_h<true><<<grid, 256, SMEM_GEMM>>>(
            (const __half*)p_ua, (const __half*)p_wa, p_proj, NTOK, DPROJ, DMODEL);
    }
    // 2) conv + silu (half2 vectorized)
    {
        dim3 grid(DXBC / 512, NTOK / 16);
        conv_silu_kernel<<<grid, 256>>>(conv_w, conv_b);
    }
    // 3) dA cumsum
    dacum_kernel<<<(BATCH * NHEADS * NCHUNK * 32 + 255) / 256, 256>>>();
    // 4) chunk states
    states_kernel<<<BATCH * NCHUNK * NHEADS, 256, SMEM_STATES>>>();
    // 5) inter-chunk scan
    scan_kernel<<<BATCH * NHEADS * 16, 256>>>();
    // 6) fused Y + gating (tensor-core, 2 CTAs/SM)
    y_kernel<<<BATCH * NCHUNK * NHEADS, 256, SMEM_Y>>>(z_bias, Dparam);
    // 7) out_proj GEMM: 128x128 tile, 2 CTAs/SM, fp32 out
    {
        dim3 grid(DMODEL / 128, NTOK / 128);
        gemm_h<false><<<grid, 256, SMEM_GEMM>>>(
            (const __half*)p_yz, (const __half*)p_wo, out, NTOK, DMODEL, DINNER);
    }
}

// round 13
// speedup vs baseline: 1.8937x; 1.0404x over previous
#include <cuda_runtime.h>
#include <cuda_fp16.h>
#include <cstdint>
#include <math.h>

// ---------------- problem constants ----------------
#define BATCH    2
#define SEQLEN   4096
#define NTOK     8192
#define DMODEL   1024
#define DINNER   2048
#define DSTATE   64
#define NHEADS   32
#define HDIM     64
#define CONVK    4
#define CHUNKSZ  128
#define NCHUNK   32
#define DXBC     6144
#define DPROJ    8224

// ---------------- device scratch (allocation-free) ----------------
__device__ __half g_proj16[(size_t)NTOK * DPROJ];
__device__ __half g_xbc16[(size_t)NTOK * DXBC];
__device__ float  g_dacum[BATCH * NHEADS * NCHUNK * CHUNKSZ];
__device__ __half g_states16[(size_t)BATCH * NCHUNK * NHEADS * HDIM * DSTATE];
__device__ __half g_prev16[(size_t)BATCH * NCHUNK * NHEADS * HDIM * DSTATE];
__device__ __half g_yz16[(size_t)NTOK * DINNER];
__device__ __half g_ua16[(size_t)NTOK * DMODEL];
__device__ __half g_wa16[(size_t)DPROJ * DMODEL];
__device__ __half g_wo16[(size_t)DMODEL * DINNER];

// ================= helpers =================
__device__ __forceinline__ uint32_t smem_u32(const void* p) {
    uint32_t a;
    asm("{ .reg .u64 t; cvta.to.shared.u64 t, %1; cvt.u32.u64 %0, t; }" : "=r"(a) : "l"(p));
    return a;
}
__device__ __forceinline__ void cp_async16(uint32_t s, const void* g) {
    asm volatile("cp.async.cg.shared.global [%0], [%1], 16;" :: "r"(s), "l"(g) : "memory");
}
__device__ __forceinline__ void sts_zero16(uint32_t s) {
    asm volatile("st.shared.v4.b32 [%0], {%1,%1,%1,%1};" :: "r"(s), "r"(0u) : "memory");
}
#define CP_COMMIT() asm volatile("cp.async.commit_group;" ::: "memory")
#define CP_WAIT2()  asm volatile("cp.async.wait_group 2;" ::: "memory")

__device__ __forceinline__ void mma_fp16(float& d0, float& d1, float& d2, float& d3,
                                         uint32_t a0, uint32_t a1, uint32_t a2, uint32_t a3,
                                         uint32_t b0, uint32_t b1) {
    asm volatile(
        "mma.sync.aligned.m16n8k16.row.col.f32.f16.f16.f32 "
        "{%0,%1,%2,%3}, {%4,%5,%6,%7}, {%8,%9}, {%0,%1,%2,%3};"
        : "+f"(d0), "+f"(d1), "+f"(d2), "+f"(d3)
        : "r"(a0), "r"(a1), "r"(a2), "r"(a3), "r"(b0), "r"(b1));
}

// ================= f32 -> f16 conversion =================
__global__ void f2h_kernel(const float* __restrict__ in, __half* __restrict__ out, int n2) {
    int i = blockIdx.x * blockDim.x + threadIdx.x;
    if (i >= n2) return;
    float2 v = ((const float2*)in)[i];
    ((__half2*)out)[i] = __floats2half2_rn(v.x, v.y);
}

// ================= FP16 mma.sync GEMM (NT): C[m,n] = sum_k A[m,k]B[n,k] =================
// Block 128x128, 8 warps (2x4), warp tile 64x32, k-tile 32 halves, 4-stage, 2 CTAs/SM.
#define KTILE    32
#define NSTAGE   4
#define TSTRIDE_H 40
#define A_HALVES (128 * TSTRIDE_H)
#define B_HALVES (128 * TSTRIDE_H)
#define STAGE_H  (A_HALVES + B_HALVES)
#define SMEM_GEMM (NSTAGE * STAGE_H * 2)         // 81920 bytes

__device__ __forceinline__ void load_tile_h(const __half* __restrict__ A,
                                            const __half* __restrict__ B,
                                            int K, int Nn, int bm, int bn,
                                            int ti, uint32_t sb, int tid)
{
    uint32_t st = sb + (uint32_t)(ti & (NSTAGE - 1)) * (STAGE_H * 2);
    const __half* ag = A + (size_t)bm * K + (size_t)ti * KTILE;
#pragma unroll
    for (int i = 0; i < 2; i++) {
        int flat = tid + (i << 8);
        int r = flat >> 2, c = flat & 3;
        cp_async16(st + r * (TSTRIDE_H * 2) + c * 16, ag + (size_t)r * K + c * 8);
    }
    uint32_t stb = st + A_HALVES * 2;
    const __half* bg = B + (size_t)ti * KTILE;
#pragma unroll
    for (int i = 0; i < 2; i++) {
        int flat = tid + (i << 8);
        int r = flat >> 2, c = flat & 3;
        uint32_t so = stb + r * (TSTRIDE_H * 2) + c * 16;
        int gn = bn + r;
        if (gn < Nn) cp_async16(so, bg + (size_t)gn * K + c * 8);
        else         sts_zero16(so);
    }
}

template<bool HALF_OUT>
__global__ void __launch_bounds__(256, 2)
gemm_h(const __half* __restrict__ A, const __half* __restrict__ B,
       void* __restrict__ Cv, int M, int Nn, int K)
{
    extern __shared__ __align__(16) uint32_t dsm32[];
    const int tid = threadIdx.x;
    const int wid = tid >> 5;
    const int lane = tid & 31;
    const int g = lane >> 2;
    const int q = lane & 3;
    const int wm = (wid & 1) * 64;
    const int wn = (wid >> 1) * 32;
    const int KT = K / KTILE;
    const int bm = blockIdx.y << 7;
    const int bn = blockIdx.x << 7;
    uint32_t sb = smem_u32(dsm32);

    float acc[4][4][4];
#pragma unroll
    for (int mi = 0; mi < 4; mi++)
#pragma unroll
        for (int ni = 0; ni < 4; ni++)
#pragma unroll
            for (int e = 0; e < 4; e++) acc[mi][ni][e] = 0.f;

#pragma unroll
    for (int t = 0; t < 3; t++) {
        load_tile_h(A, B, K, Nn, bm, bn, t, sb, tid);
        CP_COMMIT();
    }

    for (int kt = 0; kt < KT; kt++) {
        CP_WAIT2();
        __syncthreads();
        int ld = kt + 3;
        if (ld < KT) load_tile_h(A, B, K, Nn, bm, bn, ld, sb, tid);
        CP_COMMIT();

        const uint32_t* As = dsm32 + (kt & (NSTAGE - 1)) * (STAGE_H / 2);
        const uint32_t* Bs = As + A_HALVES / 2;
#pragma unroll
        for (int ks = 0; ks < 2; ks++) {
            int kq = ks * 8 + q;
            uint32_t a[4][4];
#pragma unroll
            for (int mi = 0; mi < 4; mi++) {
                int row = wm + mi * 16;
                a[mi][0] = As[(row + g)     * 20 + kq];
                a[mi][1] = As[(row + g + 8) * 20 + kq];
                a[mi][2] = As[(row + g)     * 20 + kq + 4];
                a[mi][3] = As[(row + g + 8) * 20 + kq + 4];
            }
            uint32_t b[4][2];
#pragma unroll
            for (int ni = 0; ni < 4; ni++) {
                int col = wn + ni * 8;
                b[ni][0] = Bs[(col + g) * 20 + kq];
                b[ni][1] = Bs[(col + g) * 20 + kq + 4];
            }
#pragma unroll
            for (int mi = 0; mi < 4; mi++)
#pragma unroll
                for (int ni = 0; ni < 4; ni++)
                    mma_fp16(acc[mi][ni][0], acc[mi][ni][1], acc[mi][ni][2], acc[mi][ni][3],
                             a[mi][0], a[mi][1], a[mi][2], a[mi][3],
                             b[ni][0], b[ni][1]);
        }
    }

#pragma unroll
    for (int mi = 0; mi < 4; mi++) {
#pragma unroll
        for (int ni = 0; ni < 4; ni++) {
            int col = bn + wn + ni * 8 + 2 * q;
            if (col < Nn) {
                int r0 = bm + wm + mi * 16 + g;
                if (HALF_OUT) {
                    __half* C = (__half*)Cv;
                    *(__half2*)(C + (size_t)r0 * Nn + col) =
                        __floats2half2_rn(acc[mi][ni][0], acc[mi][ni][1]);
                    *(__half2*)(C + (size_t)(r0 + 8) * Nn + col) =
                        __floats2half2_rn(acc[mi][ni][2], acc[mi][ni][3]);
                } else {
                    float* C = (float*)Cv;
                    *(float2*)(C + (size_t)r0 * Nn + col) =
                        make_float2(acc[mi][ni][0], acc[mi][ni][1]);
                    *(float2*)(C + (size_t)(r0 + 8) * Nn + col) =
                        make_float2(acc[mi][ni][2], acc[mi][ni][3]);
                }
            }
        }
    }
}

// ================= conv + silu (half2-vectorized) =================
__global__ void __launch_bounds__(256) conv_silu_kernel(const float* __restrict__ cw,
                                                        const float* __restrict__ cb)
{
    int ch = (blockIdx.x * 256 + threadIdx.x) * 2;
    int tb = blockIdx.y * 16;
    int b = tb >> 12;
    int l0 = tb & (SEQLEN - 1);
    float c00 = cw[ch * 4 + 0], c01 = cw[ch * 4 + 1], c02 = cw[ch * 4 + 2], c03 = cw[ch * 4 + 3];
    float c10 = cw[ch * 4 + 4], c11 = cw[ch * 4 + 5], c12 = cw[ch * 4 + 6], c13 = cw[ch * 4 + 7];
    float b0 = cb[ch], b1 = cb[ch + 1];
    const __half2* base = (const __half2*)(g_proj16 + (size_t)(b * SEQLEN) * DPROJ + ch);
    __half2* outb = (__half2*)(g_xbc16 + (size_t)(b * SEQLEN) * DXBC + ch);
    const int strideIn = DPROJ / 2;
    const int strideOut = DXBC / 2;

    float2 w0 = make_float2(0.f, 0.f), w1 = w0, w2 = w0;
    if (l0 >= 3) w0 = __half22float2(base[(size_t)(l0 - 3) * strideIn]);
    if (l0 >= 2) w1 = __half22float2(base[(size_t)(l0 - 2) * strideIn]);
    if (l0 >= 1) w2 = __half22float2(base[(size_t)(l0 - 1) * strideIn]);
#pragma unroll
    for (int tt = 0; tt < 16; tt++) {
        float2 xv = __half22float2(base[(size_t)(l0 + tt) * strideIn]);
        float a0 = fmaf(c03, xv.x, fmaf(c02, w2.x, fmaf(c01, w1.x, fmaf(c00, w0.x, b0))));
        float a1 = fmaf(c13, xv.y, fmaf(c12, w2.y, fmaf(c11, w1.y, fmaf(c10, w0.y, b1))));
        float s0 = a0 / (1.f + expf(-a0));
        float s1 = a1 / (1.f + expf(-a1));
        outb[(size_t)(l0 + tt) * strideOut] = __floats2half2_rn(s0, s1);
        w0 = w1; w1 = w2; w2 = xv;
    }
}

// ================= dA cumsum =================
__global__ void __launch_bounds__(256) dacum_kernel()
{
    int gw = (blockIdx.x * blockDim.x + threadIdx.x) >> 5;
    int lane = threadIdx.x & 31;
    if (gw >= BATCH * NHEADS * NCHUNK) return;
    int c = gw & 31, h = (gw >> 5) & 31, b = gw >> 10;
    int t0 = b * SEQLEN + c * CHUNKSZ + lane * 4;
    float p[4], run = 0.f;
#pragma unroll
    for (int j = 0; j < 4; j++) {
        float v = __half2float(g_proj16[(size_t)(t0 + j) * DPROJ + (DXBC + DINNER) + h]);
        run += fmaxf(v, 0.f) + log1pf(expf(-fabsf(v)));
        p[j] = run;
    }
    float tot = run;
#pragma unroll
    for (int off = 1; off < 32; off <<= 1) {
        float nb = __shfl_up_sync(0xFFFFFFFFu, tot, off);
        if (lane >= off) tot += nb;
    }
    float excl = tot - run;
    int ob = ((b * 32 + h) * 32 + c) * CHUNKSZ + lane * 4;
#pragma unroll
    for (int j = 0; j < 4; j++) g_dacum[ob + j] = -(excl + p[j]);
}

// ================= chunk states — tensor-core version =================
// states[p,n] = sum_s (x[s,p]*dec[s]) * B[s,n] : 64x64x128 NT mma.
// smem: xdT[64][136] | BT[64][136] halves, then da[128] f32.
#define ST_XT 0
#define ST_BT 8704
#define ST_HALVES 17408
#define SMEM_STATES (ST_HALVES * 2 + 512)
__global__ void __launch_bounds__(256, 3) states_kernel()
{
    extern __shared__ __align__(16) __half ssm[];
    float* da = (float*)(ssm + ST_HALVES);
    const uint32_t* Xu = (const uint32_t*)ssm;          // stride 68
    const uint32_t* Bu = (const uint32_t*)ssm + 4352;   // stride 68

    int bi = blockIdx.x;
    int h = bi & 31, c = (bi >> 5) & 31, b = bi >> 10;
    int tid = threadIdx.x;
    int wid = tid >> 5, lane = tid & 31;
    int g = lane >> 2, q = lane & 3;
    int base_t = b * SEQLEN + c * CHUNKSZ;
    int dab = ((b * 32 + h) * 32 + c) * CHUNKSZ;

    if (tid < 128) da[tid] = g_dacum[dab + tid];
    __syncthreads();
    float da_last = da[127];

#pragma unroll
    for (int i = 0; i < 16; i++) {
        int flat = tid + 256 * i;
        int s = flat >> 5, p2 = flat & 31;          // p2: half2 index over p
        size_t goff = (size_t)(base_t + s) * DXBC + h * 64 + p2 * 2;
        float dec = __expf(da_last - da[s]);
        __half2 xv2 = *(const __half2*)(g_xbc16 + goff);
        __half2 bv2 = *(const __half2*)(g_xbc16 + goff + DINNER);
        ssm[ST_XT + (p2 * 2)     * 136 + s] = __float2half_rn(__half2float(xv2.x) * dec);
        ssm[ST_XT + (p2 * 2 + 1) * 136 + s] = __float2half_rn(__half2float(xv2.y) * dec);
        ssm[ST_BT + (p2 * 2)     * 136 + s] = bv2.x;
        ssm[ST_BT + (p2 * 2 + 1) * 136 + s] = bv2.y;
    }
    __syncthreads();

    // 8 warps, warp tile 32(p) x 16(n), K=128 (8 k-steps)
    int wm = (wid & 1) * 32, wn = (wid >> 1) * 16;
    float acc[2][2][4];
#pragma unroll
    for (int mi = 0; mi < 2; mi++)
#pragma unroll
        for (int ni = 0; ni < 2; ni++)
#pragma unroll
            for (int e = 0; e < 4; e++) acc[mi][ni][e] = 0.f;

#pragma unroll
    for (int ks = 0; ks < 8; ks++) {
        int kq = ks * 8 + q;
        uint32_t a[2][4];
#pragma unroll
        for (int mi = 0; mi < 2; mi++) {
            int row = wm + mi * 16;
            a[mi][0] = Xu[(row + g)     * 68 + kq];
            a[mi][1] = Xu[(row + g + 8) * 68 + kq];
            a[mi][2] = Xu[(row + g)     * 68 + kq + 4];
            a[mi][3] = Xu[(row + g + 8) * 68 + kq + 4];
        }
        uint32_t bf[2][2];
#pragma unroll
        for (int ni = 0; ni < 2; ni++) {
            int col = wn + ni * 8;
            bf[ni][0] = Bu[(col + g) * 68 + kq];
            bf[ni][1] = Bu[(col + g) * 68 + kq + 4];
        }
#pragma unroll
        for (int mi = 0; mi < 2; mi++)
#pragma unroll
            for (int ni = 0; ni < 2; ni++)
                mma_fp16(acc[mi][ni][0], acc[mi][ni][1], acc[mi][ni][2], acc[mi][ni][3],
                         a[mi][0], a[mi][1], a[mi][2], a[mi][3],
                         bf[ni][0], bf[ni][1]);
    }

    size_t sbo = (size_t)((b * 32 + c) * 32 + h) * (HDIM * DSTATE);
#pragma unroll
    for (int mi = 0; mi < 2; mi++) {
#pragma unroll
        for (int ni = 0; ni < 2; ni++) {
            int p0 = wm + mi * 16 + g;
            int n0 = wn + ni * 8 + 2 * q;
            *(__half2*)(g_states16 + sbo + p0 * 64 + n0) =
                __floats2half2_rn(acc[mi][ni][0], acc[mi][ni][1]);
            *(__half2*)(g_states16 + sbo + (p0 + 8) * 64 + n0) =
                __floats2half2_rn(acc[mi][ni][2], acc[mi][ni][3]);
        }
    }
}

// ================= inter-chunk scan =================
__global__ void __launch_bounds__(256) scan_kernel()
{
    int bi = blockIdx.x;
    int q = bi & 15;
    int bh = bi >> 4;
    int b = bh >> 5, h = bh & 31;
    int e = q * 256 + threadIdx.x;
    float carry = 0.f;
    for (int c = 0; c < NCHUNK; c++) {
        size_t sbo = (size_t)((b * 32 + c) * 32 + h) * (HDIM * DSTATE);
        float dec = expf(g_dacum[((b * 32 + h) * 32 + c) * CHUNKSZ + 127]);
        g_prev16[sbo + e] = __float2half_rn(carry);
        carry = fmaf(carry, dec, __half2float(g_states16[sbo + e]));
    }
}

// ================= fused Y kernel — tensor-core, 2 CTAs/SM, vectorized fill =================
#define YH_CS 0
#define YH_BS 9216
#define YH_XT 18432
#define YH_G  27136
#define YH_PT 44544
#define YH_HALVES 49152
#define SMEM_Y (YH_HALVES * 2 + 512)

__global__ void __launch_bounds__(256, 2) y_kernel(const float* __restrict__ zb,
                                                   const float* __restrict__ Dp)
{
    extern __shared__ __align__(16) __half ysm[];
    float* da = (float*)(ysm + YH_HALVES);
    uint32_t* smu = (uint32_t*)ysm;

    int bi = blockIdx.x;
    int h = bi & 31, c = (bi >> 5) & 31, b = bi >> 10;
    int tid = threadIdx.x;
    int wid = tid >> 5, lane = tid & 31;
    int g = lane >> 2, q = lane & 3;
    int base_t = b * SEQLEN + c * CHUNKSZ;
    int dab = ((b * 32 + h) * 32 + c) * CHUNKSZ;
    size_t pb = (size_t)((b * 32 + c) * 32 + h) * (HDIM * DSTATE);

    if (tid < 128) da[tid] = g_dacum[dab + tid];
#pragma unroll
    for (int i = 0; i < 16; i++) {
        int flat = tid + 256 * i;
        int s = flat >> 5, p2 = flat & 31;
        size_t goff = (size_t)(base_t + s) * DXBC + h * 64 + p2 * 2;
        __half2 xv2 = *(const __half2*)(g_xbc16 + goff);
        __half2 bv2 = *(const __half2*)(g_xbc16 + goff + DINNER);
        __half2 cv2 = *(const __half2*)(g_xbc16 + goff + 2 * DINNER);
        *(__half2*)(ysm + YH_BS + s * 72 + p2 * 2) = bv2;
        *(__half2*)(ysm + YH_CS + s * 72 + p2 * 2) = cv2;
        ysm[YH_XT + (p2 * 2)     * 136 + s] = xv2.x;
        ysm[YH_XT + (p2 * 2 + 1) * 136 + s] = xv2.y;
    }
#pragma unroll
    for (int i = 0; i < 8; i++) {
        int flat = tid + 256 * i;                  // half2 over [p][n]
        int p = flat >> 5, n2 = flat & 31;
        *(__half2*)(ysm + YH_PT + p * 72 + n2 * 2) = ((const __half2*)(g_prev16 + pb))[flat];
    }
    __syncthreads();

    const uint32_t* Cu = smu;
    const uint32_t* Bu = smu + 4608;
    const uint32_t* Xu = smu + 9216;
    const uint32_t* Gu = smu + 13568;
    const uint32_t* Pu = smu + 22272;

    // ---- phase 1: G = (C B^T) .* mask.decay ----
    {
        int l0 = (wid & 3) * 32, s0 = (wid >> 2) * 64;
        float accg[2][8][4];
#pragma unroll
        for (int mi = 0; mi < 2; mi++)
#pragma unroll
            for (int ni = 0; ni < 8; ni++)
#pragma unroll
                for (int e = 0; e < 4; e++) accg[mi][ni][e] = 0.f;

#pragma unroll
        for (int ks = 0; ks < 4; ks++) {
            int kq = ks * 8 + q;
            uint32_t a[2][4];
#pragma unroll
            for (int mi = 0; mi < 2; mi++) {
                int row = l0 + mi * 16;
                a[mi][0] = Cu[(row + g)     * 36 + kq];
                a[mi][1] = Cu[(row + g + 8) * 36 + kq];
                a[mi][2] = Cu[(row + g)     * 36 + kq + 4];
                a[mi][3] = Cu[(row + g + 8) * 36 + kq + 4];
            }
            uint32_t bf[8][2];
#pragma unroll
            for (int ni = 0; ni < 8; ni++) {
                int col = s0 + ni * 8;
                bf[ni][0] = Bu[(col + g) * 36 + kq];
                bf[ni][1] = Bu[(col + g) * 36 + kq + 4];
            }
#pragma unroll
            for (int mi = 0; mi < 2; mi++)
#pragma unroll
                for (int ni = 0; ni < 8; ni++)
                    mma_fp16(accg[mi][ni][0], accg[mi][ni][1], accg[mi][ni][2], accg[mi][ni][3],
                             a[mi][0], a[mi][1], a[mi][2], a[mi][3],
                             bf[ni][0], bf[ni][1]);
        }
#pragma unroll
        for (int mi = 0; mi < 2; mi++) {
            int lA = l0 + mi * 16 + g;
            int lB = lA + 8;
            float daA = da[lA], daB = da[lB];
#pragma unroll
            for (int ni = 0; ni < 8; ni++) {
                int s = s0 + ni * 8 + 2 * q;
                float das0 = da[s], das1 = da[s + 1];
                float gA0 = (s     <= lA) ? accg[mi][ni][0] * __expf(daA - das0) : 0.f;
                float gA1 = (s + 1 <= lA) ? accg[mi][ni][1] * __expf(daA - das1) : 0.f;
                float gB0 = (s     <= lB) ? accg[mi][ni][2] * __expf(daB - das0) : 0.f;
                float gB1 = (s + 1 <= lB) ? accg[mi][ni][3] * __expf(daB - das1) : 0.f;
                *(__half2*)(ysm + YH_G + lA * 136 + s) = __floats2half2_rn(gA0, gA1);
                *(__half2*)(ysm + YH_G + lB * 136 + s) = __floats2half2_rn(gB0, gB1);
            }
        }
    }
    __syncthreads();

    // ---- phase 2: Y = G @ x + exp(da)*(C @ prev^T) + D*x; gate; fp16 out ----
    {
        int wl = (wid & 3) * 32, wp = (wid >> 2) * 32;
        float acc1[2][4][4], acc2[2][4][4];
#pragma unroll
        for (int mi = 0; mi < 2; mi++)
#pragma unroll
            for (int ni = 0; ni < 4; ni++)
#pragma unroll
                for (int e = 0; e < 4; e++) { acc1[mi][ni][e] = 0.f; acc2[mi][ni][e] = 0.f; }

#pragma unroll
        for (int ks = 0; ks < 8; ks++) {
            int kq = ks * 8 + q;
            uint32_t a[2][4];
#pragma unroll
            for (int mi = 0; mi < 2; mi++) {
                int row = wl + mi * 16;
                a[mi][0] = Gu[(row + g)     * 68 + kq];
                a[mi][1] = Gu[(row + g + 8) * 68 + kq];
                a[mi][2] = Gu[(row + g)     * 68 + kq + 4];
                a[mi][3] = Gu[(row + g + 8) * 68 + kq + 4];
            }
            uint32_t bf[4][2];
#pragma unroll
            for (int ni = 0; ni < 4; ni++) {
                int col = wp + ni * 8;
                bf[ni][0] = Xu[(col + g) * 68 + kq];
                bf[ni][1] = Xu[(col + g) * 68 + kq + 4];
            }
#pragma unroll
            for (int mi = 0; mi < 2; mi++)
#pragma unroll
                for (int ni = 0; ni < 4; ni++)
                    mma_fp16(acc1[mi][ni][0], acc1[mi][ni][1], acc1[mi][ni][2], acc1[mi][ni][3],
                             a[mi][0], a[mi][1], a[mi][2], a[mi][3],
                             bf[ni][0], bf[ni][1]);
        }
#pragma unroll
        for (int ks = 0; ks < 4; ks++) {
            int kq = ks * 8 + q;
            uint32_t a[2][4];
#pragma unroll
            for (int mi = 0; mi < 2; mi++) {
                int row = wl + mi * 16;
                a[mi][0] = Cu[(row + g)     * 36 + kq];
                a[mi][1] = Cu[(row + g + 8) * 36 + kq];
                a[mi][2] = Cu[(row + g)     * 36 + kq + 4];
                a[mi][3] = Cu[(row + g + 8) * 36 + kq + 4];
            }
            uint32_t bf[4][2];
#pragma unroll
            for (int ni = 0; ni < 4; ni++) {
                int col = wp + ni * 8;
                bf[ni][0] = Pu[(col + g) * 36 + kq];
                bf[ni][1] = Pu[(col + g) * 36 + kq + 4];
            }
#pragma unroll
            for (int mi = 0; mi < 2; mi++)
#pragma unroll
                for (int ni = 0; ni < 4; ni++)
                    mma_fp16(acc2[mi][ni][0], acc2[mi][ni][1], acc2[mi][ni][2], acc2[mi][ni][3],
                             a[mi][0], a[mi][1], a[mi][2], a[mi][3],
                             bf[ni][0], bf[ni][1]);
        }

        float Dh = Dp[h];
#pragma unroll
        for (int mi = 0; mi < 2; mi++) {
            int lA = wl + mi * 16 + g;
            int lB = lA + 8;
            float edaA = __expf(da[lA]);
            float edaB = __expf(da[lB]);
            int tA = base_t + lA, tB = base_t + lB;
#pragma unroll
            for (int ni = 0; ni < 4; ni++) {
                int p = wp + ni * 8 + 2 * q;
                int chn = h * 64 + p;
                float zb0 = zb[chn], zb1 = zb[chn + 1];
                float xA0 = __half2float(ysm[YH_XT + p * 136 + lA]);
                float xA1 = __half2float(ysm[YH_XT + (p + 1) * 136 + lA]);
                float xB0 = __half2float(ysm[YH_XT + p * 136 + lB]);
                float xB1 = __half2float(ysm[YH_XT + (p + 1) * 136 + lB]);
                __half2 zA = *(const __half2*)(g_proj16 + (size_t)tA * DPROJ + DXBC + chn);
                __half2 zB = *(const __half2*)(g_proj16 + (size_t)tB * DPROJ + DXBC + chn);

                float yA0 = acc1[mi][ni][0] + edaA * acc2[mi][ni][0] + Dh * xA0;
                float yA1 = acc1[mi][ni][1] + edaA * acc2[mi][ni][1] + Dh * xA1;
                float yB0 = acc1[mi][ni][2] + edaB * acc2[mi][ni][2] + Dh * xB0;
                float yB1 = acc1[mi][ni][3] + edaB * acc2[mi][ni][3] + Dh * xB1;

                float zA0 = __half2float(zA.x) + zb0, zA1 = __half2float(zA.y) + zb1;
                float zB0 = __half2float(zB.x) + zb0, zB1 = __half2float(zB.y) + zb1;
                yA0 *= zA0 / (1.f + expf(-zA0));
                yA1 *= zA1 / (1.f + expf(-zA1));
                yB0 *= zB0 / (1.f + expf(-zB0));
                yB1 *= zB1 / (1.f + expf(-zB1));

                *(__half2*)(g_yz16 + (size_t)tA * DINNER + chn) = __floats2half2_rn(yA0, yA1);
                *(__half2*)(g_yz16 + (size_t)tB * DINNER + chn) = __floats2half2_rn(yB0, yB1);
            }
        }
    }
}

// ================= launch =================
extern "C" void kernel_launch(void* const* d_in, const int* in_sizes, int n_in,
                              void* d_out, int out_size)
{
    const float* u          = (const float*)d_in[0];
    const float* in_proj_w  = (const float*)d_in[1];
    const float* z_bias     = (const float*)d_in[2];
    const float* conv_w     = (const float*)d_in[3];
    const float* conv_b     = (const float*)d_in[4];
    const float* Dparam     = (const float*)d_in[5];
    const float* out_proj_w = (const float*)d_in[6];
    float* out = (float*)d_out;

    void *p_proj = nullptr, *p_yz = nullptr, *p_ua = nullptr, *p_wa = nullptr, *p_wo = nullptr;
    cudaGetSymbolAddress(&p_proj, g_proj16);
    cudaGetSymbolAddress(&p_yz, g_yz16);
    cudaGetSymbolAddress(&p_ua, g_ua16);
    cudaGetSymbolAddress(&p_wa, g_wa16);
    cudaGetSymbolAddress(&p_wo, g_wo16);

    cudaFuncSetAttribute((const void*)gemm_h<true>,
                         cudaFuncAttributeMaxDynamicSharedMemorySize, SMEM_GEMM);
    cudaFuncSetAttribute((const void*)gemm_h<false>,
                         cudaFuncAttributeMaxDynamicSharedMemorySize, SMEM_GEMM);
    cudaFuncSetAttribute(states_kernel, cudaFuncAttributeMaxDynamicSharedMemorySize, SMEM_STATES);
    cudaFuncSetAttribute(y_kernel, cudaFuncAttributeMaxDynamicSharedMemorySize, SMEM_Y);

    // 0) f32 -> f16 operand conversion
    f2h_kernel<<<(NTOK * DMODEL / 2 + 255) / 256, 256>>>(u, (__half*)p_ua, NTOK * DMODEL / 2);
    f2h_kernel<<<(DPROJ * DMODEL / 2 + 255) / 256, 256>>>(in_proj_w, (__half*)p_wa, DPROJ * DMODEL / 2);
    f2h_kernel<<<(DMODEL * DINNER / 2 + 255) / 256, 256>>>(out_proj_w, (__half*)p_wo, DMODEL * DINNER / 2);

    // 1) in_proj GEMM
    {
        dim3 grid((DPROJ + 127) / 128, NTOK / 128);
        gemm_h<true><<<grid, 256, SMEM_GEMM>>>(
            (const __half*)p_ua, (const __half*)p_wa, p_proj, NTOK, DPROJ, DMODEL);
    }
    // 2) conv + silu
    {
        dim3 grid(DXBC / 512, NTOK / 16);
        conv_silu_kernel<<<grid, 256>>>(conv_w, conv_b);
    }
    // 3) dA cumsum
    dacum_kernel<<<(BATCH * NHEADS * NCHUNK * 32 + 255) / 256, 256>>>();
    // 4) chunk states (tensor-core)
    states_kernel<<<BATCH * NCHUNK * NHEADS, 256, SMEM_STATES>>>();
    // 5) inter-chunk scan
    scan_kernel<<<BATCH * NHEADS * 16, 256>>>();
    // 6) fused Y + gating (tensor-core)
    y_kernel<<<BATCH * NCHUNK * NHEADS, 256, SMEM_Y>>>(z_bias, Dparam);
    // 7) out_proj GEMM
    {
        dim3 grid(DMODEL / 128, NTOK / 128);
        gemm_h<false><<<grid, 256, SMEM_GEMM>>>(
            (const __half*)p_yz, (const __half*)p_wo, out, NTOK, DMODEL, DINNER);
    }
}

// round 14
// speedup vs baseline: 2.0881x; 1.1026x over previous
#include <cuda_runtime.h>
#include <cuda_fp16.h>
#include <cstdint>
#include <math.h>

// ---------------- problem constants ----------------
#define BATCH    2
#define SEQLEN   4096
#define NTOK     8192
#define DMODEL   1024
#define DINNER   2048
#define DSTATE   64
#define NHEADS   32
#define HDIM     64
#define CONVK    4
#define CHUNKSZ  128
#define NCHUNK   32
#define DXBC     6144
#define DPROJ    8224

// ---------------- device scratch (allocation-free) ----------------
__device__ __half g_proj16[(size_t)NTOK * DPROJ];
__device__ __half g_xbc16[(size_t)NTOK * DXBC];
__device__ float  g_dacum[BATCH * NHEADS * NCHUNK * CHUNKSZ];
__device__ __half g_states16[(size_t)BATCH * NCHUNK * NHEADS * HDIM * DSTATE];
__device__ __half g_prev16[(size_t)BATCH * NCHUNK * NHEADS * HDIM * DSTATE];
__device__ __half g_yz16[(size_t)NTOK * DINNER];
__device__ __half g_ua16[(size_t)NTOK * DMODEL];
__device__ __half g_wa16[(size_t)DPROJ * DMODEL];
__device__ __half g_wo16[(size_t)DMODEL * DINNER];

// ================= helpers =================
__device__ __forceinline__ uint32_t smem_u32(const void* p) {
    uint32_t a;
    asm("{ .reg .u64 t; cvta.to.shared.u64 t, %1; cvt.u32.u64 %0, t; }" : "=r"(a) : "l"(p));
    return a;
}
__device__ __forceinline__ void cp_async16(uint32_t s, const void* g) {
    asm volatile("cp.async.cg.shared.global [%0], [%1], 16;" :: "r"(s), "l"(g) : "memory");
}
__device__ __forceinline__ void sts_zero16(uint32_t s) {
    asm volatile("st.shared.v4.b32 [%0], {%1,%1,%1,%1};" :: "r"(s), "r"(0u) : "memory");
}
#define CP_COMMIT() asm volatile("cp.async.commit_group;" ::: "memory")
#define CP_WAIT1()  asm volatile("cp.async.wait_group 1;" ::: "memory")

__device__ __forceinline__ void mma_fp16(float& d0, float& d1, float& d2, float& d3,
                                         uint32_t a0, uint32_t a1, uint32_t a2, uint32_t a3,
                                         uint32_t b0, uint32_t b1) {
    asm volatile(
        "mma.sync.aligned.m16n8k16.row.col.f32.f16.f16.f32 "
        "{%0,%1,%2,%3}, {%4,%5,%6,%7}, {%8,%9}, {%0,%1,%2,%3};"
        : "+f"(d0), "+f"(d1), "+f"(d2), "+f"(d3)
        : "r"(a0), "r"(a1), "r"(a2), "r"(a3), "r"(b0), "r"(b1));
}

// ================= f32 -> f16 conversion =================
__global__ void f2h_kernel(const float* __restrict__ in, __half* __restrict__ out, int n2) {
    int i = blockIdx.x * blockDim.x + threadIdx.x;
    if (i >= n2) return;
    float2 v = ((const float2*)in)[i];
    ((__half2*)out)[i] = __floats2half2_rn(v.x, v.y);
}

// ================= FP16 mma.sync GEMM (NT): C[m,n] = sum_k A[m,k]B[n,k] =================
// Block 128x128, 8 warps (2x4), warp tile 64x32, k-tile 64 halves, 3-stage, 2 CTAs/SM.
// KTILE=64 halves barrier count vs KTILE=32 (more straight-line work per epoch).
#define KTILE    64
#define NSTAGE   3
#define TSTRIDE_H 72                              // halves per smem row (64 + 8 pad) = 144B
#define A_HALVES (128 * TSTRIDE_H)                // 9216
#define STAGE_H  (2 * A_HALVES)                   // 18432
#define SMEM_GEMM (NSTAGE * STAGE_H * 2)          // 110592 bytes

__device__ __forceinline__ void load_tile_h(const __half* __restrict__ A,
                                            const __half* __restrict__ B,
                                            int K, int Nn, int bm, int bn,
                                            int ti, uint32_t sb, int tid)
{
    uint32_t st = sb + (uint32_t)(ti % NSTAGE) * (STAGE_H * 2);
    const __half* ag = A + (size_t)bm * K + (size_t)ti * KTILE;
#pragma unroll
    for (int i = 0; i < 4; i++) {                 // A: 128 rows x 8 chunks of 16B
        int flat = tid + (i << 8);
        int r = flat >> 3, c = flat & 7;
        cp_async16(st + r * (TSTRIDE_H * 2) + c * 16, ag + (size_t)r * K + c * 8);
    }
    uint32_t stb = st + A_HALVES * 2;
    const __half* bg = B + (size_t)ti * KTILE;
#pragma unroll
    for (int i = 0; i < 4; i++) {                 // B: 128 rows x 8 chunks of 16B
        int flat = tid + (i << 8);
        int r = flat >> 3, c = flat & 7;
        uint32_t so = stb + r * (TSTRIDE_H * 2) + c * 16;
        int gn = bn + r;
        if (gn < Nn) cp_async16(so, bg + (size_t)gn * K + c * 8);
        else         sts_zero16(so);
    }
}

template<bool HALF_OUT>
__global__ void __launch_bounds__(256, 2)
gemm_h(const __half* __restrict__ A, const __half* __restrict__ B,
       void* __restrict__ Cv, int M, int Nn, int K)
{
    extern __shared__ __align__(16) uint32_t dsm32[];   // half2 view, row stride 36 u32
    const int tid = threadIdx.x;
    const int wid = tid >> 5;
    const int lane = tid & 31;
    const int g = lane >> 2;
    const int q = lane & 3;
    const int wm = (wid & 1) * 64;
    const int wn = (wid >> 1) * 32;
    const int KT = K / KTILE;
    const int bm = blockIdx.y << 7;
    const int bn = blockIdx.x << 7;
    uint32_t sb = smem_u32(dsm32);

    float acc[4][4][4];
#pragma unroll
    for (int mi = 0; mi < 4; mi++)
#pragma unroll
        for (int ni = 0; ni < 4; ni++)
#pragma unroll
            for (int e = 0; e < 4; e++) acc[mi][ni][e] = 0.f;

    // prologue: tiles 0..1
#pragma unroll
    for (int t = 0; t < 2; t++) {
        load_tile_h(A, B, K, Nn, bm, bn, t, sb, tid);
        CP_COMMIT();
    }

    for (int kt = 0; kt < KT; kt++) {
        CP_WAIT1();                 // tile kt resident (kt+1 may be pending)
        __syncthreads();            // all warps done with slot being refilled
        int ld = kt + 2;
        if (ld < KT) load_tile_h(A, B, K, Nn, bm, bn, ld, sb, tid);
        CP_COMMIT();

        const uint32_t* As = dsm32 + (kt % NSTAGE) * (STAGE_H / 2);
        const uint32_t* Bs = As + A_HALVES / 2;
#pragma unroll
        for (int ks = 0; ks < 4; ks++) {          // four k=16 steps
            int kq = ks * 8 + q;
            uint32_t a[4][4];
#pragma unroll
            for (int mi = 0; mi < 4; mi++) {
                int row = wm + mi * 16;
                a[mi][0] = As[(row + g)     * 36 + kq];
                a[mi][1] = As[(row + g + 8) * 36 + kq];
                a[mi][2] = As[(row + g)     * 36 + kq + 4];
                a[mi][3] = As[(row + g + 8) * 36 + kq + 4];
            }
            uint32_t b[4][2];
#pragma unroll
            for (int ni = 0; ni < 4; ni++) {
                int col = wn + ni * 8;
                b[ni][0] = Bs[(col + g) * 36 + kq];
                b[ni][1] = Bs[(col + g) * 36 + kq + 4];
            }
#pragma unroll
            for (int mi = 0; mi < 4; mi++)
#pragma unroll
                for (int ni = 0; ni < 4; ni++)
                    mma_fp16(acc[mi][ni][0], acc[mi][ni][1], acc[mi][ni][2], acc[mi][ni][3],
                             a[mi][0], a[mi][1], a[mi][2], a[mi][3],
                             b[ni][0], b[ni][1]);
        }
    }

#pragma unroll
    for (int mi = 0; mi < 4; mi++) {
#pragma unroll
        for (int ni = 0; ni < 4; ni++) {
            int col = bn + wn + ni * 8 + 2 * q;
            if (col < Nn) {
                int r0 = bm + wm + mi * 16 + g;
                if (HALF_OUT) {
                    __half* C = (__half*)Cv;
                    *(__half2*)(C + (size_t)r0 * Nn + col) =
                        __floats2half2_rn(acc[mi][ni][0], acc[mi][ni][1]);
                    *(__half2*)(C + (size_t)(r0 + 8) * Nn + col) =
                        __floats2half2_rn(acc[mi][ni][2], acc[mi][ni][3]);
                } else {
                    float* C = (float*)Cv;
                    *(float2*)(C + (size_t)r0 * Nn + col) =
                        make_float2(acc[mi][ni][0], acc[mi][ni][1]);
                    *(float2*)(C + (size_t)(r0 + 8) * Nn + col) =
                        make_float2(acc[mi][ni][2], acc[mi][ni][3]);
                }
            }
        }
    }
}

// ================= conv + silu (half2-vectorized) =================
__global__ void __launch_bounds__(256) conv_silu_kernel(const float* __restrict__ cw,
                                                        const float* __restrict__ cb)
{
    int ch = (blockIdx.x * 256 + threadIdx.x) * 2;
    int tb = blockIdx.y * 16;
    int b = tb >> 12;
    int l0 = tb & (SEQLEN - 1);
    float c00 = cw[ch * 4 + 0], c01 = cw[ch * 4 + 1], c02 = cw[ch * 4 + 2], c03 = cw[ch * 4 + 3];
    float c10 = cw[ch * 4 + 4], c11 = cw[ch * 4 + 5], c12 = cw[ch * 4 + 6], c13 = cw[ch * 4 + 7];
    float b0 = cb[ch], b1 = cb[ch + 1];
    const __half2* base = (const __half2*)(g_proj16 + (size_t)(b * SEQLEN) * DPROJ + ch);
    __half2* outb = (__half2*)(g_xbc16 + (size_t)(b * SEQLEN) * DXBC + ch);
    const int strideIn = DPROJ / 2;
    const int strideOut = DXBC / 2;

    float2 w0 = make_float2(0.f, 0.f), w1 = w0, w2 = w0;
    if (l0 >= 3) w0 = __half22float2(base[(size_t)(l0 - 3) * strideIn]);
    if (l0 >= 2) w1 = __half22float2(base[(size_t)(l0 - 2) * strideIn]);
    if (l0 >= 1) w2 = __half22float2(base[(size_t)(l0 - 1) * strideIn]);
#pragma unroll
    for (int tt = 0; tt < 16; tt++) {
        float2 xv = __half22float2(base[(size_t)(l0 + tt) * strideIn]);
        float a0 = fmaf(c03, xv.x, fmaf(c02, w2.x, fmaf(c01, w1.x, fmaf(c00, w0.x, b0))));
        float a1 = fmaf(c13, xv.y, fmaf(c12, w2.y, fmaf(c11, w1.y, fmaf(c10, w0.y, b1))));
        float s0 = a0 / (1.f + expf(-a0));
        float s1 = a1 / (1.f + expf(-a1));
        outb[(size_t)(l0 + tt) * strideOut] = __floats2half2_rn(s0, s1);
        w0 = w1; w1 = w2; w2 = xv;
    }
}

// ================= dA cumsum =================
__global__ void __launch_bounds__(256) dacum_kernel()
{
    int gw = (blockIdx.x * blockDim.x + threadIdx.x) >> 5;
    int lane = threadIdx.x & 31;
    if (gw >= BATCH * NHEADS * NCHUNK) return;
    int c = gw & 31, h = (gw >> 5) & 31, b = gw >> 10;
    int t0 = b * SEQLEN + c * CHUNKSZ + lane * 4;
    float p[4], run = 0.f;
#pragma unroll
    for (int j = 0; j < 4; j++) {
        float v = __half2float(g_proj16[(size_t)(t0 + j) * DPROJ + (DXBC + DINNER) + h]);
        run += fmaxf(v, 0.f) + log1pf(expf(-fabsf(v)));
        p[j] = run;
    }
    float tot = run;
#pragma unroll
    for (int off = 1; off < 32; off <<= 1) {
        float nb = __shfl_up_sync(0xFFFFFFFFu, tot, off);
        if (lane >= off) tot += nb;
    }
    float excl = tot - run;
    int ob = ((b * 32 + h) * 32 + c) * CHUNKSZ + lane * 4;
#pragma unroll
    for (int j = 0; j < 4; j++) g_dacum[ob + j] = -(excl + p[j]);
}

// ================= chunk states — tensor-core version =================
#define ST_XT 0
#define ST_BT 8704
#define ST_HALVES 17408
#define SMEM_STATES (ST_HALVES * 2 + 512)
__global__ void __launch_bounds__(256, 3) states_kernel()
{
    extern __shared__ __align__(16) __half ssm[];
    float* da = (float*)(ssm + ST_HALVES);
    const uint32_t* Xu = (const uint32_t*)ssm;          // stride 68
    const uint32_t* Bu = (const uint32_t*)ssm + 4352;   // stride 68

    int bi = blockIdx.x;
    int h = bi & 31, c = (bi >> 5) & 31, b = bi >> 10;
    int tid = threadIdx.x;
    int wid = tid >> 5, lane = tid & 31;
    int g = lane >> 2, q = lane & 3;
    int base_t = b * SEQLEN + c * CHUNKSZ;
    int dab = ((b * 32 + h) * 32 + c) * CHUNKSZ;

    if (tid < 128) da[tid] = g_dacum[dab + tid];
    __syncthreads();
    float da_last = da[127];

#pragma unroll
    for (int i = 0; i < 16; i++) {
        int flat = tid + 256 * i;
        int s = flat >> 5, p2 = flat & 31;
        size_t goff = (size_t)(base_t + s) * DXBC + h * 64 + p2 * 2;
        float dec = __expf(da_last - da[s]);
        __half2 xv2 = *(const __half2*)(g_xbc16 + goff);
        __half2 bv2 = *(const __half2*)(g_xbc16 + goff + DINNER);
        ssm[ST_XT + (p2 * 2)     * 136 + s] = __float2half_rn(__half2float(xv2.x) * dec);
        ssm[ST_XT + (p2 * 2 + 1) * 136 + s] = __float2half_rn(__half2float(xv2.y) * dec);
        ssm[ST_BT + (p2 * 2)     * 136 + s] = bv2.x;
        ssm[ST_BT + (p2 * 2 + 1) * 136 + s] = bv2.y;
    }
    __syncthreads();

    int wm = (wid & 1) * 32, wn = (wid >> 1) * 16;
    float acc[2][2][4];
#pragma unroll
    for (int mi = 0; mi < 2; mi++)
#pragma unroll
        for (int ni = 0; ni < 2; ni++)
#pragma unroll
            for (int e = 0; e < 4; e++) acc[mi][ni][e] = 0.f;

#pragma unroll
    for (int ks = 0; ks < 8; ks++) {
        int kq = ks * 8 + q;
        uint32_t a[2][4];
#pragma unroll
        for (int mi = 0; mi < 2; mi++) {
            int row = wm + mi * 16;
            a[mi][0] = Xu[(row + g)     * 68 + kq];
            a[mi][1] = Xu[(row + g + 8) * 68 + kq];
            a[mi][2] = Xu[(row + g)     * 68 + kq + 4];
            a[mi][3] = Xu[(row + g + 8) * 68 + kq + 4];
        }
        uint32_t bf[2][2];
#pragma unroll
        for (int ni = 0; ni < 2; ni++) {
            int col = wn + ni * 8;
            bf[ni][0] = Bu[(col + g) * 68 + kq];
            bf[ni][1] = Bu[(col + g) * 68 + kq + 4];
        }
#pragma unroll
        for (int mi = 0; mi < 2; mi++)
#pragma unroll
            for (int ni = 0; ni < 2; ni++)
                mma_fp16(acc[mi][ni][0], acc[mi][ni][1], acc[mi][ni][2], acc[mi][ni][3],
                         a[mi][0], a[mi][1], a[mi][2], a[mi][3],
                         bf[ni][0], bf[ni][1]);
    }

    size_t sbo = (size_t)((b * 32 + c) * 32 + h) * (HDIM * DSTATE);
#pragma unroll
    for (int mi = 0; mi < 2; mi++) {
#pragma unroll
        for (int ni = 0; ni < 2; ni++) {
            int p0 = wm + mi * 16 + g;
            int n0 = wn + ni * 8 + 2 * q;
            *(__half2*)(g_states16 + sbo + p0 * 64 + n0) =
                __floats2half2_rn(acc[mi][ni][0], acc[mi][ni][1]);
            *(__half2*)(g_states16 + sbo + (p0 + 8) * 64 + n0) =
                __floats2half2_rn(acc[mi][ni][2], acc[mi][ni][3]);
        }
    }
}

// ================= inter-chunk scan =================
__global__ void __launch_bounds__(256) scan_kernel()
{
    int bi = blockIdx.x;
    int q = bi & 15;
    int bh = bi >> 4;
    int b = bh >> 5, h = bh & 31;
    int e = q * 256 + threadIdx.x;
    float carry = 0.f;
    for (int c = 0; c < NCHUNK; c++) {
        size_t sbo = (size_t)((b * 32 + c) * 32 + h) * (HDIM * DSTATE);
        float dec = expf(g_dacum[((b * 32 + h) * 32 + c) * CHUNKSZ + 127]);
        g_prev16[sbo + e] = __float2half_rn(carry);
        carry = fmaf(carry, dec, __half2float(g_states16[sbo + e]));
    }
}

// ================= fused Y kernel — tensor-core, 2 CTAs/SM =================
#define YH_CS 0
#define YH_BS 9216
#define YH_XT 18432
#define YH_G  27136
#define YH_PT 44544
#define YH_HALVES 49152
#define SMEM_Y (YH_HALVES * 2 + 512)

__global__ void __launch_bounds__(256, 2) y_kernel(const float* __restrict__ zb,
                                                   const float* __restrict__ Dp)
{
    extern __shared__ __align__(16) __half ysm[];
    float* da = (float*)(ysm + YH_HALVES);
    uint32_t* smu = (uint32_t*)ysm;

    int bi = blockIdx.x;
    int h = bi & 31, c = (bi >> 5) & 31, b = bi >> 10;
    int tid = threadIdx.x;
    int wid = tid >> 5, lane = tid & 31;
    int g = lane >> 2, q = lane & 3;
    int base_t = b * SEQLEN + c * CHUNKSZ;
    int dab = ((b * 32 + h) * 32 + c) * CHUNKSZ;
    size_t pb = (size_t)((b * 32 + c) * 32 + h) * (HDIM * DSTATE);

    if (tid < 128) da[tid] = g_dacum[dab + tid];
#pragma unroll
    for (int i = 0; i < 16; i++) {
        int flat = tid + 256 * i;
        int s = flat >> 5, p2 = flat & 31;
        size_t goff = (size_t)(base_t + s) * DXBC + h * 64 + p2 * 2;
        __half2 xv2 = *(const __half2*)(g_xbc16 + goff);
        __half2 bv2 = *(const __half2*)(g_xbc16 + goff + DINNER);
        __half2 cv2 = *(const __half2*)(g_xbc16 + goff + 2 * DINNER);
        *(__half2*)(ysm + YH_BS + s * 72 + p2 * 2) = bv2;
        *(__half2*)(ysm + YH_CS + s * 72 + p2 * 2) = cv2;
        ysm[YH_XT + (p2 * 2)     * 136 + s] = xv2.x;
        ysm[YH_XT + (p2 * 2 + 1) * 136 + s] = xv2.y;
    }
#pragma unroll
    for (int i = 0; i < 8; i++) {
        int flat = tid + 256 * i;
        int p = flat >> 5, n2 = flat & 31;
        *(__half2*)(ysm + YH_PT + p * 72 + n2 * 2) = ((const __half2*)(g_prev16 + pb))[flat];
    }
    __syncthreads();

    const uint32_t* Cu = smu;
    const uint32_t* Bu = smu + 4608;
    const uint32_t* Xu = smu + 9216;
    const uint32_t* Gu = smu + 13568;
    const uint32_t* Pu = smu + 22272;

    // ---- phase 1: G = (C B^T) .* mask.decay ----
    {
        int l0 = (wid & 3) * 32, s0 = (wid >> 2) * 64;
        float accg[2][8][4];
#pragma unroll
        for (int mi = 0; mi < 2; mi++)
#pragma unroll
            for (int ni = 0; ni < 8; ni++)
#pragma unroll
                for (int e = 0; e < 4; e++) accg[mi][ni][e] = 0.f;

#pragma unroll
        for (int ks = 0; ks < 4; ks++) {
            int kq = ks * 8 + q;
            uint32_t a[2][4];
#pragma unroll
            for (int mi = 0; mi < 2; mi++) {
                int row = l0 + mi * 16;
                a[mi][0] = Cu[(row + g)     * 36 + kq];
                a[mi][1] = Cu[(row + g + 8) * 36 + kq];
                a[mi][2] = Cu[(row + g)     * 36 + kq + 4];
                a[mi][3] = Cu[(row + g + 8) * 36 + kq + 4];
            }
            uint32_t bf[8][2];
#pragma unroll
            for (int ni = 0; ni < 8; ni++) {
                int col = s0 + ni * 8;
                bf[ni][0] = Bu[(col + g) * 36 + kq];
                bf[ni][1] = Bu[(col + g) * 36 + kq + 4];
            }
#pragma unroll
            for (int mi = 0; mi < 2; mi++)
#pragma unroll
                for (int ni = 0; ni < 8; ni++)
                    mma_fp16(accg[mi][ni][0], accg[mi][ni][1], accg[mi][ni][2], accg[mi][ni][3],
                             a[mi][0], a[mi][1], a[mi][2], a[mi][3],
                             bf[ni][0], bf[ni][1]);
        }
#pragma unroll
        for (int mi = 0; mi < 2; mi++) {
            int lA = l0 + mi * 16 + g;
            int lB = lA + 8;
            float daA = da[lA], daB = da[lB];
#pragma unroll
            for (int ni = 0; ni < 8; ni++) {
                int s = s0 + ni * 8 + 2 * q;
                float das0 = da[s], das1 = da[s + 1];
                float gA0 = (s     <= lA) ? accg[mi][ni][0] * __expf(daA - das0) : 0.f;
                float gA1 = (s + 1 <= lA) ? accg[mi][ni][1] * __expf(daA - das1) : 0.f;
                float gB0 = (s     <= lB) ? accg[mi][ni][2] * __expf(daB - das0) : 0.f;
                float gB1 = (s + 1 <= lB) ? accg[mi][ni][3] * __expf(daB - das1) : 0.f;
                *(__half2*)(ysm + YH_G + lA * 136 + s) = __floats2half2_rn(gA0, gA1);
                *(__half2*)(ysm + YH_G + lB * 136 + s) = __floats2half2_rn(gB0, gB1);
            }
        }
    }
    __syncthreads();

    // ---- phase 2: Y = G @ x + exp(da)*(C @ prev^T) + D*x; gate; fp16 out ----
    {
        int wl = (wid & 3) * 32, wp = (wid >> 2) * 32;
        float acc1[2][4][4], acc2[2][4][4];
#pragma unroll
        for (int mi = 0; mi < 2; mi++)
#pragma unroll
            for (int ni = 0; ni < 4; ni++)
#pragma unroll
                for (int e = 0; e < 4; e++) { acc1[mi][ni][e] = 0.f; acc2[mi][ni][e] = 0.f; }

#pragma unroll
        for (int ks = 0; ks < 8; ks++) {
            int kq = ks * 8 + q;
            uint32_t a[2][4];
#pragma unroll
            for (int mi = 0; mi < 2; mi++) {
                int row = wl + mi * 16;
                a[mi][0] = Gu[(row + g)     * 68 + kq];
                a[mi][1] = Gu[(row + g + 8) * 68 + kq];
                a[mi][2] = Gu[(row + g)     * 68 + kq + 4];
                a[mi][3] = Gu[(row + g + 8) * 68 + kq + 4];
            }
            uint32_t bf[4][2];
#pragma unroll
            for (int ni = 0; ni < 4; ni++) {
                int col = wp + ni * 8;
                bf[ni][0] = Xu[(col + g) * 68 + kq];
                bf[ni][1] = Xu[(col + g) * 68 + kq + 4];
            }
#pragma unroll
            for (int mi = 0; mi < 2; mi++)
#pragma unroll
                for (int ni = 0; ni < 4; ni++)
                    mma_fp16(acc1[mi][ni][0], acc1[mi][ni][1], acc1[mi][ni][2], acc1[mi][ni][3],
                             a[mi][0], a[mi][1], a[mi][2], a[mi][3],
                             bf[ni][0], bf[ni][1]);
        }
#pragma unroll
        for (int ks = 0; ks < 4; ks++) {
            int kq = ks * 8 + q;
            uint32_t a[2][4];
#pragma unroll
            for (int mi = 0; mi < 2; mi++) {
                int row = wl + mi * 16;
                a[mi][0] = Cu[(row + g)     * 36 + kq];
                a[mi][1] = Cu[(row + g + 8) * 36 + kq];
                a[mi][2] = Cu[(row + g)     * 36 + kq + 4];
                a[mi][3] = Cu[(row + g + 8) * 36 + kq + 4];
            }
            uint32_t bf[4][2];
#pragma unroll
            for (int ni = 0; ni < 4; ni++) {
                int col = wp + ni * 8;
                bf[ni][0] = Pu[(col + g) * 36 + kq];
                bf[ni][1] = Pu[(col + g) * 36 + kq + 4];
            }
#pragma unroll
            for (int mi = 0; mi < 2; mi++)
#pragma unroll
                for (int ni = 0; ni < 4; ni++)
                    mma_fp16(acc2[mi][ni][0], acc2[mi][ni][1], acc2[mi][ni][2], acc2[mi][ni][3],
                             a[mi][0], a[mi][1], a[mi][2], a[mi][3],
                             bf[ni][0], bf[ni][1]);
        }

        float Dh = Dp[h];
#pragma unroll
        for (int mi = 0; mi < 2; mi++) {
            int lA = wl + mi * 16 + g;
            int lB = lA + 8;
            float edaA = __expf(da[lA]);
            float edaB = __expf(da[lB]);
            int tA = base_t + lA, tB = base_t + lB;
#pragma unroll
            for (int ni = 0; ni < 4; ni++) {
                int p = wp + ni * 8 + 2 * q;
                int chn = h * 64 + p;
                float zb0 = zb[chn], zb1 = zb[chn + 1];
                float xA0 = __half2float(ysm[YH_XT + p * 136 + lA]);
                float xA1 = __half2float(ysm[YH_XT + (p + 1) * 136 + lA]);
                float xB0 = __half2float(ysm[YH_XT + p * 136 + lB]);
                float xB1 = __half2float(ysm[YH_XT + (p + 1) * 136 + lB]);
                __half2 zA = *(const __half2*)(g_proj16 + (size_t)tA * DPROJ + DXBC + chn);
                __half2 zB = *(const __half2*)(g_proj16 + (size_t)tB * DPROJ + DXBC + chn);

                float yA0 = acc1[mi][ni][0] + edaA * acc2[mi][ni][0] + Dh * xA0;
                float yA1 = acc1[mi][ni][1] + edaA * acc2[mi][ni][1] + Dh * xA1;
                float yB0 = acc1[mi][ni][2] + edaB * acc2[mi][ni][2] + Dh * xB0;
                float yB1 = acc1[mi][ni][3] + edaB * acc2[mi][ni][3] + Dh * xB1;

                float zA0 = __half2float(zA.x) + zb0, zA1 = __half2float(zA.y) + zb1;
                float zB0 = __half2float(zB.x) + zb0, zB1 = __half2float(zB.y) + zb1;
                yA0 *= zA0 / (1.f + expf(-zA0));
                yA1 *= zA1 / (1.f + expf(-zA1));
                yB0 *= zB0 / (1.f + expf(-zB0));
                yB1 *= zB1 / (1.f + expf(-zB1));

                *(__half2*)(g_yz16 + (size_t)tA * DINNER + chn) = __floats2half2_rn(yA0, yA1);
                *(__half2*)(g_yz16 + (size_t)tB * DINNER + chn) = __floats2half2_rn(yB0, yB1);
            }
        }
    }
}

// ================= launch =================
extern "C" void kernel_launch(void* const* d_in, const int* in_sizes, int n_in,
                              void* d_out, int out_size)
{
    const float* u          = (const float*)d_in[0];
    const float* in_proj_w  = (const float*)d_in[1];
    const float* z_bias     = (const float*)d_in[2];
    const float* conv_w     = (const float*)d_in[3];
    const float* conv_b     = (const float*)d_in[4];
    const float* Dparam     = (const float*)d_in[5];
    const float* out_proj_w = (const float*)d_in[6];
    float* out = (float*)d_out;

    void *p_proj = nullptr, *p_yz = nullptr, *p_ua = nullptr, *p_wa = nullptr, *p_wo = nullptr;
    cudaGetSymbolAddress(&p_proj, g_proj16);
    cudaGetSymbolAddress(&p_yz, g_yz16);
    cudaGetSymbolAddress(&p_ua, g_ua16);
    cudaGetSymbolAddress(&p_wa, g_wa16);
    cudaGetSymbolAddress(&p_wo, g_wo16);

    cudaFuncSetAttribute((const void*)gemm_h<true>,
                         cudaFuncAttributeMaxDynamicSharedMemorySize, SMEM_GEMM);
    cudaFuncSetAttribute((const void*)gemm_h<false>,
                         cudaFuncAttributeMaxDynamicSharedMemorySize, SMEM_GEMM);
    cudaFuncSetAttribute(states_kernel, cudaFuncAttributeMaxDynamicSharedMemorySize, SMEM_STATES);
    cudaFuncSetAttribute(y_kernel, cudaFuncAttributeMaxDynamicSharedMemorySize, SMEM_Y);

    // 0) f32 -> f16 operand conversion
    f2h_kernel<<<(NTOK * DMODEL / 2 + 255) / 256, 256>>>(u, (__half*)p_ua, NTOK * DMODEL / 2);
    f2h_kernel<<<(DPROJ * DMODEL / 2 + 255) / 256, 256>>>(in_proj_w, (__half*)p_wa, DPROJ * DMODEL / 2);
    f2h_kernel<<<(DMODEL * DINNER / 2 + 255) / 256, 256>>>(out_proj_w, (__half*)p_wo, DMODEL * DINNER / 2);

    // 1) in_proj GEMM (KTILE=64, 3-stage)
    {
        dim3 grid((DPROJ + 127) / 128, NTOK / 128);
        gemm_h<true><<<grid, 256, SMEM_GEMM>>>(
            (const __half*)p_ua, (const __half*)p_wa, p_proj, NTOK, DPROJ, DMODEL);
    }
    // 2) conv + silu
    {
        dim3 grid(DXBC / 512, NTOK / 16);
        conv_silu_kernel<<<grid, 256>>>(conv_w, conv_b);
    }
    // 3) dA cumsum
    dacum_kernel<<<(BATCH * NHEADS * NCHUNK * 32 + 255) / 256, 256>>>();
    // 4) chunk states (tensor-core)
    states_kernel<<<BATCH * NCHUNK * NHEADS, 256, SMEM_STATES>>>();
    // 5) inter-chunk scan
    scan_kernel<<<BATCH * NHEADS * 16, 256>>>();
    // 6) fused Y + gating (tensor-core)
    y_kernel<<<BATCH * NCHUNK * NHEADS, 256, SMEM_Y>>>(z_bias, Dparam);
    // 7) out_proj GEMM (KTILE=64, 3-stage)
    {
        dim3 grid(DMODEL / 128, NTOK / 128);
        gemm_h<false><<<grid, 256, SMEM_GEMM>>>(
            (const __half*)p_yz, (const __half*)p_wo, out, NTOK, DMODEL, DINNER);
    }
}